// round 2
// baseline (speedup 1.0000x reference)
#include <cuda_runtime.h>
#include <math.h>

#define Bsz 256
#define Tsz 128
#define EMB 256
#define HID 512
#define VOC 1004
#define FCI 2048
#define BT  (Bsz*Tsz)
#define G4  (4*HID)

typedef unsigned long long ull;

// ---------- f32x2 packed helpers ----------
__device__ __forceinline__ ull ffma2(ull a, ull b, ull c) {
    ull d; asm("fma.rn.f32x2 %0, %1, %2, %3;" : "=l"(d) : "l"(a), "l"(b), "l"(c)); return d;
}
__device__ __forceinline__ ull dup2(float x) {
    ull r; asm("mov.b64 %0, {%1, %2};" : "=l"(r) : "f"(x), "f"(x)); return r;
}
__device__ __forceinline__ float2 unpk(ull v) {
    float2 r; asm("mov.b64 {%0, %1}, %2;" : "=f"(r.x), "=f"(r.y) : "l"(v)); return r;
}
__device__ __forceinline__ float tanh_fast(float x) {
    float r; asm("tanh.approx.f32 %0, %1;" : "=f"(r) : "f"(x)); return r;
}
__device__ __forceinline__ float sigmoid_fast(float x) {
    return 0.5f + 0.5f * tanh_fast(0.5f * x);
}

// ------------------------- device scratch -------------------------
__device__ __align__(16) float g_feats    [Bsz*EMB];
__device__ __align__(16) float g_ctx_base [Bsz*EMB];
__device__ __align__(16) float g_gate_base[Bsz*G4];
__device__ __align__(16) float g_ctx      [(size_t)BT*EMB];
__device__ __align__(16) float g_gatesX   [(size_t)BT*G4];
__device__ __align__(16) float g_hseq     [(size_t)BT*HID];
__device__ __align__(16) float g_h[2][Bsz*HID];
__device__ __align__(16) float g_c[Bsz*HID];

__global__ void init_state_kernel() {
    int i = blockIdx.x*blockDim.x + threadIdx.x;
    if (i < Bsz*HID) { g_h[0][i] = 0.f; g_c[i] = 0.f; }
}

// ------------------------- NT SGEMM, f32x2 inner -------------------------
// C[m,n] = sum_k A[m,k]*W[n,k] (+ bias[n]) (+ rowAdd[m/rowDiv, n])
// BM=128, BN=64, BK=16, 256 threads. Per thread: 8 m (4 f32x2 pairs) x 4 n.
// Requires: M % 128 == 0, K % 16 == 0. N arbitrary (guarded).
__global__ __launch_bounds__(256)
void gemm128(const float* __restrict__ A, int lda,
             const float* __restrict__ W, int ldw,
             float* __restrict__ C, int ldc,
             int M, int N, int K,
             const float* __restrict__ bias,
             const float* __restrict__ rowAdd, int rowDiv, int rowLd)
{
    __shared__ __align__(16) float As[16][130];   // [k][m], stride 130 (even, conflict-audited)
    __shared__ __align__(16) ull   Ws2[16][65];   // [k][n] duplicated pairs

    const int n0 = blockIdx.x*64, m0 = blockIdx.y*128;
    const int t  = threadIdx.x;

    // loaders
    const int ar = t>>1, ac = (t&1)*8;   // A: 128 rows x 16k, 2 float4/thread
    const int wr = t>>2, wc = (t&3)*4;   // W: 64 rows x 16k, 1 float4/thread

    // compute mapping: n = n0 + tx + 16*j (strided for 1-phase LDS.64)
    const int tx = t&15, ty = t>>4;
    const int cm = ty*8;

    ull acc[4][4];
    #pragma unroll
    for (int j=0;j<4;j++)
        #pragma unroll
        for (int i=0;i<4;i++) acc[j][i] = 0ull;

    const float* Ap = A + (size_t)(m0+ar)*lda + ac;
    const bool wok = (n0+wr) < N;
    const float* Wp = W + (size_t)(wok ? (n0+wr) : 0)*ldw + wc;

    float4 av0 = *(const float4*)Ap;
    float4 av1 = *(const float4*)(Ap+4);
    float4 wv  = wok ? *(const float4*)Wp : make_float4(0,0,0,0);

    for (int k0 = 0; k0 < K; k0 += 16) {
        As[ac+0][ar]=av0.x; As[ac+1][ar]=av0.y; As[ac+2][ar]=av0.z; As[ac+3][ar]=av0.w;
        As[ac+4][ar]=av1.x; As[ac+5][ar]=av1.y; As[ac+6][ar]=av1.z; As[ac+7][ar]=av1.w;
        Ws2[wc+0][wr]=dup2(wv.x); Ws2[wc+1][wr]=dup2(wv.y);
        Ws2[wc+2][wr]=dup2(wv.z); Ws2[wc+3][wr]=dup2(wv.w);
        __syncthreads();

        if (k0 + 16 < K) {
            av0 = *(const float4*)(Ap + k0 + 16);
            av1 = *(const float4*)(Ap + k0 + 20);
            wv  = wok ? *(const float4*)(Wp + k0 + 16) : make_float4(0,0,0,0);
        }

        #pragma unroll
        for (int kk = 0; kk < 16; kk++) {
            ull a2[4];
            a2[0] = *(const ull*)&As[kk][cm+0];
            a2[1] = *(const ull*)&As[kk][cm+2];
            a2[2] = *(const ull*)&As[kk][cm+4];
            a2[3] = *(const ull*)&As[kk][cm+6];
            ull wd[4];
            wd[0] = Ws2[kk][tx+ 0];
            wd[1] = Ws2[kk][tx+16];
            wd[2] = Ws2[kk][tx+32];
            wd[3] = Ws2[kk][tx+48];
            #pragma unroll
            for (int j=0;j<4;j++)
                #pragma unroll
                for (int i=0;i<4;i++)
                    acc[j][i] = ffma2(a2[i], wd[j], acc[j][i]);
        }
        __syncthreads();
    }

    // epilogue: scalar stores (n strided by 16 per thread)
    #pragma unroll
    for (int j=0;j<4;j++) {
        const int gn = n0 + tx + 16*j;
        if (gn >= N) continue;
        const float bv = bias ? bias[gn] : 0.f;
        #pragma unroll
        for (int i=0;i<4;i++) {
            const int gm0 = m0 + cm + 2*i;
            float2 v = unpk(acc[j][i]);
            float a0 = bv, a1 = bv;
            if (rowAdd) {
                a0 += rowAdd[(size_t)( gm0      / rowDiv)*rowLd + gn];
                a1 += rowAdd[(size_t)((gm0 + 1) / rowDiv)*rowLd + gn];
            }
            C[(size_t)gm0*ldc + gn]     = v.x + a0;
            C[(size_t)(gm0+1)*ldc + gn] = v.y + a1;
        }
    }
}

// ------------------------- fused LSTM step, f32x2 -------------------------
// Tile: 32 batch x 32 hidden x 4 gates, 256 threads, grid (8,16)=128 CTAs.
// Per thread: 4 batch (2 f32x2 pairs) x 4 gates at one h.
__global__ __launch_bounds__(256)
void lstm_step(const float* __restrict__ W_hh,
               const float* __restrict__ b_hh,
               int tstep)
{
    __shared__ __align__(16) float As[16][34];    // [k][b]
    __shared__ __align__(16) ull   Ws2[16][130];  // [k][4g x 32h] dup'd

    const float* __restrict__ h_in  = g_h[tstep & 1];
    float*       __restrict__ h_out = g_h[(tstep+1) & 1];

    const int b0 = blockIdx.x*32, h0 = blockIdx.y*32;
    const int t  = threadIdx.x;
    const int th = t & 31;           // hidden within tile
    const int tb = (t >> 5) * 4;     // batch group of 4

    // loaders
    const int ar = t>>2, ac = (t&3)*4;         // A: 32x16, first 128 threads
    const int wr = t>>1, wc = (t&1)*8;         // W: 128 rows x 16k, 2 float4/thread
    const int wg = wr>>5, wj = wr&31;

    ull acc[4][2];
    #pragma unroll
    for (int g=0;g<4;g++) { acc[g][0]=0ull; acc[g][1]=0ull; }

    const float* Ap = h_in + (size_t)(b0 + ar)*HID + ac;
    const float* Wp = W_hh + (size_t)(wg*HID + h0 + wj)*HID + wc;

    float4 av  = (t < 128) ? *(const float4*)Ap : make_float4(0,0,0,0);
    float4 wv0 = *(const float4*)Wp;
    float4 wv1 = *(const float4*)(Wp+4);

    for (int k0 = 0; k0 < HID; k0 += 16) {
        if (t < 128) {
            As[ac+0][ar]=av.x; As[ac+1][ar]=av.y; As[ac+2][ar]=av.z; As[ac+3][ar]=av.w;
        }
        Ws2[wc+0][wr]=dup2(wv0.x); Ws2[wc+1][wr]=dup2(wv0.y);
        Ws2[wc+2][wr]=dup2(wv0.z); Ws2[wc+3][wr]=dup2(wv0.w);
        Ws2[wc+4][wr]=dup2(wv1.x); Ws2[wc+5][wr]=dup2(wv1.y);
        Ws2[wc+6][wr]=dup2(wv1.z); Ws2[wc+7][wr]=dup2(wv1.w);
        __syncthreads();

        if (k0 + 16 < HID) {
            if (t < 128) av = *(const float4*)(Ap + k0 + 16);
            wv0 = *(const float4*)(Wp + k0 + 16);
            wv1 = *(const float4*)(Wp + k0 + 20);
        }

        #pragma unroll
        for (int kk = 0; kk < 16; kk++) {
            ull a2[2];
            a2[0] = *(const ull*)&As[kk][tb+0];
            a2[1] = *(const ull*)&As[kk][tb+2];
            ull wd[4];
            wd[0] = Ws2[kk][     th];
            wd[1] = Ws2[kk][32 + th];
            wd[2] = Ws2[kk][64 + th];
            wd[3] = Ws2[kk][96 + th];
            #pragma unroll
            for (int g=0;g<4;g++) {
                acc[g][0] = ffma2(a2[0], wd[g], acc[g][0]);
                acc[g][1] = ffma2(a2[1], wd[g], acc[g][1]);
            }
        }
        __syncthreads();
    }

    // ---- fused LSTM cell epilogue ----
    const int h = h0 + th;
    const float bi = b_hh[h];
    const float bf = b_hh[HID   + h];
    const float bg = b_hh[2*HID + h];
    const float bo = b_hh[3*HID + h];

    #pragma unroll
    for (int i=0;i<2;i++) {
        float2 vi = unpk(acc[0][i]);
        float2 vf = unpk(acc[1][i]);
        float2 vg = unpk(acc[2][i]);
        float2 vo = unpk(acc[3][i]);
        #pragma unroll
        for (int s=0;s<2;s++) {
            const int b = b0 + tb + 2*i + s;
            const size_t base = ((size_t)b*Tsz + tstep)*G4;
            float gi = (s ? vi.y : vi.x) + g_gatesX[base +            h] + bi;
            float gf = (s ? vf.y : vf.x) + g_gatesX[base + HID   +    h] + bf;
            float gg = (s ? vg.y : vg.x) + g_gatesX[base + 2*HID +    h] + bg;
            float go = (s ? vo.y : vo.x) + g_gatesX[base + 3*HID +    h] + bo;

            float si = sigmoid_fast(gi);
            float sf = sigmoid_fast(gf);
            float so = sigmoid_fast(go);

            const int ch = b*HID + h;
            float cnew = sf*g_c[ch] + si*tanh_fast(gg);
            float hnew = so*tanh_fast(cnew);
            g_c[ch]   = cnew;
            h_out[ch] = hnew;
            g_hseq[((size_t)b*Tsz + tstep)*HID + h] = hnew;
        }
    }
}

// ------------------------- launch -------------------------
extern "C" void kernel_launch(void* const* d_in, const int* in_sizes, int n_in,
                              void* d_out, int out_size)
{
    const float* images   = (const float*)d_in[0];
    const float* captions = (const float*)d_in[1];
    const float* W_fc  = (const float*)d_in[2];
    const float* b_fc  = (const float*)d_in[3];
    const float* W_att = (const float*)d_in[4];
    const float* b_att = (const float*)d_in[5];
    const float* W_ih  = (const float*)d_in[6];
    const float* b_ih  = (const float*)d_in[7];
    const float* W_hh  = (const float*)d_in[8];
    const float* b_hh  = (const float*)d_in[9];
    const float* W_out = (const float*)d_in[10];
    const float* b_out = (const float*)d_in[11];
    float* out = (float*)d_out;

    float *p_feats, *p_ctxb, *p_gateb, *p_ctx, *p_gatesX, *p_hseq;
    cudaGetSymbolAddress((void**)&p_feats,  g_feats);
    cudaGetSymbolAddress((void**)&p_ctxb,   g_ctx_base);
    cudaGetSymbolAddress((void**)&p_gateb,  g_gate_base);
    cudaGetSymbolAddress((void**)&p_ctx,    g_ctx);
    cudaGetSymbolAddress((void**)&p_gatesX, g_gatesX);
    cudaGetSymbolAddress((void**)&p_hseq,   g_hseq);

    init_state_kernel<<<(Bsz*HID + 255)/256, 256>>>();

    // feats = images @ W_fc^T + b_fc                [256,256] K=2048
    gemm128<<<dim3(EMB/64, Bsz/128), 256>>>(images, FCI, W_fc, FCI, p_feats, EMB,
                                            Bsz, EMB, FCI, b_fc, nullptr, 1, 0);

    // ctx_base = feats @ W_att[:, :256]^T + b_att   [256,256] K=256
    gemm128<<<dim3(EMB/64, Bsz/128), 256>>>(p_feats, EMB, W_att, EMB+HID, p_ctxb, EMB,
                                            Bsz, EMB, EMB, b_att, nullptr, 1, 0);

    // gate_base = feats @ W_ih[:, :256]^T + b_ih    [256,2048] K=256
    gemm128<<<dim3(G4/64, Bsz/128), 256>>>(p_feats, EMB, W_ih, 2*EMB, p_gateb, G4,
                                           Bsz, G4, EMB, b_ih, nullptr, 1, 0);

    // ctx[b,t] = captions @ W_att[:, 256:]^T + ctx_base[b]   M=32768,N=256,K=512
    gemm128<<<dim3(EMB/64, BT/128), 256>>>(captions, HID, W_att + EMB, EMB+HID, p_ctx, EMB,
                                           BT, EMB, HID, nullptr, p_ctxb, Tsz, EMB);

    // gatesX[b,t] = ctx @ W_ih[:, 256:]^T + gate_base[b]     M=32768,N=2048,K=256
    gemm128<<<dim3(G4/64, BT/128), 256>>>(p_ctx, EMB, W_ih + EMB, 2*EMB, p_gatesX, G4,
                                          BT, G4, EMB, nullptr, p_gateb, Tsz, G4);

    // sequential recurrence, fused GEMM + cell
    for (int t = 0; t < Tsz; t++)
        lstm_step<<<dim3(Bsz/32, HID/32), 256>>>(W_hh, b_hh, t);

    // out = hseq @ W_out^T + b_out                  M=32768,N=1004,K=512
    gemm128<<<dim3((VOC+63)/64, BT/128), 256>>>(p_hseq, HID, W_out, HID, out, VOC,
                                                BT, VOC, HID, b_out, nullptr, 1, 0);
}

// round 4
// speedup vs baseline: 1.4751x; 1.4751x over previous
#include <cuda_runtime.h>
#include <cuda_bf16.h>
#include <math.h>
#include <cstdint>

#define Bsz 256
#define Tsz 128
#define EMB 256
#define HID 512
#define VOC 1004
#define VOCP 1024
#define FCI 2048
#define BT  (Bsz*Tsz)
#define G4  (4*HID)

typedef __nv_bfloat16 bf16;

// ===================== PTX helpers =====================
__device__ __forceinline__ uint32_t smem_u32(const void* p) {
    uint32_t a;
    asm("{ .reg .u64 t; cvta.to.shared.u64 t, %1; cvt.u32.u64 %0, t; }" : "=r"(a) : "l"(p));
    return a;
}
__device__ __forceinline__ void cp16(uint32_t s, const void* g) {
    asm volatile("cp.async.cg.shared.global [%0], [%1], 16;" :: "r"(s), "l"(g) : "memory");
}
#define CP_COMMIT() asm volatile("cp.async.commit_group;" ::: "memory")
#define CP_WAIT(n)  asm volatile("cp.async.wait_group %0;" :: "n"(n) : "memory")

#define LDM_X4(r0,r1,r2,r3, addr) \
    asm volatile("ldmatrix.sync.aligned.m8n8.x4.shared.b16 {%0,%1,%2,%3}, [%4];" \
        : "=r"(r0), "=r"(r1), "=r"(r2), "=r"(r3) : "r"(addr))

#define MMA_BF16(c0,c1,c2,c3, a0,a1,a2,a3, b0,b1) \
    asm volatile("mma.sync.aligned.m16n8k16.row.col.f32.bf16.bf16.f32 " \
        "{%0,%1,%2,%3}, {%4,%5,%6,%7}, {%8,%9}, {%0,%1,%2,%3};" \
        : "+f"(c0), "+f"(c1), "+f"(c2), "+f"(c3) \
        : "r"(a0), "r"(a1), "r"(a2), "r"(a3), "r"(b0), "r"(b1))

// ===================== device scratch =====================
__device__ __align__(16) float g_feats    [Bsz*EMB];
__device__ __align__(16) float g_ctx_base [Bsz*EMB];
__device__ __align__(16) float g_gate_base[Bsz*G4];
__device__ __align__(16) float g_gatesX   [(size_t)BT*G4];
__device__ __align__(16) float g_h[2][Bsz*HID];
__device__ __align__(16) float g_c[Bsz*HID];

__device__ __align__(16) bf16 g_cap_hi [(size_t)BT*HID];
__device__ __align__(16) bf16 g_cap_lo [(size_t)BT*HID];
__device__ __align__(16) bf16 g_ctx_hi [(size_t)BT*EMB];
__device__ __align__(16) bf16 g_ctx_lo [(size_t)BT*EMB];
__device__ __align__(16) bf16 g_hseq_hi[(size_t)BT*HID];
__device__ __align__(16) bf16 g_hseq_lo[(size_t)BT*HID];
__device__ __align__(16) bf16 g_watt_hi[EMB*HID],  g_watt_lo[EMB*HID];
__device__ __align__(16) bf16 g_wih_hi [G4*EMB],   g_wih_lo [G4*EMB];
__device__ __align__(16) bf16 g_wout_hi[VOCP*HID], g_wout_lo[VOCP*HID];

__global__ void init_state_kernel() {
    int i = blockIdx.x*blockDim.x + threadIdx.x;
    if (i < Bsz*HID) { g_h[0][i] = 0.f; g_c[i] = 0.f; }
}

// ===================== split fp32 -> (hi, lo) bf16 =====================
__global__ void split_mat(const float* __restrict__ src, int ldsrc, int Nreal, int K,
                          bf16* __restrict__ hi, bf16* __restrict__ lo, int Npad)
{
    size_t i = (size_t)blockIdx.x*blockDim.x + threadIdx.x;
    if (i >= (size_t)Npad*K) return;
    int n = (int)(i / K), k = (int)(i % K);
    float x = (n < Nreal) ? src[(size_t)n*ldsrc + k] : 0.f;
    bf16 h = __float2bfloat16(x);
    hi[i] = h;
    lo[i] = __float2bfloat16(x - __bfloat162float(h));
}

// ===================== HMMA bf16 NT GEMM, 3-pass split ================
// C[m,n] = sum_p Ap[m,k]*Bp[n,k]  (+bias[n]) (+rowAdd[m0/128, n])
// Block 128x128, BK=32, 8 warps (2m x 4n), warp tile 64x32.
// Requires M%128==0, Npad%128==0, K%32==0. B rows padded to Npad (zeros).
#define SPAD 40   // padded row stride in bf16 (80 bytes)

__global__ __launch_bounds__(256)
void hmma_nt(const bf16* __restrict__ Ahi, const bf16* __restrict__ Alo,
             const bf16* __restrict__ Bhi, const bf16* __restrict__ Blo,
             int K,
             float* __restrict__ C, bf16* __restrict__ Chi, bf16* __restrict__ Clo,
             int ldc, int Nreal,
             const float* __restrict__ bias,
             const float* __restrict__ rowAdd, int rowLd)
{
    __shared__ bf16 sA[2][128*SPAD];
    __shared__ bf16 sB[2][128*SPAD];

    const int tid = threadIdx.x;
    const int wid = tid >> 5, lane = tid & 31;
    const int warpM = wid & 1, warpN = wid >> 1;
    const int n0 = blockIdx.x * 128, m0 = blockIdx.y * 128;

    const int kch = K >> 5;        // chunks per pass
    const int nch = 3 * kch;

    // loader decomposition (4 chunks of 16B per thread)
    const int l_tile = tid >> 7;           // reused below differently; compute per-u
    (void)l_tile;

    auto load_chunk = [&](int c, int st) {
        const int p = c / kch, kc = c % kch;
        const bf16* Ap = (p == 1) ? Alo : Ahi;
        const bf16* Bp = (p == 2) ? Blo : Bhi;
        #pragma unroll
        for (int j = 0; j < 4; j++) {
            const int u = tid + j * 256;          // 0..1023
            const int tile = u >> 9;              // 0:A 1:B
            const int row = (u >> 2) & 127;
            const int seg = u & 3;
            const bf16* g = (tile ? Bp + (size_t)(n0 + row) * K
                                  : Ap + (size_t)(m0 + row) * K) + kc * 32 + seg * 8;
            bf16* dst = (tile ? sB[st] : sA[st]) + row * SPAD + seg * 8;
            cp16(smem_u32(dst), g);
        }
        CP_COMMIT();
    };

    float acc[4][4][4];
    #pragma unroll
    for (int a=0;a<4;a++)
        #pragma unroll
        for (int b=0;b<4;b++)
            #pragma unroll
            for (int d=0;d<4;d++) acc[a][b][d] = 0.f;

    // prologue: fill both stages
    load_chunk(0, 0);
    if (nch > 1) load_chunk(1, 1);

    const uint32_t aAddrBase0 = smem_u32(&sA[0][0]) +
        (uint32_t)((warpM*64 + (lane & 15)) * SPAD * 2) + ((lane >> 4) * 16);
    const uint32_t bAddrBase0 = smem_u32(&sB[0][0]) +
        (uint32_t)((warpN*32 + (lane & 15)) * SPAD * 2) + ((lane >> 4) * 16);
    const uint32_t stageOff = (uint32_t)(128 * SPAD * 2);

    for (int c = 0; c < nch; c++) {
        const int st = c & 1;
        if (c + 1 < nch) { CP_WAIT(1); } else { CP_WAIT(0); }
        __syncthreads();

        const uint32_t aB = aAddrBase0 + st * stageOff;
        const uint32_t bB = bAddrBase0 + st * stageOff;

        #pragma unroll
        for (int ks = 0; ks < 2; ks++) {
            uint32_t a[4][4];
            #pragma unroll
            for (int mf = 0; mf < 4; mf++)
                LDM_X4(a[mf][0], a[mf][1], a[mf][2], a[mf][3],
                       aB + (uint32_t)(mf * 16 * SPAD * 2) + ks * 32);
            uint32_t br[2][4];
            #pragma unroll
            for (int nq = 0; nq < 2; nq++)
                LDM_X4(br[nq][0], br[nq][1], br[nq][2], br[nq][3],
                       bB + (uint32_t)(nq * 16 * SPAD * 2) + ks * 32);
            #pragma unroll
            for (int mf = 0; mf < 4; mf++) {
                #pragma unroll
                for (int nf = 0; nf < 4; nf++) {
                    const int nq = nf >> 1, nh = nf & 1;
                    MMA_BF16(acc[mf][nf][0], acc[mf][nf][1], acc[mf][nf][2], acc[mf][nf][3],
                             a[mf][0], a[mf][1], a[mf][2], a[mf][3],
                             br[nq][nh], br[nq][nh + 2]);
                }
            }
        }
        __syncthreads();
        if (c + 2 < nch) load_chunk(c + 2, st);
    }

    // ---------------- epilogue ----------------
    const int rowbase = rowAdd ? (m0 >> 7) * rowLd : 0;
    const int mloc = warpM*64 + (lane >> 2);
    const int nloc = warpN*32 + 2*(lane & 3);

    #pragma unroll
    for (int mf = 0; mf < 4; mf++) {
        #pragma unroll
        for (int nf = 0; nf < 4; nf++) {
            const int gn = n0 + nloc + nf*8;
            float add0 = 0.f, add1 = 0.f;
            if (bias)   { add0 += bias[gn]; add1 += bias[gn+1]; }
            if (rowAdd) { add0 += rowAdd[rowbase + gn]; add1 += rowAdd[rowbase + gn + 1]; }
            #pragma unroll
            for (int half = 0; half < 2; half++) {
                const int gm = m0 + mloc + mf*16 + half*8;
                const float v0 = acc[mf][nf][half*2 + 0] + add0;
                const float v1 = acc[mf][nf][half*2 + 1] + add1;
                if (gn < Nreal) {
                    const size_t off = (size_t)gm * ldc + gn;
                    if (C) *(float2*)(C + off) = make_float2(v0, v1);
                    if (Chi) {
                        bf16 h0 = __float2bfloat16(v0);
                        bf16 h1 = __float2bfloat16(v1);
                        __nv_bfloat162 hv; hv.x = h0; hv.y = h1;
                        __nv_bfloat162 lv;
                        lv.x = __float2bfloat16(v0 - __bfloat162float(h0));
                        lv.y = __float2bfloat16(v1 - __bfloat162float(h1));
                        *(__nv_bfloat162*)(Chi + off) = hv;
                        *(__nv_bfloat162*)(Clo + off) = lv;
                    }
                }
            }
        }
    }
}

// ===================== small fp32 NT SGEMM =====================
__global__ __launch_bounds__(256)
void gemm64(const float* __restrict__ A, int lda,
            const float* __restrict__ W, int ldw,
            float* __restrict__ C, int ldc,
            int M, int N, int K,
            const float* __restrict__ bias)
{
    __shared__ float As[16][68];
    __shared__ float Ws[16][68];
    const int n0 = blockIdx.x*64, m0 = blockIdx.y*64;
    const int t  = threadIdx.x;
    const int lr = t>>2, lc = (t&3)*4;
    const int tx = t&15, ty = t>>4;
    const int cm = ty*4, cn = tx*4;
    float acc[4][4] = {};
    const float* Ap = A + (size_t)(m0+lr)*lda + lc;
    const bool wok = (n0+lr) < N;
    const float* Wp = W + (size_t)(wok ? (n0+lr) : 0)*ldw + lc;
    float4 av = *(const float4*)Ap;
    float4 wv = wok ? *(const float4*)Wp : make_float4(0,0,0,0);
    for (int k0 = 0; k0 < K; k0 += 16) {
        As[lc+0][lr]=av.x; As[lc+1][lr]=av.y; As[lc+2][lr]=av.z; As[lc+3][lr]=av.w;
        Ws[lc+0][lr]=wv.x; Ws[lc+1][lr]=wv.y; Ws[lc+2][lr]=wv.z; Ws[lc+3][lr]=wv.w;
        __syncthreads();
        if (k0 + 16 < K) {
            av = *(const float4*)(Ap + k0 + 16);
            wv = wok ? *(const float4*)(Wp + k0 + 16) : make_float4(0,0,0,0);
        }
        #pragma unroll
        for (int kk = 0; kk < 16; kk++) {
            float4 a = *(const float4*)&As[kk][cm];
            float4 w = *(const float4*)&Ws[kk][cn];
            acc[0][0]+=a.x*w.x; acc[0][1]+=a.x*w.y; acc[0][2]+=a.x*w.z; acc[0][3]+=a.x*w.w;
            acc[1][0]+=a.y*w.x; acc[1][1]+=a.y*w.y; acc[1][2]+=a.y*w.z; acc[1][3]+=a.y*w.w;
            acc[2][0]+=a.z*w.x; acc[2][1]+=a.z*w.y; acc[2][2]+=a.z*w.z; acc[2][3]+=a.z*w.w;
            acc[3][0]+=a.w*w.x; acc[3][1]+=a.w*w.y; acc[3][2]+=a.w*w.z; acc[3][3]+=a.w*w.w;
        }
        __syncthreads();
    }
    #pragma unroll
    for (int i = 0; i < 4; i++) {
        const int gm = m0 + cm + i;
        #pragma unroll
        for (int j = 0; j < 4; j++) {
            const int gn = n0 + cn + j;
            if (gn < N) C[(size_t)gm*ldc + gn] = acc[i][j] + (bias ? bias[gn] : 0.f);
        }
    }
}

// ===================== fused LSTM step =====================
__global__ __launch_bounds__(256)
void lstm_step(const float* __restrict__ W_hh,
               const float* __restrict__ b_hh,
               int tstep)
{
    __shared__ float As[16][36];
    __shared__ float Ws[16][132];
    const float* __restrict__ h_in  = g_h[tstep & 1];
    float*       __restrict__ h_out = g_h[(tstep+1) & 1];
    const int b0 = blockIdx.x*32, h0 = blockIdx.y*32;
    const int t  = threadIdx.x;
    const int lr = t>>2, lc = (t&3)*4;
    const int th = t & 31;
    const int tmb = (t>>5)*4;
    float acc[4][4] = {};
    const int i0 = t,      br0 = i0>>2, bc0 = (i0&3)*4, ga0 = br0>>5, j0 = br0&31;
    const int i1 = t+256,  br1 = i1>>2, bc1 = (i1&3)*4, ga1 = br1>>5, j1 = br1&31;
    const float* Wp0 = W_hh + (size_t)(ga0*HID + h0 + j0)*HID + bc0;
    const float* Wp1 = W_hh + (size_t)(ga1*HID + h0 + j1)*HID + bc1;
    const float* Ap  = h_in + (size_t)(b0 + lr)*HID + lc;
    float4 av = (t < 128) ? *(const float4*)Ap : make_float4(0,0,0,0);
    float4 wv0 = *(const float4*)Wp0;
    float4 wv1 = *(const float4*)Wp1;
    for (int k0 = 0; k0 < HID; k0 += 16) {
        if (t < 128) {
            As[lc+0][lr]=av.x; As[lc+1][lr]=av.y; As[lc+2][lr]=av.z; As[lc+3][lr]=av.w;
        }
        Ws[bc0+0][br0]=wv0.x; Ws[bc0+1][br0]=wv0.y; Ws[bc0+2][br0]=wv0.z; Ws[bc0+3][br0]=wv0.w;
        Ws[bc1+0][br1]=wv1.x; Ws[bc1+1][br1]=wv1.y; Ws[bc1+2][br1]=wv1.z; Ws[bc1+3][br1]=wv1.w;
        __syncthreads();
        if (k0 + 16 < HID) {
            if (t < 128) av = *(const float4*)(Ap + k0 + 16);
            wv0 = *(const float4*)(Wp0 + k0 + 16);
            wv1 = *(const float4*)(Wp1 + k0 + 16);
        }
        #pragma unroll
        for (int kk = 0; kk < 16; kk++) {
            float4 a = *(const float4*)&As[kk][tmb];
            float wi = Ws[kk][      th];
            float wf = Ws[kk][ 32 + th];
            float wg = Ws[kk][ 64 + th];
            float wo = Ws[kk][ 96 + th];
            acc[0][0]+=a.x*wi; acc[0][1]+=a.y*wi; acc[0][2]+=a.z*wi; acc[0][3]+=a.w*wi;
            acc[1][0]+=a.x*wf; acc[1][1]+=a.y*wf; acc[1][2]+=a.z*wf; acc[1][3]+=a.w*wf;
            acc[2][0]+=a.x*wg; acc[2][1]+=a.y*wg; acc[2][2]+=a.z*wg; acc[2][3]+=a.w*wg;
            acc[3][0]+=a.x*wo; acc[3][1]+=a.y*wo; acc[3][2]+=a.z*wo; acc[3][3]+=a.w*wo;
        }
        __syncthreads();
    }
    const int h = h0 + th;
    const float bi = b_hh[h];
    const float bf = b_hh[HID   + h];
    const float bg = b_hh[2*HID + h];
    const float bo = b_hh[3*HID + h];
    #pragma unroll
    for (int i = 0; i < 4; i++) {
        const int b = b0 + tmb + i;
        const size_t base = ((size_t)b*Tsz + tstep)*G4;
        float gi = acc[0][i] + g_gatesX[base +           h] + bi;
        float gf = acc[1][i] + g_gatesX[base + HID   +   h] + bf;
        float gg = acc[2][i] + g_gatesX[base + 2*HID +   h] + bg;
        float go = acc[3][i] + g_gatesX[base + 3*HID +   h] + bo;
        float si = 1.f/(1.f + expf(-gi));
        float sf = 1.f/(1.f + expf(-gf));
        float so = 1.f/(1.f + expf(-go));
        const int ch = b*HID + h;
        float cnew = sf*g_c[ch] + si*tanhf(gg);
        float hnew = so*tanhf(cnew);
        g_c[ch]   = cnew;
        h_out[ch] = hnew;
        const size_t ho = ((size_t)b*Tsz + tstep)*HID + h;
        bf16 hh = __float2bfloat16(hnew);
        g_hseq_hi[ho] = hh;
        g_hseq_lo[ho] = __float2bfloat16(hnew - __bfloat162float(hh));
    }
}

// ===================== launch =====================
extern "C" void kernel_launch(void* const* d_in, const int* in_sizes, int n_in,
                              void* d_out, int out_size)
{
    const float* images   = (const float*)d_in[0];
    const float* captions = (const float*)d_in[1];
    const float* W_fc  = (const float*)d_in[2];
    const float* b_fc  = (const float*)d_in[3];
    const float* W_att = (const float*)d_in[4];
    const float* b_att = (const float*)d_in[5];
    const float* W_ih  = (const float*)d_in[6];
    const float* b_ih  = (const float*)d_in[7];
    const float* W_hh  = (const float*)d_in[8];
    const float* b_hh  = (const float*)d_in[9];
    const float* W_out = (const float*)d_in[10];
    const float* b_out = (const float*)d_in[11];
    float* out = (float*)d_out;

    float *p_feats, *p_ctxb, *p_gateb, *p_gatesX;
    bf16 *p_cap_hi, *p_cap_lo, *p_ctx_hi, *p_ctx_lo, *p_hseq_hi, *p_hseq_lo;
    bf16 *p_watt_hi, *p_watt_lo, *p_wih_hi, *p_wih_lo, *p_wout_hi, *p_wout_lo;
    cudaGetSymbolAddress((void**)&p_feats,  g_feats);
    cudaGetSymbolAddress((void**)&p_ctxb,   g_ctx_base);
    cudaGetSymbolAddress((void**)&p_gateb,  g_gate_base);
    cudaGetSymbolAddress((void**)&p_gatesX, g_gatesX);
    cudaGetSymbolAddress((void**)&p_cap_hi, g_cap_hi);
    cudaGetSymbolAddress((void**)&p_cap_lo, g_cap_lo);
    cudaGetSymbolAddress((void**)&p_ctx_hi, g_ctx_hi);
    cudaGetSymbolAddress((void**)&p_ctx_lo, g_ctx_lo);
    cudaGetSymbolAddress((void**)&p_hseq_hi, g_hseq_hi);
    cudaGetSymbolAddress((void**)&p_hseq_lo, g_hseq_lo);
    cudaGetSymbolAddress((void**)&p_watt_hi, g_watt_hi);
    cudaGetSymbolAddress((void**)&p_watt_lo, g_watt_lo);
    cudaGetSymbolAddress((void**)&p_wih_hi, g_wih_hi);
    cudaGetSymbolAddress((void**)&p_wih_lo, g_wih_lo);
    cudaGetSymbolAddress((void**)&p_wout_hi, g_wout_hi);
    cudaGetSymbolAddress((void**)&p_wout_lo, g_wout_lo);

    init_state_kernel<<<(Bsz*HID + 255)/256, 256>>>();

    // ---- fp32 -> bf16 splits ----
    split_mat<<<((size_t)BT*HID + 255)/256, 256>>>(captions, HID, BT, HID, p_cap_hi, p_cap_lo, BT);
    split_mat<<<(EMB*HID + 255)/256, 256>>>(W_att + EMB, EMB+HID, EMB, HID, p_watt_hi, p_watt_lo, EMB);
    split_mat<<<(G4*EMB + 255)/256, 256>>>(W_ih + EMB, 2*EMB, G4, EMB, p_wih_hi, p_wih_lo, G4);
    split_mat<<<(VOCP*HID + 255)/256, 256>>>(W_out, HID, VOC, HID, p_wout_hi, p_wout_lo, VOCP);

    // ---- small fp32 GEMMs ----
    gemm64<<<dim3(EMB/64, Bsz/64), 256>>>(images, FCI, W_fc, FCI, p_feats, EMB, Bsz, EMB, FCI, b_fc);
    gemm64<<<dim3(EMB/64, Bsz/64), 256>>>(p_feats, EMB, W_att, EMB+HID, p_ctxb, EMB, Bsz, EMB, EMB, b_att);
    gemm64<<<dim3(G4/64, Bsz/64), 256>>>(p_feats, EMB, W_ih, 2*EMB, p_gateb, G4, Bsz, G4, EMB, b_ih);

    // ---- ctx = captions @ W_att'^T + ctx_base  ->  split bf16 ----
    hmma_nt<<<dim3(EMB/128, BT/128), 256>>>(
        p_cap_hi, p_cap_lo, p_watt_hi, p_watt_lo, HID,
        nullptr, p_ctx_hi, p_ctx_lo, EMB, EMB, nullptr, p_ctxb, EMB);

    // ---- gatesX = ctx @ W_ih'^T + gate_base  ->  fp32 ----
    hmma_nt<<<dim3(G4/128, BT/128), 256>>>(
        p_ctx_hi, p_ctx_lo, p_wih_hi, p_wih_lo, EMB,
        p_gatesX, nullptr, nullptr, G4, G4, nullptr, p_gateb, G4);

    // ---- recurrence ----
    for (int t = 0; t < Tsz; t++)
        lstm_step<<<dim3(Bsz/32, HID/32), 256>>>(W_hh, b_hh, t);

    // ---- out = hseq @ W_out^T + b_out ----
    hmma_nt<<<dim3(VOCP/128, BT/128), 256>>>(
        p_hseq_hi, p_hseq_lo, p_wout_hi, p_wout_lo, HID,
        out, nullptr, nullptr, VOC, VOC, b_out, nullptr, 0);
}

// round 5
// speedup vs baseline: 2.0942x; 1.4198x over previous
#include <cuda_runtime.h>
#include <cuda_bf16.h>
#include <math.h>
#include <cstdint>

#define Bsz 256
#define Tsz 128
#define EMB 256
#define HID 512
#define VOC 1004
#define VOCP 1024
#define FCI 2048
#define BT  (Bsz*Tsz)
#define G4  (4*HID)

typedef __nv_bfloat16 bf16;

// ===================== PTX helpers =====================
__device__ __forceinline__ uint32_t smem_u32(const void* p) {
    uint32_t a;
    asm("{ .reg .u64 t; cvta.to.shared.u64 t, %1; cvt.u32.u64 %0, t; }" : "=r"(a) : "l"(p));
    return a;
}
__device__ __forceinline__ void cp16(uint32_t s, const void* g) {
    asm volatile("cp.async.cg.shared.global [%0], [%1], 16;" :: "r"(s), "l"(g) : "memory");
}
#define CP_COMMIT() asm volatile("cp.async.commit_group;" ::: "memory")
#define CP_WAIT(n)  asm volatile("cp.async.wait_group %0;" :: "n"(n) : "memory")

#define LDM_X4(r0,r1,r2,r3, addr) \
    asm volatile("ldmatrix.sync.aligned.m8n8.x4.shared.b16 {%0,%1,%2,%3}, [%4];" \
        : "=r"(r0), "=r"(r1), "=r"(r2), "=r"(r3) : "r"(addr))

#define MMA_BF16(c0,c1,c2,c3, a0,a1,a2,a3, b0,b1) \
    asm volatile("mma.sync.aligned.m16n8k16.row.col.f32.bf16.bf16.f32 " \
        "{%0,%1,%2,%3}, {%4,%5,%6,%7}, {%8,%9}, {%0,%1,%2,%3};" \
        : "+f"(c0), "+f"(c1), "+f"(c2), "+f"(c3) \
        : "r"(a0), "r"(a1), "r"(a2), "r"(a3), "r"(b0), "r"(b1))

// ===================== device scratch =====================
__device__ __align__(16) float g_feats    [Bsz*EMB];
__device__ __align__(16) float g_ctx_base [Bsz*EMB];
__device__ __align__(16) float g_gate_base[Bsz*G4];
__device__ __align__(16) float g_gatesX   [(size_t)BT*G4];    // [t][b][j] layout
__device__ __align__(16) float g_c        [Bsz*HID];
__device__ __align__(16) float g_bcomb    [G4];
__device__ __align__(16) float g_w0p      [G4*EMB];

__device__ __align__(16) bf16 g_hhi[2][Bsz*HID];
__device__ __align__(16) bf16 g_hlo[2][Bsz*HID];

__device__ __align__(16) bf16 g_cap_hi [(size_t)BT*HID];
__device__ __align__(16) bf16 g_cap_lo [(size_t)BT*HID];
__device__ __align__(16) bf16 g_ctx_hi [(size_t)BT*EMB];
__device__ __align__(16) bf16 g_ctx_lo [(size_t)BT*EMB];
__device__ __align__(16) bf16 g_hseq_hi[(size_t)BT*HID];
__device__ __align__(16) bf16 g_hseq_lo[(size_t)BT*HID];
__device__ __align__(16) bf16 g_watt_hi[EMB*HID],  g_watt_lo[EMB*HID];
__device__ __align__(16) bf16 g_wihp_hi[G4*EMB],   g_wihp_lo[G4*EMB];
__device__ __align__(16) bf16 g_whhp_hi[G4*HID],   g_whhp_lo[G4*HID];
__device__ __align__(16) bf16 g_wout_hi[VOCP*HID], g_wout_lo[VOCP*HID];

__global__ void init_state_kernel() {
    int i = blockIdx.x*blockDim.x + threadIdx.x;
    if (i < Bsz*HID) {
        g_c[i] = 0.f;
        g_hhi[0][i] = __float2bfloat16(0.f);
        g_hlo[0][i] = __float2bfloat16(0.f);
    }
}

// ===================== split fp32 -> (hi, lo) bf16 =====================
__global__ void split_mat(const float* __restrict__ src, int ldsrc, int Nreal, int K,
                          bf16* __restrict__ hi, bf16* __restrict__ lo, int Npad)
{
    size_t i = (size_t)blockIdx.x*blockDim.x + threadIdx.x;
    if (i >= (size_t)Npad*K) return;
    int n = (int)(i / K), k = (int)(i % K);
    float x = (n < Nreal) ? src[(size_t)n*ldsrc + k] : 0.f;
    bf16 h = __float2bfloat16(x);
    hi[i] = h;
    lo[i] = __float2bfloat16(x - __bfloat162float(h));
}

// perm rows g*HID+h -> j=h*4+g, then split
__global__ void perm_split_w(const float* __restrict__ src, int ldsrc, int koff, int K,
                             bf16* __restrict__ hi, bf16* __restrict__ lo)
{
    size_t i = (size_t)blockIdx.x*blockDim.x + threadIdx.x;
    if (i >= (size_t)G4*K) return;
    int j = (int)(i / K), k = (int)(i % K);
    int h = j >> 2, g = j & 3;
    float x = src[(size_t)(g*HID + h)*ldsrc + koff + k];
    bf16 hh = __float2bfloat16(x);
    hi[i] = hh;
    lo[i] = __float2bfloat16(x - __bfloat162float(hh));
}

// perm rows of W_ih first half (fp32) + combined bias
__global__ void perm_w0_bias(const float* __restrict__ W_ih,
                             const float* __restrict__ b_ih,
                             const float* __restrict__ b_hh)
{
    int i = blockIdx.x*blockDim.x + threadIdx.x;
    if (i >= G4*EMB) return;
    int j = i >> 8, k = i & 255;
    int h = j >> 2, g = j & 3;
    g_w0p[i] = W_ih[(size_t)(g*HID + h)*(2*EMB) + k];
    if (k == 0) g_bcomb[j] = b_ih[g*HID + h] + b_hh[g*HID + h];
}

// ===================== HMMA bf16 NT GEMM, 3-pass split ================
#define SPAD 40

__global__ __launch_bounds__(256)
void hmma_nt(const bf16* __restrict__ Ahi, const bf16* __restrict__ Alo,
             const bf16* __restrict__ Bhi, const bf16* __restrict__ Blo,
             int K,
             float* __restrict__ C, bf16* __restrict__ Chi, bf16* __restrict__ Clo,
             int ldc, int Nreal,
             const float* __restrict__ bias,
             const float* __restrict__ rowAdd, int rowLd,
             int rowSwap)
{
    __shared__ bf16 sA[2][128*SPAD];
    __shared__ bf16 sB[2][128*SPAD];

    const int tid = threadIdx.x;
    const int wid = tid >> 5, lane = tid & 31;
    const int warpM = wid & 1, warpN = wid >> 1;
    const int n0 = blockIdx.x * 128, m0 = blockIdx.y * 128;

    const int kch = K >> 5;
    const int nch = 3 * kch;

    auto load_chunk = [&](int c, int st) {
        const int p = c / kch, kc = c % kch;
        const bf16* Ap = (p == 1) ? Alo : Ahi;
        const bf16* Bp = (p == 2) ? Blo : Bhi;
        #pragma unroll
        for (int j = 0; j < 4; j++) {
            const int u = tid + j * 256;
            const int tile = u >> 9;
            const int row = (u >> 2) & 127;
            const int seg = u & 3;
            const bf16* g = (tile ? Bp + (size_t)(n0 + row) * K
                                  : Ap + (size_t)(m0 + row) * K) + kc * 32 + seg * 8;
            bf16* dst = (tile ? sB[st] : sA[st]) + row * SPAD + seg * 8;
            cp16(smem_u32(dst), g);
        }
        CP_COMMIT();
    };

    float acc[4][4][4];
    #pragma unroll
    for (int a=0;a<4;a++)
        #pragma unroll
        for (int b=0;b<4;b++)
            #pragma unroll
            for (int d=0;d<4;d++) acc[a][b][d] = 0.f;

    load_chunk(0, 0);
    if (nch > 1) load_chunk(1, 1);

    const uint32_t aAddrBase0 = smem_u32(&sA[0][0]) +
        (uint32_t)((warpM*64 + (lane & 15)) * SPAD * 2) + ((lane >> 4) * 16);
    const uint32_t bAddrBase0 = smem_u32(&sB[0][0]) +
        (uint32_t)((warpN*32 + (lane & 15)) * SPAD * 2) + ((lane >> 4) * 16);
    const uint32_t stageOff = (uint32_t)(128 * SPAD * 2);

    for (int c = 0; c < nch; c++) {
        const int st = c & 1;
        if (c + 1 < nch) { CP_WAIT(1); } else { CP_WAIT(0); }
        __syncthreads();

        const uint32_t aB = aAddrBase0 + st * stageOff;
        const uint32_t bB = bAddrBase0 + st * stageOff;

        #pragma unroll
        for (int ks = 0; ks < 2; ks++) {
            uint32_t a[4][4];
            #pragma unroll
            for (int mf = 0; mf < 4; mf++)
                LDM_X4(a[mf][0], a[mf][1], a[mf][2], a[mf][3],
                       aB + (uint32_t)(mf * 16 * SPAD * 2) + ks * 32);
            uint32_t br[2][4];
            #pragma unroll
            for (int nq = 0; nq < 2; nq++)
                LDM_X4(br[nq][0], br[nq][1], br[nq][2], br[nq][3],
                       bB + (uint32_t)(nq * 16 * SPAD * 2) + ks * 32);
            #pragma unroll
            for (int mf = 0; mf < 4; mf++) {
                #pragma unroll
                for (int nf = 0; nf < 4; nf++) {
                    const int nq = nf >> 1, nh = nf & 1;
                    MMA_BF16(acc[mf][nf][0], acc[mf][nf][1], acc[mf][nf][2], acc[mf][nf][3],
                             a[mf][0], a[mf][1], a[mf][2], a[mf][3],
                             br[nq][nh], br[nq][nh + 2]);
                }
            }
        }
        __syncthreads();
        if (c + 2 < nch) load_chunk(c + 2, st);
    }

    const int rowbase = rowAdd ? (m0 >> 7) * rowLd : 0;
    const int mloc = warpM*64 + (lane >> 2);
    const int nloc = warpN*32 + 2*(lane & 3);

    #pragma unroll
    for (int mf = 0; mf < 4; mf++) {
        #pragma unroll
        for (int nf = 0; nf < 4; nf++) {
            const int gn = n0 + nloc + nf*8;
            float add0 = 0.f, add1 = 0.f;
            if (bias)   { add0 += bias[gn]; add1 += bias[gn+1]; }
            if (rowAdd) { add0 += rowAdd[rowbase + gn]; add1 += rowAdd[rowbase + gn + 1]; }
            #pragma unroll
            for (int half = 0; half < 2; half++) {
                const int gm = m0 + mloc + mf*16 + half*8;
                const int grow = rowSwap ? (gm % Tsz)*Bsz + gm/Tsz : gm;
                const float v0 = acc[mf][nf][half*2 + 0] + add0;
                const float v1 = acc[mf][nf][half*2 + 1] + add1;
                if (gn < Nreal) {
                    const size_t off = (size_t)grow * ldc + gn;
                    if (C) *(float2*)(C + off) = make_float2(v0, v1);
                    if (Chi) {
                        bf16 h0 = __float2bfloat16(v0);
                        bf16 h1 = __float2bfloat16(v1);
                        __nv_bfloat162 hv; hv.x = h0; hv.y = h1;
                        __nv_bfloat162 lv;
                        lv.x = __float2bfloat16(v0 - __bfloat162float(h0));
                        lv.y = __float2bfloat16(v1 - __bfloat162float(h1));
                        *(__nv_bfloat162*)(Chi + off) = hv;
                        *(__nv_bfloat162*)(Clo + off) = lv;
                    }
                }
            }
        }
    }
}

// ===================== small fp32 NT SGEMM =====================
__global__ __launch_bounds__(256)
void gemm64(const float* __restrict__ A, int lda,
            const float* __restrict__ W, int ldw,
            float* __restrict__ C, int ldc,
            int M, int N, int K,
            const float* __restrict__ bias)
{
    __shared__ float As[16][68];
    __shared__ float Ws[16][68];
    const int n0 = blockIdx.x*64, m0 = blockIdx.y*64;
    const int t  = threadIdx.x;
    const int lr = t>>2, lc = (t&3)*4;
    const int tx = t&15, ty = t>>4;
    const int cm = ty*4, cn = tx*4;
    float acc[4][4] = {};
    const float* Ap = A + (size_t)(m0+lr)*lda + lc;
    const bool wok = (n0+lr) < N;
    const float* Wp = W + (size_t)(wok ? (n0+lr) : 0)*ldw + lc;
    float4 av = *(const float4*)Ap;
    float4 wv = wok ? *(const float4*)Wp : make_float4(0,0,0,0);
    for (int k0 = 0; k0 < K; k0 += 16) {
        As[lc+0][lr]=av.x; As[lc+1][lr]=av.y; As[lc+2][lr]=av.z; As[lc+3][lr]=av.w;
        Ws[lc+0][lr]=wv.x; Ws[lc+1][lr]=wv.y; Ws[lc+2][lr]=wv.z; Ws[lc+3][lr]=wv.w;
        __syncthreads();
        if (k0 + 16 < K) {
            av = *(const float4*)(Ap + k0 + 16);
            wv = wok ? *(const float4*)(Wp + k0 + 16) : make_float4(0,0,0,0);
        }
        #pragma unroll
        for (int kk = 0; kk < 16; kk++) {
            float4 a = *(const float4*)&As[kk][cm];
            float4 w = *(const float4*)&Ws[kk][cn];
            acc[0][0]+=a.x*w.x; acc[0][1]+=a.x*w.y; acc[0][2]+=a.x*w.z; acc[0][3]+=a.x*w.w;
            acc[1][0]+=a.y*w.x; acc[1][1]+=a.y*w.y; acc[1][2]+=a.y*w.z; acc[1][3]+=a.y*w.w;
            acc[2][0]+=a.z*w.x; acc[2][1]+=a.z*w.y; acc[2][2]+=a.z*w.z; acc[2][3]+=a.z*w.w;
            acc[3][0]+=a.w*w.x; acc[3][1]+=a.w*w.y; acc[3][2]+=a.w*w.z; acc[3][3]+=a.w*w.w;
        }
        __syncthreads();
    }
    #pragma unroll
    for (int i = 0; i < 4; i++) {
        const int gm = m0 + cm + i;
        #pragma unroll
        for (int j = 0; j < 4; j++) {
            const int gn = n0 + cn + j;
            if (gn < N) C[(size_t)gm*ldc + gn] = acc[i][j] + (bias ? bias[gn] : 0.f);
        }
    }
}

// ===================== HMMA LSTM step =====================
// gates[b, j] = gatesX[t][b][j] + h @ whhp^T (3-pass split), j = h*4+g.
// Block 64(m=batch) x 64(n=j), BK=64, 8 warps (2m x 4n), warp tile 32x16.
// Epilogue: fused LSTM cell for 64 b x 16 h, writes c, h(hi/lo), hseq(hi/lo).
#define LSPAD 72

__global__ __launch_bounds__(256)
void lstm_hmma(int tstep)
{
    __shared__ bf16 sA[2][64*LSPAD];
    __shared__ bf16 sB[2][64*LSPAD];

    const bf16* __restrict__ Ahi = g_hhi[tstep & 1];
    const bf16* __restrict__ Alo = g_hlo[tstep & 1];
    bf16* __restrict__ Hhi = g_hhi[(tstep+1) & 1];
    bf16* __restrict__ Hlo = g_hlo[(tstep+1) & 1];

    const int tid = threadIdx.x;
    const int wid = tid >> 5, lane = tid & 31;
    const int warpM = wid & 1, warpN = wid >> 1;
    const int n0 = blockIdx.x * 64, m0 = blockIdx.y * 64;

    auto load_chunk = [&](int c, int st) {
        const int p = c >> 3, kc = c & 7;
        const bf16* Ap = (p == 1) ? Alo : Ahi;
        const bf16* Bp = (p == 2) ? g_whhp_lo : g_whhp_hi;
        #pragma unroll
        for (int j = 0; j < 4; j++) {
            const int u = tid + j * 256;          // 0..1023
            const int tile = u >> 9;              // 0:A 1:B
            const int row = (u >> 3) & 63;
            const int seg = u & 7;
            const bf16* g = (tile ? Bp + (size_t)(n0 + row) * HID
                                  : Ap + (size_t)(m0 + row) * HID) + kc * 64 + seg * 8;
            bf16* dst = (tile ? sB[st] : sA[st]) + row * LSPAD + seg * 8;
            cp16(smem_u32(dst), g);
        }
        CP_COMMIT();
    };

    float acc[2][2][4];
    #pragma unroll
    for (int a=0;a<2;a++)
        #pragma unroll
        for (int b=0;b<2;b++)
            #pragma unroll
            for (int d=0;d<4;d++) acc[a][b][d] = 0.f;

    load_chunk(0, 0);
    load_chunk(1, 1);

    const uint32_t aAddrBase0 = smem_u32(&sA[0][0]) +
        (uint32_t)((warpM*32 + (lane & 15)) * LSPAD * 2) + ((lane >> 4) * 16);
    const uint32_t bAddrBase0 = smem_u32(&sB[0][0]) +
        (uint32_t)((warpN*16 + (lane & 15)) * LSPAD * 2) + ((lane >> 4) * 16);
    const uint32_t stageOff = (uint32_t)(64 * LSPAD * 2);

    const int nch = 24;   // 3 passes x 8 chunks
    for (int c = 0; c < nch; c++) {
        const int st = c & 1;
        if (c + 1 < nch) { CP_WAIT(1); } else { CP_WAIT(0); }
        __syncthreads();

        const uint32_t aB = aAddrBase0 + st * stageOff;
        const uint32_t bB = bAddrBase0 + st * stageOff;

        #pragma unroll
        for (int ks = 0; ks < 4; ks++) {
            uint32_t a[2][4];
            #pragma unroll
            for (int mf = 0; mf < 2; mf++)
                LDM_X4(a[mf][0], a[mf][1], a[mf][2], a[mf][3],
                       aB + (uint32_t)(mf * 16 * LSPAD * 2) + ks * 32);
            uint32_t br[4];
            LDM_X4(br[0], br[1], br[2], br[3], bB + ks * 32);
            #pragma unroll
            for (int mf = 0; mf < 2; mf++) {
                MMA_BF16(acc[mf][0][0], acc[mf][0][1], acc[mf][0][2], acc[mf][0][3],
                         a[mf][0], a[mf][1], a[mf][2], a[mf][3], br[0], br[2]);
                MMA_BF16(acc[mf][1][0], acc[mf][1][1], acc[mf][1][2], acc[mf][1][3],
                         a[mf][0], a[mf][1], a[mf][2], a[mf][3], br[1], br[3]);
            }
        }
        __syncthreads();
        if (c + 2 < nch) load_chunk(c + 2, st);
    }

    // stage gates tile to smem [64 b][64 n], stride 66
    float* sG = (float*)&sA[0][0];
    __syncthreads();
    {
        const int mloc = warpM*32 + (lane >> 2);
        const int nloc = warpN*16 + 2*(lane & 3);
        #pragma unroll
        for (int mf = 0; mf < 2; mf++) {
            #pragma unroll
            for (int nf = 0; nf < 2; nf++) {
                const int n = nloc + nf*8;
                #pragma unroll
                for (int half = 0; half < 2; half++) {
                    const int m = mloc + mf*16 + half*8;
                    *(float2*)&sG[m*66 + n] =
                        make_float2(acc[mf][nf][half*2], acc[mf][nf][half*2+1]);
                }
            }
        }
    }
    __syncthreads();

    // fused LSTM cell: 64 b x 16 h
    const int b = tid & 63;
    const int hq = tid >> 6;            // 0..3
    const int gb = m0 + b;
    const int h0q = n0 >> 2;
    #pragma unroll
    for (int j = 0; j < 4; j++) {
        const int hsub = hq*4 + j;      // 0..15
        const float4 gx = *(const float4*)&g_gatesX[((size_t)tstep*Bsz + gb)*G4 + n0 + hsub*4];
        const float gi = sG[b*66 + hsub*4 + 0] + gx.x;
        const float gf = sG[b*66 + hsub*4 + 1] + gx.y;
        const float gg = sG[b*66 + hsub*4 + 2] + gx.z;
        const float go = sG[b*66 + hsub*4 + 3] + gx.w;

        const float si = 1.f/(1.f + expf(-gi));
        const float sf = 1.f/(1.f + expf(-gf));
        const float so = 1.f/(1.f + expf(-go));

        const int ci = gb*HID + h0q + hsub;
        const float cnew = sf*g_c[ci] + si*tanhf(gg);
        const float hnew = so*tanhf(cnew);
        g_c[ci] = cnew;

        const bf16 hh = __float2bfloat16(hnew);
        const bf16 hl = __float2bfloat16(hnew - __bfloat162float(hh));
        Hhi[ci] = hh;
        Hlo[ci] = hl;
        const size_t ho = ((size_t)gb*Tsz + tstep)*HID + h0q + hsub;
        g_hseq_hi[ho] = hh;
        g_hseq_lo[ho] = hl;
    }
}

// ===================== launch =====================
extern "C" void kernel_launch(void* const* d_in, const int* in_sizes, int n_in,
                              void* d_out, int out_size)
{
    const float* images   = (const float*)d_in[0];
    const float* captions = (const float*)d_in[1];
    const float* W_fc  = (const float*)d_in[2];
    const float* b_fc  = (const float*)d_in[3];
    const float* W_att = (const float*)d_in[4];
    const float* b_att = (const float*)d_in[5];
    const float* W_ih  = (const float*)d_in[6];
    const float* b_ih  = (const float*)d_in[7];
    const float* W_hh  = (const float*)d_in[8];
    const float* b_hh  = (const float*)d_in[9];
    const float* W_out = (const float*)d_in[10];
    const float* b_out = (const float*)d_in[11];
    float* out = (float*)d_out;

    float *p_feats, *p_ctxb, *p_gateb, *p_gatesX, *p_bcomb, *p_w0p;
    bf16 *p_cap_hi, *p_cap_lo, *p_ctx_hi, *p_ctx_lo, *p_hseq_hi, *p_hseq_lo;
    bf16 *p_watt_hi, *p_watt_lo, *p_wihp_hi, *p_wihp_lo, *p_whhp_hi, *p_whhp_lo, *p_wout_hi, *p_wout_lo;
    cudaGetSymbolAddress((void**)&p_feats,  g_feats);
    cudaGetSymbolAddress((void**)&p_ctxb,   g_ctx_base);
    cudaGetSymbolAddress((void**)&p_gateb,  g_gate_base);
    cudaGetSymbolAddress((void**)&p_gatesX, g_gatesX);
    cudaGetSymbolAddress((void**)&p_bcomb,  g_bcomb);
    cudaGetSymbolAddress((void**)&p_w0p,    g_w0p);
    cudaGetSymbolAddress((void**)&p_cap_hi, g_cap_hi);
    cudaGetSymbolAddress((void**)&p_cap_lo, g_cap_lo);
    cudaGetSymbolAddress((void**)&p_ctx_hi, g_ctx_hi);
    cudaGetSymbolAddress((void**)&p_ctx_lo, g_ctx_lo);
    cudaGetSymbolAddress((void**)&p_hseq_hi, g_hseq_hi);
    cudaGetSymbolAddress((void**)&p_hseq_lo, g_hseq_lo);
    cudaGetSymbolAddress((void**)&p_watt_hi, g_watt_hi);
    cudaGetSymbolAddress((void**)&p_watt_lo, g_watt_lo);
    cudaGetSymbolAddress((void**)&p_wihp_hi, g_wihp_hi);
    cudaGetSymbolAddress((void**)&p_wihp_lo, g_wihp_lo);
    cudaGetSymbolAddress((void**)&p_whhp_hi, g_whhp_hi);
    cudaGetSymbolAddress((void**)&p_whhp_lo, g_whhp_lo);
    cudaGetSymbolAddress((void**)&p_wout_hi, g_wout_hi);
    cudaGetSymbolAddress((void**)&p_wout_lo, g_wout_lo);

    init_state_kernel<<<(Bsz*HID + 255)/256, 256>>>();

    // ---- preprocessing: splits + permutes ----
    split_mat<<<((size_t)BT*HID + 255)/256, 256>>>(captions, HID, BT, HID, p_cap_hi, p_cap_lo, BT);
    split_mat<<<(EMB*HID + 255)/256, 256>>>(W_att + EMB, EMB+HID, EMB, HID, p_watt_hi, p_watt_lo, EMB);
    split_mat<<<(VOCP*HID + 255)/256, 256>>>(W_out, HID, VOC, HID, p_wout_hi, p_wout_lo, VOCP);
    perm_split_w<<<(G4*EMB + 255)/256, 256>>>(W_ih, 2*EMB, EMB, EMB, p_wihp_hi, p_wihp_lo);
    perm_split_w<<<(G4*HID + 255)/256, 256>>>(W_hh, HID, 0, HID, p_whhp_hi, p_whhp_lo);
    perm_w0_bias<<<(G4*EMB + 255)/256, 256>>>(W_ih, b_ih, b_hh);

    // ---- small fp32 GEMMs ----
    gemm64<<<dim3(EMB/64, Bsz/64), 256>>>(images, FCI, W_fc, FCI, p_feats, EMB, Bsz, EMB, FCI, b_fc);
    gemm64<<<dim3(EMB/64, Bsz/64), 256>>>(p_feats, EMB, W_att, EMB+HID, p_ctxb, EMB, Bsz, EMB, EMB, b_att);
    // gate_base = feats @ w0p^T + (b_ih + b_hh), permuted layout
    gemm64<<<dim3(G4/64, Bsz/64), 256>>>(p_feats, EMB, p_w0p, EMB, p_gateb, G4, Bsz, G4, EMB, p_bcomb);

    // ---- ctx = captions @ W_att'^T + ctx_base  ->  split bf16 ----
    hmma_nt<<<dim3(EMB/128, BT/128), 256>>>(
        p_cap_hi, p_cap_lo, p_watt_hi, p_watt_lo, HID,
        nullptr, p_ctx_hi, p_ctx_lo, EMB, EMB, nullptr, p_ctxb, EMB, 0);

    // ---- gatesX = ctx @ wihp^T + gate_base  ->  fp32, [t][b][j] layout ----
    hmma_nt<<<dim3(G4/128, BT/128), 256>>>(
        p_ctx_hi, p_ctx_lo, p_wihp_hi, p_wihp_lo, EMB,
        p_gatesX, nullptr, nullptr, G4, G4, nullptr, p_gateb, G4, 1);

    // ---- recurrence: HMMA + fused cell ----
    for (int t = 0; t < Tsz; t++)
        lstm_hmma<<<dim3(G4/64, Bsz/64), 256>>>(t);

    // ---- out = hseq @ W_out^T + b_out ----
    hmma_nt<<<dim3(VOCP/128, BT/128), 256>>>(
        p_hseq_hi, p_hseq_lo, p_wout_hi, p_wout_lo, HID,
        out, nullptr, nullptr, VOC, VOC, b_out, nullptr, 0, 0);
}

// round 6
// speedup vs baseline: 2.3415x; 1.1181x over previous
#include <cuda_runtime.h>
#include <cuda_bf16.h>
#include <math.h>
#include <cstdint>

#define Bsz 256
#define Tsz 128
#define EMB 256
#define HID 512
#define VOC 1004
#define VOCP 1024
#define FCI 2048
#define BT  (Bsz*Tsz)
#define G4  (4*HID)

typedef __nv_bfloat16 bf16;

// ===================== PTX helpers =====================
__device__ __forceinline__ uint32_t smem_u32(const void* p) {
    uint32_t a;
    asm("{ .reg .u64 t; cvta.to.shared.u64 t, %1; cvt.u32.u64 %0, t; }" : "=r"(a) : "l"(p));
    return a;
}
__device__ __forceinline__ void cp16(uint32_t s, const void* g) {
    asm volatile("cp.async.cg.shared.global [%0], [%1], 16;" :: "r"(s), "l"(g) : "memory");
}
#define CP_COMMIT() asm volatile("cp.async.commit_group;" ::: "memory")
#define CP_WAIT(n)  asm volatile("cp.async.wait_group %0;" :: "n"(n) : "memory")

#define LDM_X4(r0,r1,r2,r3, addr) \
    asm volatile("ldmatrix.sync.aligned.m8n8.x4.shared.b16 {%0,%1,%2,%3}, [%4];" \
        : "=r"(r0), "=r"(r1), "=r"(r2), "=r"(r3) : "r"(addr))

#define MMA_BF16(c0,c1,c2,c3, a0,a1,a2,a3, b0,b1) \
    asm volatile("mma.sync.aligned.m16n8k16.row.col.f32.bf16.bf16.f32 " \
        "{%0,%1,%2,%3}, {%4,%5,%6,%7}, {%8,%9}, {%0,%1,%2,%3};" \
        : "+f"(c0), "+f"(c1), "+f"(c2), "+f"(c3) \
        : "r"(a0), "r"(a1), "r"(a2), "r"(a3), "r"(b0), "r"(b1))

// ===================== device scratch =====================
__device__ __align__(16) float g_feats    [Bsz*EMB];
__device__ __align__(16) float g_ctx_base [Bsz*EMB];
__device__ __align__(16) float g_gate_base[Bsz*G4];
__device__ __align__(16) float g_gatesX   [(size_t)BT*G4];    // [t][b][j]
__device__ __align__(16) float g_bcomb    [G4];
__device__ __align__(16) float g_w0p      [G4*EMB];

__device__ __align__(16) bf16 g_hhi[2][Bsz*HID];
__device__ __align__(16) bf16 g_hlo[2][Bsz*HID];

__device__ __align__(16) bf16 g_cap_hi [(size_t)BT*HID];
__device__ __align__(16) bf16 g_cap_lo [(size_t)BT*HID];
__device__ __align__(16) bf16 g_ctx_hi [(size_t)BT*EMB];
__device__ __align__(16) bf16 g_ctx_lo [(size_t)BT*EMB];
__device__ __align__(16) bf16 g_hseq_hi[(size_t)BT*HID];
__device__ __align__(16) bf16 g_hseq_lo[(size_t)BT*HID];
__device__ __align__(16) bf16 g_watt_hi[EMB*HID],  g_watt_lo[EMB*HID];
__device__ __align__(16) bf16 g_wihp_hi[G4*EMB],   g_wihp_lo[G4*EMB];
__device__ __align__(16) bf16 g_whhp_hi[G4*HID],   g_whhp_lo[G4*HID];
__device__ __align__(16) bf16 g_wout_hi[VOCP*HID], g_wout_lo[VOCP*HID];

// grid barrier state
__device__ unsigned g_bar_arrive;
__device__ volatile unsigned g_bar_gen;

__global__ void init_state_kernel() {
    int i = blockIdx.x*blockDim.x + threadIdx.x;
    if (i < Bsz*HID) {
        g_hhi[0][i] = __float2bfloat16(0.f);
        g_hlo[0][i] = __float2bfloat16(0.f);
    }
}

// ===================== split fp32 -> (hi, lo) bf16 =====================
__global__ void split_mat(const float* __restrict__ src, int ldsrc, int Nreal, int K,
                          bf16* __restrict__ hi, bf16* __restrict__ lo, int Npad)
{
    size_t i = (size_t)blockIdx.x*blockDim.x + threadIdx.x;
    if (i >= (size_t)Npad*K) return;
    int n = (int)(i / K), k = (int)(i % K);
    float x = (n < Nreal) ? src[(size_t)n*ldsrc + k] : 0.f;
    bf16 h = __float2bfloat16(x);
    hi[i] = h;
    lo[i] = __float2bfloat16(x - __bfloat162float(h));
}

__global__ void perm_split_w(const float* __restrict__ src, int ldsrc, int koff, int K,
                             bf16* __restrict__ hi, bf16* __restrict__ lo)
{
    size_t i = (size_t)blockIdx.x*blockDim.x + threadIdx.x;
    if (i >= (size_t)G4*K) return;
    int j = (int)(i / K), k = (int)(i % K);
    int h = j >> 2, g = j & 3;
    float x = src[(size_t)(g*HID + h)*ldsrc + koff + k];
    bf16 hh = __float2bfloat16(x);
    hi[i] = hh;
    lo[i] = __float2bfloat16(x - __bfloat162float(hh));
}

__global__ void perm_w0_bias(const float* __restrict__ W_ih,
                             const float* __restrict__ b_ih,
                             const float* __restrict__ b_hh)
{
    int i = blockIdx.x*blockDim.x + threadIdx.x;
    if (i >= G4*EMB) return;
    int j = i >> 8, k = i & 255;
    int h = j >> 2, g = j & 3;
    g_w0p[i] = W_ih[(size_t)(g*HID + h)*(2*EMB) + k];
    if (k == 0) g_bcomb[j] = b_ih[g*HID + h] + b_hh[g*HID + h];
}

// ===================== HMMA bf16 NT GEMM, 3-pass split ================
#define SPAD 40

__global__ __launch_bounds__(256)
void hmma_nt(const bf16* __restrict__ Ahi, const bf16* __restrict__ Alo,
             const bf16* __restrict__ Bhi, const bf16* __restrict__ Blo,
             int K,
             float* __restrict__ C, bf16* __restrict__ Chi, bf16* __restrict__ Clo,
             int ldc, int Nreal,
             const float* __restrict__ bias,
             const float* __restrict__ rowAdd, int rowLd,
             int rowSwap)
{
    __shared__ bf16 sA[2][128*SPAD];
    __shared__ bf16 sB[2][128*SPAD];

    const int tid = threadIdx.x;
    const int wid = tid >> 5, lane = tid & 31;
    const int warpM = wid & 1, warpN = wid >> 1;
    const int n0 = blockIdx.x * 128, m0 = blockIdx.y * 128;

    const int kch = K >> 5;
    const int nch = 3 * kch;

    auto load_chunk = [&](int c, int st) {
        const int p = c / kch, kc = c % kch;
        const bf16* Ap = (p == 1) ? Alo : Ahi;
        const bf16* Bp = (p == 2) ? Blo : Bhi;
        #pragma unroll
        for (int j = 0; j < 4; j++) {
            const int u = tid + j * 256;
            const int tile = u >> 9;
            const int row = (u >> 2) & 127;
            const int seg = u & 3;
            const bf16* g = (tile ? Bp + (size_t)(n0 + row) * K
                                  : Ap + (size_t)(m0 + row) * K) + kc * 32 + seg * 8;
            bf16* dst = (tile ? sB[st] : sA[st]) + row * SPAD + seg * 8;
            cp16(smem_u32(dst), g);
        }
        CP_COMMIT();
    };

    float acc[4][4][4];
    #pragma unroll
    for (int a=0;a<4;a++)
        #pragma unroll
        for (int b=0;b<4;b++)
            #pragma unroll
            for (int d=0;d<4;d++) acc[a][b][d] = 0.f;

    load_chunk(0, 0);
    if (nch > 1) load_chunk(1, 1);

    const uint32_t aAddrBase0 = smem_u32(&sA[0][0]) +
        (uint32_t)((warpM*64 + (lane & 15)) * SPAD * 2) + ((lane >> 4) * 16);
    const uint32_t bAddrBase0 = smem_u32(&sB[0][0]) +
        (uint32_t)((warpN*32 + (lane & 15)) * SPAD * 2) + ((lane >> 4) * 16);
    const uint32_t stageOff = (uint32_t)(128 * SPAD * 2);

    for (int c = 0; c < nch; c++) {
        const int st = c & 1;
        if (c + 1 < nch) { CP_WAIT(1); } else { CP_WAIT(0); }
        __syncthreads();

        const uint32_t aB = aAddrBase0 + st * stageOff;
        const uint32_t bB = bAddrBase0 + st * stageOff;

        #pragma unroll
        for (int ks = 0; ks < 2; ks++) {
            uint32_t a[4][4];
            #pragma unroll
            for (int mf = 0; mf < 4; mf++)
                LDM_X4(a[mf][0], a[mf][1], a[mf][2], a[mf][3],
                       aB + (uint32_t)(mf * 16 * SPAD * 2) + ks * 32);
            uint32_t br[2][4];
            #pragma unroll
            for (int nq = 0; nq < 2; nq++)
                LDM_X4(br[nq][0], br[nq][1], br[nq][2], br[nq][3],
                       bB + (uint32_t)(nq * 16 * SPAD * 2) + ks * 32);
            #pragma unroll
            for (int mf = 0; mf < 4; mf++) {
                #pragma unroll
                for (int nf = 0; nf < 4; nf++) {
                    const int nq = nf >> 1, nh = nf & 1;
                    MMA_BF16(acc[mf][nf][0], acc[mf][nf][1], acc[mf][nf][2], acc[mf][nf][3],
                             a[mf][0], a[mf][1], a[mf][2], a[mf][3],
                             br[nq][nh], br[nq][nh + 2]);
                }
            }
        }
        __syncthreads();
        if (c + 2 < nch) load_chunk(c + 2, st);
    }

    const int rowbase = rowAdd ? (m0 >> 7) * rowLd : 0;
    const int mloc = warpM*64 + (lane >> 2);
    const int nloc = warpN*32 + 2*(lane & 3);

    #pragma unroll
    for (int mf = 0; mf < 4; mf++) {
        #pragma unroll
        for (int nf = 0; nf < 4; nf++) {
            const int gn = n0 + nloc + nf*8;
            float add0 = 0.f, add1 = 0.f;
            if (bias)   { add0 += bias[gn]; add1 += bias[gn+1]; }
            if (rowAdd) { add0 += rowAdd[rowbase + gn]; add1 += rowAdd[rowbase + gn + 1]; }
            #pragma unroll
            for (int half = 0; half < 2; half++) {
                const int gm = m0 + mloc + mf*16 + half*8;
                const int grow = rowSwap ? (gm % Tsz)*Bsz + gm/Tsz : gm;
                const float v0 = acc[mf][nf][half*2 + 0] + add0;
                const float v1 = acc[mf][nf][half*2 + 1] + add1;
                if (gn < Nreal) {
                    const size_t off = (size_t)grow * ldc + gn;
                    if (C) *(float2*)(C + off) = make_float2(v0, v1);
                    if (Chi) {
                        bf16 h0 = __float2bfloat16(v0);
                        bf16 h1 = __float2bfloat16(v1);
                        __nv_bfloat162 hv; hv.x = h0; hv.y = h1;
                        __nv_bfloat162 lv;
                        lv.x = __float2bfloat16(v0 - __bfloat162float(h0));
                        lv.y = __float2bfloat16(v1 - __bfloat162float(h1));
                        *(__nv_bfloat162*)(Chi + off) = hv;
                        *(__nv_bfloat162*)(Clo + off) = lv;
                    }
                }
            }
        }
    }
}

// ===================== small fp32 NT SGEMM =====================
__global__ __launch_bounds__(256)
void gemm64(const float* __restrict__ A, int lda,
            const float* __restrict__ W, int ldw,
            float* __restrict__ C, int ldc,
            int M, int N, int K,
            const float* __restrict__ bias)
{
    __shared__ float As[16][68];
    __shared__ float Ws[16][68];
    const int n0 = blockIdx.x*64, m0 = blockIdx.y*64;
    const int t  = threadIdx.x;
    const int lr = t>>2, lc = (t&3)*4;
    const int tx = t&15, ty = t>>4;
    const int cm = ty*4, cn = tx*4;
    float acc[4][4] = {};
    const float* Ap = A + (size_t)(m0+lr)*lda + lc;
    const bool wok = (n0+lr) < N;
    const float* Wp = W + (size_t)(wok ? (n0+lr) : 0)*ldw + lc;
    float4 av = *(const float4*)Ap;
    float4 wv = wok ? *(const float4*)Wp : make_float4(0,0,0,0);
    for (int k0 = 0; k0 < K; k0 += 16) {
        As[lc+0][lr]=av.x; As[lc+1][lr]=av.y; As[lc+2][lr]=av.z; As[lc+3][lr]=av.w;
        Ws[lc+0][lr]=wv.x; Ws[lc+1][lr]=wv.y; Ws[lc+2][lr]=wv.z; Ws[lc+3][lr]=wv.w;
        __syncthreads();
        if (k0 + 16 < K) {
            av = *(const float4*)(Ap + k0 + 16);
            wv = wok ? *(const float4*)(Wp + k0 + 16) : make_float4(0,0,0,0);
        }
        #pragma unroll
        for (int kk = 0; kk < 16; kk++) {
            float4 a = *(const float4*)&As[kk][cm];
            float4 w = *(const float4*)&Ws[kk][cn];
            acc[0][0]+=a.x*w.x; acc[0][1]+=a.x*w.y; acc[0][2]+=a.x*w.z; acc[0][3]+=a.x*w.w;
            acc[1][0]+=a.y*w.x; acc[1][1]+=a.y*w.y; acc[1][2]+=a.y*w.z; acc[1][3]+=a.y*w.w;
            acc[2][0]+=a.z*w.x; acc[2][1]+=a.z*w.y; acc[2][2]+=a.z*w.z; acc[2][3]+=a.z*w.w;
            acc[3][0]+=a.w*w.x; acc[3][1]+=a.w*w.y; acc[3][2]+=a.w*w.z; acc[3][3]+=a.w*w.w;
        }
        __syncthreads();
    }
    #pragma unroll
    for (int i = 0; i < 4; i++) {
        const int gm = m0 + cm + i;
        #pragma unroll
        for (int j = 0; j < 4; j++) {
            const int gn = n0 + cn + j;
            if (gn < N) C[(size_t)gm*ldc + gn] = acc[i][j] + (bias ? bias[gn] : 0.f);
        }
    }
}

// ===================== persistent HMMA LSTM =====================
// grid (32 j-tiles, 4 b-tiles) = 128 CTAs, 1/SM, single wave.
// W_hh (hi+lo) resident in smem; c in registers; h double-buffered in
// global with a grid barrier per step.
// smem layout (bytes):
//   [0 .. 66560)        W hi: 64 rows x 520 bf16 (stride 1040B)
//   [66560 .. 133120)   W lo
//   [133120 .. 151552)  A stages: 2 x (64 rows x 72 bf16)  | gates stage (reuse)
#define WPAD   520
#define LSPAD  72
#define SM_W(p)   ((p) ? 66560u : 0u)
#define SM_A(st)  (133120u + (uint32_t)(st)*9216u)
#define LSTM_SMEM 151552

__device__ __forceinline__ void grid_sync() {
    __syncthreads();
    if (threadIdx.x == 0) {
        __threadfence();
        unsigned gen = g_bar_gen;
        if (atomicInc(&g_bar_arrive, 127u) == 127u) {
            __threadfence();
            g_bar_gen = gen + 1;
        } else {
            while (g_bar_gen == gen) { }
            __threadfence();
        }
    }
    __syncthreads();
}

__global__ __launch_bounds__(256, 1)
void lstm_persist()
{
    extern __shared__ __align__(16) char smem[];
    const uint32_t sb = smem_u32(smem);

    const int tid = threadIdx.x;
    const int wid = tid >> 5, lane = tid & 31;
    const int warpM = wid & 1, warpN = wid >> 1;
    const int n0 = blockIdx.x * 64;      // j tile
    const int m0 = blockIdx.y * 64;      // batch tile

    // ---- load resident W (hi+lo) once ----
    #pragma unroll
    for (int it = 0; it < 32; it++) {
        const int u = tid + it * 256;            // 0..8191
        const int copy = u >> 12;                // 0: hi, 1: lo
        const int v = u & 4095;
        const int row = v >> 6, seg = v & 63;
        const bf16* src = (copy ? g_whhp_lo : g_whhp_hi) + (size_t)(n0 + row) * HID + seg * 8;
        cp16(sb + SM_W(copy) + (uint32_t)(row * (WPAD*2) + seg * 16), src);
    }
    CP_COMMIT(); CP_WAIT(0);
    __syncthreads();

    // ---- per-thread c state (64b x 16h tile: b=tid&63, hq=tid>>6, 4 h each) ----
    float c_reg[4] = {0.f, 0.f, 0.f, 0.f};
    const int bloc = tid & 63;
    const int hq = tid >> 6;
    const int gb = m0 + bloc;
    const int h0q = n0 >> 2;

    const uint32_t aAddrBase = sb + SM_A(0) - SM_A(0) + 0;  // computed per stage below
    const uint32_t aOff = (uint32_t)((warpM*32 + (lane & 15)) * (LSPAD*2)) + ((lane >> 4) * 16);
    const uint32_t bOff = (uint32_t)((warpN*16 + (lane & 15)) * (WPAD*2)) + ((lane >> 4) * 16);
    (void)aAddrBase;

    float* sG = (float*)(smem + 133120);

    for (int t = 0; t < Tsz; t++) {
        const bf16* __restrict__ Ahi = g_hhi[t & 1];
        const bf16* __restrict__ Alo = g_hlo[t & 1];
        bf16* __restrict__ Hhi = g_hhi[(t+1) & 1];
        bf16* __restrict__ Hlo = g_hlo[(t+1) & 1];

        auto load_A = [&](int c, int st) {
            const int p = c >> 3, kc = c & 7;
            const bf16* Ap = (p == 1) ? Alo : Ahi;
            #pragma unroll
            for (int j = 0; j < 2; j++) {
                const int u = tid + j * 256;         // 0..511
                const int row = u >> 3, seg = u & 7;
                cp16(sb + SM_A(st) + (uint32_t)(row * (LSPAD*2) + seg * 16),
                     Ap + (size_t)(m0 + row) * HID + kc * 64 + seg * 8);
            }
            CP_COMMIT();
        };

        float acc[2][2][4];
        #pragma unroll
        for (int a=0;a<2;a++)
            #pragma unroll
            for (int b=0;b<2;b++)
                #pragma unroll
                for (int d=0;d<4;d++) acc[a][b][d] = 0.f;

        load_A(0, 0);
        load_A(1, 1);

        #pragma unroll 1
        for (int c = 0; c < 24; c++) {
            const int st = c & 1;
            const int p = c >> 3, kc = c & 7;
            if (c + 1 < 24) { CP_WAIT(1); } else { CP_WAIT(0); }
            __syncthreads();

            const uint32_t aB = sb + SM_A(st) + aOff;
            const uint32_t bB = sb + SM_W(p == 2 ? 1 : 0) + bOff + (uint32_t)(kc * 128);

            #pragma unroll
            for (int ks = 0; ks < 4; ks++) {
                uint32_t a[2][4];
                #pragma unroll
                for (int mf = 0; mf < 2; mf++)
                    LDM_X4(a[mf][0], a[mf][1], a[mf][2], a[mf][3],
                           aB + (uint32_t)(mf * 16 * (LSPAD*2)) + ks * 32);
                uint32_t br[4];
                LDM_X4(br[0], br[1], br[2], br[3], bB + ks * 32);
                #pragma unroll
                for (int mf = 0; mf < 2; mf++) {
                    MMA_BF16(acc[mf][0][0], acc[mf][0][1], acc[mf][0][2], acc[mf][0][3],
                             a[mf][0], a[mf][1], a[mf][2], a[mf][3], br[0], br[2]);
                    MMA_BF16(acc[mf][1][0], acc[mf][1][1], acc[mf][1][2], acc[mf][1][3],
                             a[mf][0], a[mf][1], a[mf][2], a[mf][3], br[1], br[3]);
                }
            }
            __syncthreads();
            if (c + 2 < 24) load_A(c + 2, st);
        }

        // stage gates tile [64 b][64 j], stride 66 (reuses A staging area)
        {
            const int mloc = warpM*32 + (lane >> 2);
            const int nloc = warpN*16 + 2*(lane & 3);
            #pragma unroll
            for (int mf = 0; mf < 2; mf++) {
                #pragma unroll
                for (int nf = 0; nf < 2; nf++) {
                    const int n = nloc + nf*8;
                    #pragma unroll
                    for (int half = 0; half < 2; half++) {
                        const int m = mloc + mf*16 + half*8;
                        *(float2*)&sG[m*66 + n] =
                            make_float2(acc[mf][nf][half*2], acc[mf][nf][half*2+1]);
                    }
                }
            }
        }
        __syncthreads();

        // fused LSTM cell: 64 b x 16 h
        #pragma unroll
        for (int j = 0; j < 4; j++) {
            const int hsub = hq*4 + j;
            const float4 gx = *(const float4*)&g_gatesX[((size_t)t*Bsz + gb)*G4 + n0 + hsub*4];
            const float gi = sG[bloc*66 + hsub*4 + 0] + gx.x;
            const float gf = sG[bloc*66 + hsub*4 + 1] + gx.y;
            const float gg = sG[bloc*66 + hsub*4 + 2] + gx.z;
            const float go = sG[bloc*66 + hsub*4 + 3] + gx.w;

            const float si = 1.f/(1.f + expf(-gi));
            const float sf = 1.f/(1.f + expf(-gf));
            const float so = 1.f/(1.f + expf(-go));

            const float cnew = sf*c_reg[j] + si*tanhf(gg);
            const float hnew = so*tanhf(cnew);
            c_reg[j] = cnew;

            const bf16 hh = __float2bfloat16(hnew);
            const bf16 hl = __float2bfloat16(hnew - __bfloat162float(hh));
            const int ci = gb*HID + h0q + hsub;
            Hhi[ci] = hh;
            Hlo[ci] = hl;
            const size_t ho = ((size_t)gb*Tsz + t)*HID + h0q + hsub;
            g_hseq_hi[ho] = hh;
            g_hseq_lo[ho] = hl;
        }

        grid_sync();
    }
}

// ===================== launch =====================
extern "C" void kernel_launch(void* const* d_in, const int* in_sizes, int n_in,
                              void* d_out, int out_size)
{
    const float* images   = (const float*)d_in[0];
    const float* captions = (const float*)d_in[1];
    const float* W_fc  = (const float*)d_in[2];
    const float* b_fc  = (const float*)d_in[3];
    const float* W_att = (const float*)d_in[4];
    const float* b_att = (const float*)d_in[5];
    const float* W_ih  = (const float*)d_in[6];
    const float* b_ih  = (const float*)d_in[7];
    const float* W_hh  = (const float*)d_in[8];
    const float* b_hh  = (const float*)d_in[9];
    const float* W_out = (const float*)d_in[10];
    const float* b_out = (const float*)d_in[11];
    float* out = (float*)d_out;

    float *p_feats, *p_ctxb, *p_gateb, *p_gatesX, *p_bcomb, *p_w0p;
    bf16 *p_cap_hi, *p_cap_lo, *p_ctx_hi, *p_ctx_lo, *p_hseq_hi, *p_hseq_lo;
    bf16 *p_watt_hi, *p_watt_lo, *p_wihp_hi, *p_wihp_lo, *p_wout_hi, *p_wout_lo;
    cudaGetSymbolAddress((void**)&p_feats,  g_feats);
    cudaGetSymbolAddress((void**)&p_ctxb,   g_ctx_base);
    cudaGetSymbolAddress((void**)&p_gateb,  g_gate_base);
    cudaGetSymbolAddress((void**)&p_gatesX, g_gatesX);
    cudaGetSymbolAddress((void**)&p_bcomb,  g_bcomb);
    cudaGetSymbolAddress((void**)&p_w0p,    g_w0p);
    cudaGetSymbolAddress((void**)&p_cap_hi, g_cap_hi);
    cudaGetSymbolAddress((void**)&p_cap_lo, g_cap_lo);
    cudaGetSymbolAddress((void**)&p_ctx_hi, g_ctx_hi);
    cudaGetSymbolAddress((void**)&p_ctx_lo, g_ctx_lo);
    cudaGetSymbolAddress((void**)&p_hseq_hi, g_hseq_hi);
    cudaGetSymbolAddress((void**)&p_hseq_lo, g_hseq_lo);
    cudaGetSymbolAddress((void**)&p_watt_hi, g_watt_hi);
    cudaGetSymbolAddress((void**)&p_watt_lo, g_watt_lo);
    cudaGetSymbolAddress((void**)&p_wihp_hi, g_wihp_hi);
    cudaGetSymbolAddress((void**)&p_wihp_lo, g_wihp_lo);
    cudaGetSymbolAddress((void**)&p_wout_hi, g_wout_hi);
    cudaGetSymbolAddress((void**)&p_wout_lo, g_wout_lo);

    static int smem_set = 0;
    if (!smem_set) {
        cudaFuncSetAttribute(lstm_persist, cudaFuncAttributeMaxDynamicSharedMemorySize, LSTM_SMEM);
        smem_set = 1;
    }

    init_state_kernel<<<(Bsz*HID + 255)/256, 256>>>();

    // ---- preprocessing: splits + permutes ----
    split_mat<<<((size_t)BT*HID + 255)/256, 256>>>(captions, HID, BT, HID, p_cap_hi, p_cap_lo, BT);
    split_mat<<<(EMB*HID + 255)/256, 256>>>(W_att + EMB, EMB+HID, EMB, HID, p_watt_hi, p_watt_lo, EMB);
    split_mat<<<(VOCP*HID + 255)/256, 256>>>(W_out, HID, VOC, HID, p_wout_hi, p_wout_lo, VOCP);
    perm_split_w<<<(G4*EMB + 255)/256, 256>>>(W_ih, 2*EMB, EMB, EMB, p_wihp_hi, p_wihp_lo);
    {
        bf16 *p_whhp_hi, *p_whhp_lo;
        cudaGetSymbolAddress((void**)&p_whhp_hi, g_whhp_hi);
        cudaGetSymbolAddress((void**)&p_whhp_lo, g_whhp_lo);
        perm_split_w<<<(G4*HID + 255)/256, 256>>>(W_hh, HID, 0, HID, p_whhp_hi, p_whhp_lo);
    }
    perm_w0_bias<<<(G4*EMB + 255)/256, 256>>>(W_ih, b_ih, b_hh);

    // ---- small fp32 GEMMs ----
    gemm64<<<dim3(EMB/64, Bsz/64), 256>>>(images, FCI, W_fc, FCI, p_feats, EMB, Bsz, EMB, FCI, b_fc);
    gemm64<<<dim3(EMB/64, Bsz/64), 256>>>(p_feats, EMB, W_att, EMB+HID, p_ctxb, EMB, Bsz, EMB, EMB, b_att);
    gemm64<<<dim3(G4/64, Bsz/64), 256>>>(p_feats, EMB, p_w0p, EMB, p_gateb, G4, Bsz, G4, EMB, p_bcomb);

    // ---- ctx = captions @ W_att'^T + ctx_base  ->  split bf16 ----
    hmma_nt<<<dim3(EMB/128, BT/128), 256>>>(
        p_cap_hi, p_cap_lo, p_watt_hi, p_watt_lo, HID,
        nullptr, p_ctx_hi, p_ctx_lo, EMB, EMB, nullptr, p_ctxb, EMB, 0);

    // ---- gatesX = ctx @ wihp^T + gate_base  ->  fp32, [t][b][j] ----
    hmma_nt<<<dim3(G4/128, BT/128), 256>>>(
        p_ctx_hi, p_ctx_lo, p_wihp_hi, p_wihp_lo, EMB,
        p_gatesX, nullptr, nullptr, G4, G4, nullptr, p_gateb, G4, 1);

    // ---- recurrence: ONE persistent kernel ----
    lstm_persist<<<dim3(32, 4), 256, LSTM_SMEM>>>();

    // ---- out = hseq @ W_out^T + b_out ----
    hmma_nt<<<dim3(VOCP/128, BT/128), 256>>>(
        p_hseq_hi, p_hseq_lo, p_wout_hi, p_wout_lo, HID,
        out, nullptr, nullptr, VOC, VOC, b_out, nullptr, 0, 0);
}

// round 9
// speedup vs baseline: 2.5464x; 1.0875x over previous
#include <cuda_runtime.h>
#include <cuda_bf16.h>
#include <math.h>
#include <cstdint>

#define Bsz 256
#define Tsz 128
#define EMB 256
#define HID 512
#define VOC 1004
#define VOCP 1024
#define FCI 2048
#define BT  (Bsz*Tsz)
#define G4  (4*HID)

typedef __nv_bfloat16 bf16;

// ===================== PTX helpers =====================
__device__ __forceinline__ uint32_t smem_u32(const void* p) {
    uint32_t a;
    asm("{ .reg .u64 t; cvta.to.shared.u64 t, %1; cvt.u32.u64 %0, t; }" : "=r"(a) : "l"(p));
    return a;
}
__device__ __forceinline__ void cp16(uint32_t s, const void* g) {
    asm volatile("cp.async.cg.shared.global [%0], [%1], 16;" :: "r"(s), "l"(g) : "memory");
}
#define CP_COMMIT() asm volatile("cp.async.commit_group;" ::: "memory")
#define CP_WAIT(n)  asm volatile("cp.async.wait_group %0;" :: "n"(n) : "memory")

#define LDM_X4(r0,r1,r2,r3, addr) \
    asm volatile("ldmatrix.sync.aligned.m8n8.x4.shared.b16 {%0,%1,%2,%3}, [%4];" \
        : "=r"(r0), "=r"(r1), "=r"(r2), "=r"(r3) : "r"(addr))

#define MMA_BF16(c0,c1,c2,c3, a0,a1,a2,a3, b0,b1) \
    asm volatile("mma.sync.aligned.m16n8k16.row.col.f32.bf16.bf16.f32 " \
        "{%0,%1,%2,%3}, {%4,%5,%6,%7}, {%8,%9}, {%0,%1,%2,%3};" \
        : "+f"(c0), "+f"(c1), "+f"(c2), "+f"(c3) \
        : "r"(a0), "r"(a1), "r"(a2), "r"(a3), "r"(b0), "r"(b1))

// ===================== device scratch =====================
__device__ __align__(16) float g_feats    [Bsz*EMB];
__device__ __align__(16) float g_ctx_base [Bsz*EMB];
__device__ __align__(16) float g_gate_base[Bsz*G4];
__device__ __align__(16) float g_gatesX   [(size_t)BT*G4];    // [t][b][j]
__device__ __align__(16) float g_bcomb    [G4];
__device__ __align__(16) float g_w0p      [G4*EMB];

__device__ __align__(16) bf16 g_hhi[2][Bsz*HID];
__device__ __align__(16) bf16 g_hlo[2][Bsz*HID];

__device__ __align__(16) bf16 g_cap_hi [(size_t)BT*HID];
__device__ __align__(16) bf16 g_cap_lo [(size_t)BT*HID];
__device__ __align__(16) bf16 g_ctx_hi [(size_t)BT*EMB];
__device__ __align__(16) bf16 g_ctx_lo [(size_t)BT*EMB];
__device__ __align__(16) bf16 g_hseq_hi[(size_t)BT*HID];
__device__ __align__(16) bf16 g_hseq_lo[(size_t)BT*HID];
__device__ __align__(16) bf16 g_watt_hi[EMB*HID],  g_watt_lo[EMB*HID];
__device__ __align__(16) bf16 g_wihp_hi[G4*EMB],   g_wihp_lo[G4*EMB];
__device__ __align__(16) bf16 g_whhp_hi[G4*HID],   g_whhp_lo[G4*HID];
__device__ __align__(16) bf16 g_wout_hi[VOCP*HID], g_wout_lo[VOCP*HID];

// group barrier state (4 independent batch-tile groups of 32 CTAs)
__device__ unsigned g_bar_arrive[4];
__device__ volatile unsigned g_bar_gen[4];

__global__ void init_state_kernel() {
    int i = blockIdx.x*blockDim.x + threadIdx.x;
    if (i < Bsz*HID) {
        g_hhi[0][i] = __float2bfloat16(0.f);
        g_hlo[0][i] = __float2bfloat16(0.f);
    }
}

// ===================== split fp32 -> (hi, lo) bf16 =====================
__global__ void split_mat(const float* __restrict__ src, int ldsrc, int Nreal, int K,
                          bf16* __restrict__ hi, bf16* __restrict__ lo, int Npad)
{
    size_t i = (size_t)blockIdx.x*blockDim.x + threadIdx.x;
    if (i >= (size_t)Npad*K) return;
    int n = (int)(i / K), k = (int)(i % K);
    float x = (n < Nreal) ? src[(size_t)n*ldsrc + k] : 0.f;
    bf16 h = __float2bfloat16(x);
    hi[i] = h;
    lo[i] = __float2bfloat16(x - __bfloat162float(h));
}

__global__ void perm_split_w(const float* __restrict__ src, int ldsrc, int koff, int K,
                             bf16* __restrict__ hi, bf16* __restrict__ lo)
{
    size_t i = (size_t)blockIdx.x*blockDim.x + threadIdx.x;
    if (i >= (size_t)G4*K) return;
    int j = (int)(i / K), k = (int)(i % K);
    int h = j >> 2, g = j & 3;
    float x = src[(size_t)(g*HID + h)*ldsrc + koff + k];
    bf16 hh = __float2bfloat16(x);
    hi[i] = hh;
    lo[i] = __float2bfloat16(x - __bfloat162float(hh));
}

__global__ void perm_w0_bias(const float* __restrict__ W_ih,
                             const float* __restrict__ b_ih,
                             const float* __restrict__ b_hh)
{
    int i = blockIdx.x*blockDim.x + threadIdx.x;
    if (i >= G4*EMB) return;
    int j = i >> 8, k = i & 255;
    int h = j >> 2, g = j & 3;
    g_w0p[i] = W_ih[(size_t)(g*HID + h)*(2*EMB) + k];
    if (k == 0) g_bcomb[j] = b_ih[g*HID + h] + b_hh[g*HID + h];
}

// ===================== HMMA bf16 NT GEMM, 3-pass split ================
#define SPAD 40

__global__ __launch_bounds__(256)
void hmma_nt(const bf16* __restrict__ Ahi, const bf16* __restrict__ Alo,
             const bf16* __restrict__ Bhi, const bf16* __restrict__ Blo,
             int K,
             float* __restrict__ C, bf16* __restrict__ Chi, bf16* __restrict__ Clo,
             int ldc, int Nreal,
             const float* __restrict__ bias,
             const float* __restrict__ rowAdd, int rowLd,
             int rowSwap)
{
    __shared__ bf16 sA[2][128*SPAD];
    __shared__ bf16 sB[2][128*SPAD];

    const int tid = threadIdx.x;
    const int wid = tid >> 5, lane = tid & 31;
    const int warpM = wid & 1, warpN = wid >> 1;
    const int n0 = blockIdx.x * 128, m0 = blockIdx.y * 128;

    const int kch = K >> 5;
    const int nch = 3 * kch;

    auto load_chunk = [&](int c, int st) {
        const int p = c / kch, kc = c % kch;
        const bf16* Ap = (p == 1) ? Alo : Ahi;
        const bf16* Bp = (p == 2) ? Blo : Bhi;
        #pragma unroll
        for (int j = 0; j < 4; j++) {
            const int u = tid + j * 256;
            const int tile = u >> 9;
            const int row = (u >> 2) & 127;
            const int seg = u & 3;
            const bf16* g = (tile ? Bp + (size_t)(n0 + row) * K
                                  : Ap + (size_t)(m0 + row) * K) + kc * 32 + seg * 8;
            bf16* dst = (tile ? sB[st] : sA[st]) + row * SPAD + seg * 8;
            cp16(smem_u32(dst), g);
        }
        CP_COMMIT();
    };

    float acc[4][4][4];
    #pragma unroll
    for (int a=0;a<4;a++)
        #pragma unroll
        for (int b=0;b<4;b++)
            #pragma unroll
            for (int d=0;d<4;d++) acc[a][b][d] = 0.f;

    load_chunk(0, 0);
    if (nch > 1) load_chunk(1, 1);

    const uint32_t aAddrBase0 = smem_u32(&sA[0][0]) +
        (uint32_t)((warpM*64 + (lane & 15)) * SPAD * 2) + ((lane >> 4) * 16);
    const uint32_t bAddrBase0 = smem_u32(&sB[0][0]) +
        (uint32_t)((warpN*32 + (lane & 15)) * SPAD * 2) + ((lane >> 4) * 16);
    const uint32_t stageOff = (uint32_t)(128 * SPAD * 2);

    for (int c = 0; c < nch; c++) {
        const int st = c & 1;
        if (c + 1 < nch) { CP_WAIT(1); } else { CP_WAIT(0); }
        __syncthreads();

        const uint32_t aB = aAddrBase0 + st * stageOff;
        const uint32_t bB = bAddrBase0 + st * stageOff;

        #pragma unroll
        for (int ks = 0; ks < 2; ks++) {
            uint32_t a[4][4];
            #pragma unroll
            for (int mf = 0; mf < 4; mf++)
                LDM_X4(a[mf][0], a[mf][1], a[mf][2], a[mf][3],
                       aB + (uint32_t)(mf * 16 * SPAD * 2) + ks * 32);
            uint32_t br[2][4];
            #pragma unroll
            for (int nq = 0; nq < 2; nq++)
                LDM_X4(br[nq][0], br[nq][1], br[nq][2], br[nq][3],
                       bB + (uint32_t)(nq * 16 * SPAD * 2) + ks * 32);
            #pragma unroll
            for (int mf = 0; mf < 4; mf++) {
                #pragma unroll
                for (int nf = 0; nf < 4; nf++) {
                    const int nq = nf >> 1, nh = nf & 1;
                    MMA_BF16(acc[mf][nf][0], acc[mf][nf][1], acc[mf][nf][2], acc[mf][nf][3],
                             a[mf][0], a[mf][1], a[mf][2], a[mf][3],
                             br[nq][nh], br[nq][nh + 2]);
                }
            }
        }
        __syncthreads();
        if (c + 2 < nch) load_chunk(c + 2, st);
    }

    const int rowbase = rowAdd ? (m0 >> 7) * rowLd : 0;
    const int mloc = warpM*64 + (lane >> 2);
    const int nloc = warpN*32 + 2*(lane & 3);

    #pragma unroll
    for (int mf = 0; mf < 4; mf++) {
        #pragma unroll
        for (int nf = 0; nf < 4; nf++) {
            const int gn = n0 + nloc + nf*8;
            float add0 = 0.f, add1 = 0.f;
            if (bias)   { add0 += bias[gn]; add1 += bias[gn+1]; }
            if (rowAdd) { add0 += rowAdd[rowbase + gn]; add1 += rowAdd[rowbase + gn + 1]; }
            #pragma unroll
            for (int half = 0; half < 2; half++) {
                const int gm = m0 + mloc + mf*16 + half*8;
                const int grow = rowSwap ? (gm % Tsz)*Bsz + gm/Tsz : gm;
                const float v0 = acc[mf][nf][half*2 + 0] + add0;
                const float v1 = acc[mf][nf][half*2 + 1] + add1;
                if (gn < Nreal) {
                    const size_t off = (size_t)grow * ldc + gn;
                    if (C) *(float2*)(C + off) = make_float2(v0, v1);
                    if (Chi) {
                        bf16 h0 = __float2bfloat16(v0);
                        bf16 h1 = __float2bfloat16(v1);
                        __nv_bfloat162 hv; hv.x = h0; hv.y = h1;
                        __nv_bfloat162 lv;
                        lv.x = __float2bfloat16(v0 - __bfloat162float(h0));
                        lv.y = __float2bfloat16(v1 - __bfloat162float(h1));
                        *(__nv_bfloat162*)(Chi + off) = hv;
                        *(__nv_bfloat162*)(Clo + off) = lv;
                    }
                }
            }
        }
    }
}

// ===================== small fp32 NT SGEMM =====================
__global__ __launch_bounds__(256)
void gemm64(const float* __restrict__ A, int lda,
            const float* __restrict__ W, int ldw,
            float* __restrict__ C, int ldc,
            int M, int N, int K,
            const float* __restrict__ bias)
{
    __shared__ float As[16][68];
    __shared__ float Ws[16][68];
    const int n0 = blockIdx.x*64, m0 = blockIdx.y*64;
    const int t  = threadIdx.x;
    const int lr = t>>2, lc = (t&3)*4;
    const int tx = t&15, ty = t>>4;
    const int cm = ty*4, cn = tx*4;
    float acc[4][4] = {};
    const float* Ap = A + (size_t)(m0+lr)*lda + lc;
    const bool wok = (n0+lr) < N;
    const float* Wp = W + (size_t)(wok ? (n0+lr) : 0)*ldw + lc;
    float4 av = *(const float4*)Ap;
    float4 wv = wok ? *(const float4*)Wp : make_float4(0,0,0,0);
    for (int k0 = 0; k0 < K; k0 += 16) {
        As[lc+0][lr]=av.x; As[lc+1][lr]=av.y; As[lc+2][lr]=av.z; As[lc+3][lr]=av.w;
        Ws[lc+0][lr]=wv.x; Ws[lc+1][lr]=wv.y; Ws[lc+2][lr]=wv.z; Ws[lc+3][lr]=wv.w;
        __syncthreads();
        if (k0 + 16 < K) {
            av = *(const float4*)(Ap + k0 + 16);
            wv = wok ? *(const float4*)(Wp + k0 + 16) : make_float4(0,0,0,0);
        }
        #pragma unroll
        for (int kk = 0; kk < 16; kk++) {
            float4 a = *(const float4*)&As[kk][cm];
            float4 w = *(const float4*)&Ws[kk][cn];
            acc[0][0]+=a.x*w.x; acc[0][1]+=a.x*w.y; acc[0][2]+=a.x*w.z; acc[0][3]+=a.x*w.w;
            acc[1][0]+=a.y*w.x; acc[1][1]+=a.y*w.y; acc[1][2]+=a.y*w.z; acc[1][3]+=a.y*w.w;
            acc[2][0]+=a.z*w.x; acc[2][1]+=a.z*w.y; acc[2][2]+=a.z*w.z; acc[2][3]+=a.z*w.w;
            acc[3][0]+=a.w*w.x; acc[3][1]+=a.w*w.y; acc[3][2]+=a.w*w.z; acc[3][3]+=a.w*w.w;
        }
        __syncthreads();
    }
    #pragma unroll
    for (int i = 0; i < 4; i++) {
        const int gm = m0 + cm + i;
        #pragma unroll
        for (int j = 0; j < 4; j++) {
            const int gn = n0 + cn + j;
            if (gn < N) C[(size_t)gm*ldc + gn] = acc[i][j] + (bias ? bias[gn] : 0.f);
        }
    }
}

// ===================== persistent HMMA LSTM =====================
// grid (32 j-tiles, 4 b-tiles) = 128 CTAs, 1/SM.
// W_hh (hi+lo) resident in smem; c in registers; h in global, synced with a
// PER-GROUP barrier (32 CTAs sharing a batch tile).
// smem layout (bytes):
//   [0 .. 66560)        W hi: 64 rows x 520 bf16 (stride 1040B)
//   [66560 .. 133120)   W lo
//   [133120 .. 200704)  A stages: 2 x (64 rows x 264 bf16, stride 528B)
//                       gates tile [64][66] floats reuses this area too
#define WPAD   520
#define APAD   264
#define SM_W(p)   ((p) ? 66560u : 0u)
#define SM_A(st)  (133120u + (uint32_t)(st)*33792u)
#define LSTM_SMEM 200704

__device__ __forceinline__ void group_sync(int grp) {
    __syncthreads();
    if (threadIdx.x == 0) {
        __threadfence();
        unsigned gen = g_bar_gen[grp];
        if (atomicInc(&g_bar_arrive[grp], 31u) == 31u) {
            __threadfence();
            g_bar_gen[grp] = gen + 1;
        } else {
            while (g_bar_gen[grp] == gen) { }
            __threadfence();
        }
    }
    __syncthreads();
}

__global__ __launch_bounds__(256, 1)
void lstm_persist()
{
    extern __shared__ __align__(16) char smem[];
    const uint32_t sb = smem_u32(smem);

    const int tid = threadIdx.x;
    const int wid = tid >> 5, lane = tid & 31;
    const int warpM = wid & 1, warpN = wid >> 1;
    const int n0 = blockIdx.x * 64;      // j tile
    const int m0 = blockIdx.y * 64;      // batch tile
    const int grp = blockIdx.y;

    // ---- load resident W (hi+lo) once ----
    #pragma unroll
    for (int it = 0; it < 32; it++) {
        const int u = tid + it * 256;            // 0..8191
        const int copy = u >> 12;                // 0: hi, 1: lo
        const int v = u & 4095;
        const int row = v >> 6, seg = v & 63;
        const bf16* src = (copy ? g_whhp_lo : g_whhp_hi) + (size_t)(n0 + row) * HID + seg * 8;
        cp16(sb + SM_W(copy) + (uint32_t)(row * (WPAD*2) + seg * 16), src);
    }
    CP_COMMIT(); CP_WAIT(0);
    __syncthreads();

    float c_reg[4] = {0.f, 0.f, 0.f, 0.f};
    const int bloc = tid & 63;
    const int hq = tid >> 6;
    const int gb = m0 + bloc;
    const int h0q = n0 >> 2;

    const uint32_t aOff = (uint32_t)((warpM*32 + (lane & 15)) * (APAD*2)) + ((lane >> 4) * 16);
    const uint32_t bOff = (uint32_t)((warpN*16 + (lane & 15)) * (WPAD*2)) + ((lane >> 4) * 16);

    float* sG = (float*)(smem + 133120);

    for (int t = 0; t < Tsz; t++) {
        const bf16* __restrict__ Ahi = g_hhi[t & 1];
        const bf16* __restrict__ Alo = g_hlo[t & 1];
        bf16* __restrict__ Hhi = g_hhi[(t+1) & 1];
        bf16* __restrict__ Hlo = g_hlo[(t+1) & 1];

        // chunk c (0..5): pass p = c>>1 (0:hi*hi 1:lo*hi 2:hi*lo), k-half kc = c&1
        auto load_A = [&](int c, int st) {
            const int p = c >> 1, kc = c & 1;
            const bf16* Ap = (p == 1) ? Alo : Ahi;
            #pragma unroll
            for (int j = 0; j < 8; j++) {
                const int u = tid + j * 256;         // 0..2047
                const int row = u >> 5, seg = u & 31;
                cp16(sb + SM_A(st) + (uint32_t)(row * (APAD*2) + seg * 16),
                     Ap + (size_t)(m0 + row) * HID + kc * 256 + seg * 8);
            }
            CP_COMMIT();
        };

        float acc[2][2][4];
        #pragma unroll
        for (int a=0;a<2;a++)
            #pragma unroll
            for (int b=0;b<2;b++)
                #pragma unroll
                for (int d=0;d<4;d++) acc[a][b][d] = 0.f;

        load_A(0, 0);
        load_A(1, 1);

        #pragma unroll 1
        for (int c = 0; c < 6; c++) {
            const int st = c & 1;
            const int p = c >> 1, kc = c & 1;
            if (c + 1 < 6) { CP_WAIT(1); } else { CP_WAIT(0); }
            __syncthreads();

            const uint32_t aB = sb + SM_A(st) + aOff;
            const uint32_t bB = sb + SM_W(p == 2 ? 1 : 0) + bOff + (uint32_t)(kc * 512);

            #pragma unroll
            for (int ks = 0; ks < 16; ks++) {
                uint32_t a[2][4];
                #pragma unroll
                for (int mf = 0; mf < 2; mf++)
                    LDM_X4(a[mf][0], a[mf][1], a[mf][2], a[mf][3],
                           aB + (uint32_t)(mf * 16 * (APAD*2)) + ks * 32);
                uint32_t br[4];
                LDM_X4(br[0], br[1], br[2], br[3], bB + ks * 32);
                #pragma unroll
                for (int mf = 0; mf < 2; mf++) {
                    MMA_BF16(acc[mf][0][0], acc[mf][0][1], acc[mf][0][2], acc[mf][0][3],
                             a[mf][0], a[mf][1], a[mf][2], a[mf][3], br[0], br[2]);
                    MMA_BF16(acc[mf][1][0], acc[mf][1][1], acc[mf][1][2], acc[mf][1][3],
                             a[mf][0], a[mf][1], a[mf][2], a[mf][3], br[1], br[3]);
                }
            }
            __syncthreads();
            if (c + 2 < 6) load_A(c + 2, st);
        }

        // stage gates tile [64 b][64 j], stride 66 (reuses A staging area)
        {
            const int mloc = warpM*32 + (lane >> 2);
            const int nloc = warpN*16 + 2*(lane & 3);
            #pragma unroll
            for (int mf = 0; mf < 2; mf++) {
                #pragma unroll
                for (int nf = 0; nf < 2; nf++) {
                    const int n = nloc + nf*8;
                    #pragma unroll
                    for (int half = 0; half < 2; half++) {
                        const int m = mloc + mf*16 + half*8;
                        *(float2*)&sG[m*66 + n] =
                            make_float2(acc[mf][nf][half*2], acc[mf][nf][half*2+1]);
                    }
                }
            }
        }
        __syncthreads();

        // coalesced gatesX add into sG
        #pragma unroll
        for (int i = 0; i < 4; i++) {
            const int idx = tid + i * 256;        // 0..1023
            const int row = idx >> 4;
            const int c4 = idx & 15;
            const float4 gx = *(const float4*)&g_gatesX[((size_t)t*Bsz + m0 + row)*G4 + n0 + c4*4];
            float* p = &sG[row*66 + c4*4];
            p[0] += gx.x; p[1] += gx.y; p[2] += gx.z; p[3] += gx.w;
        }
        __syncthreads();

        // fused LSTM cell: 64 b x 16 h (4 consecutive h per thread)
        float hv[4];
        #pragma unroll
        for (int j = 0; j < 4; j++) {
            const int hsub = hq*4 + j;
            const float gi = sG[bloc*66 + hsub*4 + 0];
            const float gf = sG[bloc*66 + hsub*4 + 1];
            const float gg = sG[bloc*66 + hsub*4 + 2];
            const float go = sG[bloc*66 + hsub*4 + 3];

            const float si = 1.f/(1.f + expf(-gi));
            const float sf = 1.f/(1.f + expf(-gf));
            const float so = 1.f/(1.f + expf(-go));

            const float cnew = sf*c_reg[j] + si*tanhf(gg);
            hv[j] = so*tanhf(cnew);
            c_reg[j] = cnew;
        }
        union { bf16 v[4]; uint2 u; } ph, pl;
        #pragma unroll
        for (int j = 0; j < 4; j++) {
            ph.v[j] = __float2bfloat16(hv[j]);
            pl.v[j] = __float2bfloat16(hv[j] - __bfloat162float(ph.v[j]));
        }
        const int ci = gb*HID + h0q + hq*4;
        *(uint2*)&Hhi[ci] = ph.u;
        *(uint2*)&Hlo[ci] = pl.u;
        const size_t ho = ((size_t)gb*Tsz + t)*HID + h0q + hq*4;
        *(uint2*)&g_hseq_hi[ho] = ph.u;
        *(uint2*)&g_hseq_lo[ho] = pl.u;

        group_sync(grp);
    }
}

// ===================== launch =====================
extern "C" void kernel_launch(void* const* d_in, const int* in_sizes, int n_in,
                              void* d_out, int out_size)
{
    const float* images   = (const float*)d_in[0];
    const float* captions = (const float*)d_in[1];
    const float* W_fc  = (const float*)d_in[2];
    const float* b_fc  = (const float*)d_in[3];
    const float* W_att = (const float*)d_in[4];
    const float* b_att = (const float*)d_in[5];
    const float* W_ih  = (const float*)d_in[6];
    const float* b_ih  = (const float*)d_in[7];
    const float* W_hh  = (const float*)d_in[8];
    const float* b_hh  = (const float*)d_in[9];
    const float* W_out = (const float*)d_in[10];
    const float* b_out = (const float*)d_in[11];
    float* out = (float*)d_out;

    float *p_feats, *p_ctxb, *p_gateb, *p_gatesX, *p_bcomb, *p_w0p;
    bf16 *p_cap_hi, *p_cap_lo, *p_ctx_hi, *p_ctx_lo, *p_hseq_hi, *p_hseq_lo;
    bf16 *p_watt_hi, *p_watt_lo, *p_wihp_hi, *p_wihp_lo, *p_whhp_hi, *p_whhp_lo, *p_wout_hi, *p_wout_lo;
    cudaGetSymbolAddress((void**)&p_feats,  g_feats);
    cudaGetSymbolAddress((void**)&p_ctxb,   g_ctx_base);
    cudaGetSymbolAddress((void**)&p_gateb,  g_gate_base);
    cudaGetSymbolAddress((void**)&p_gatesX, g_gatesX);
    cudaGetSymbolAddress((void**)&p_bcomb,  g_bcomb);
    cudaGetSymbolAddress((void**)&p_w0p,    g_w0p);
    cudaGetSymbolAddress((void**)&p_cap_hi, g_cap_hi);
    cudaGetSymbolAddress((void**)&p_cap_lo, g_cap_lo);
    cudaGetSymbolAddress((void**)&p_ctx_hi, g_ctx_hi);
    cudaGetSymbolAddress((void**)&p_ctx_lo, g_ctx_lo);
    cudaGetSymbolAddress((void**)&p_hseq_hi, g_hseq_hi);
    cudaGetSymbolAddress((void**)&p_hseq_lo, g_hseq_lo);
    cudaGetSymbolAddress((void**)&p_watt_hi, g_watt_hi);
    cudaGetSymbolAddress((void**)&p_watt_lo, g_watt_lo);
    cudaGetSymbolAddress((void**)&p_wihp_hi, g_wihp_hi);
    cudaGetSymbolAddress((void**)&p_wihp_lo, g_wihp_lo);
    cudaGetSymbolAddress((void**)&p_whhp_hi, g_whhp_hi);
    cudaGetSymbolAddress((void**)&p_whhp_lo, g_whhp_lo);
    cudaGetSymbolAddress((void**)&p_wout_hi, g_wout_hi);
    cudaGetSymbolAddress((void**)&p_wout_lo, g_wout_lo);

    static int smem_set = 0;
    if (!smem_set) {
        cudaFuncSetAttribute(lstm_persist, cudaFuncAttributeMaxDynamicSharedMemorySize, LSTM_SMEM);
        smem_set = 1;
    }

    init_state_kernel<<<(Bsz*HID + 255)/256, 256>>>();

    // ---- preprocessing: splits + permutes ----
    split_mat<<<((size_t)BT*HID + 255)/256, 256>>>(captions, HID, BT, HID, p_cap_hi, p_cap_lo, BT);
    split_mat<<<(EMB*HID + 255)/256, 256>>>(W_att + EMB, EMB+HID, EMB, HID, p_watt_hi, p_watt_lo, EMB);
    split_mat<<<(VOCP*HID + 255)/256, 256>>>(W_out, HID, VOC, HID, p_wout_hi, p_wout_lo, VOCP);
    perm_split_w<<<(G4*EMB + 255)/256, 256>>>(W_ih, 2*EMB, EMB, EMB, p_wihp_hi, p_wihp_lo);
    perm_split_w<<<(G4*HID + 255)/256, 256>>>(W_hh, HID, 0, HID, p_whhp_hi, p_whhp_lo);
    perm_w0_bias<<<(G4*EMB + 255)/256, 256>>>(W_ih, b_ih, b_hh);

    // ---- small fp32 GEMMs ----
    gemm64<<<dim3(EMB/64, Bsz/64), 256>>>(images, FCI, W_fc, FCI, p_feats, EMB, Bsz, EMB, FCI, b_fc);
    gemm64<<<dim3(EMB/64, Bsz/64), 256>>>(p_feats, EMB, W_att, EMB+HID, p_ctxb, EMB, Bsz, EMB, EMB, b_att);
    gemm64<<<dim3(G4/64, Bsz/64), 256>>>(p_feats, EMB, p_w0p, EMB, p_gateb, G4, Bsz, G4, EMB, p_bcomb);

    // ---- ctx = captions @ W_att'^T + ctx_base  ->  split bf16 ----
    hmma_nt<<<dim3(EMB/128, BT/128), 256>>>(
        p_cap_hi, p_cap_lo, p_watt_hi, p_watt_lo, HID,
        nullptr, p_ctx_hi, p_ctx_lo, EMB, EMB, nullptr, p_ctxb, EMB, 0);

    // ---- gatesX = ctx @ wihp^T + gate_base  ->  fp32, [t][b][j] ----
    hmma_nt<<<dim3(G4/128, BT/128), 256>>>(
        p_ctx_hi, p_ctx_lo, p_wihp_hi, p_wihp_lo, EMB,
        p_gatesX, nullptr, nullptr, G4, G4, nullptr, p_gateb, G4, 1);

    // ---- recurrence: ONE persistent kernel, per-group barriers ----
    lstm_persist<<<dim3(32, 4), 256, LSTM_SMEM>>>();

    // ---- out = hseq @ W_out^T + b_out ----
    hmma_nt<<<dim3(VOCP/128, BT/128), 256>>>(
        p_hseq_hi, p_hseq_lo, p_wout_hi, p_wout_lo, HID,
        out, nullptr, nullptr, VOC, VOC, b_out, nullptr, 0, 0);
}

// round 12
// speedup vs baseline: 2.9854x; 1.1724x over previous
#include <cuda_runtime.h>
#include <cuda_bf16.h>
#include <cuda.h>
#include <math.h>
#include <cstdint>

#define Bsz 256
#define Tsz 128
#define EMB 256
#define HID 512
#define VOC 1004
#define VOCP 1024
#define FCI 2048
#define BT  (Bsz*Tsz)
#define G4  (4*HID)

typedef __nv_bfloat16 bf16;

// ===================== PTX helpers =====================
__device__ __forceinline__ uint32_t smem_u32(const void* p) {
    uint32_t a;
    asm("{ .reg .u64 t; cvta.to.shared.u64 t, %1; cvt.u32.u64 %0, t; }" : "=r"(a) : "l"(p));
    return a;
}
__device__ __forceinline__ void cp16(uint32_t s, const void* g) {
    asm volatile("cp.async.cg.shared.global [%0], [%1], 16;" :: "r"(s), "l"(g) : "memory");
}
#define CP_COMMIT() asm volatile("cp.async.commit_group;" ::: "memory")
#define CP_WAIT(n)  asm volatile("cp.async.wait_group %0;" :: "n"(n) : "memory")

#define LDM_X4(r0,r1,r2,r3, addr) \
    asm volatile("ldmatrix.sync.aligned.m8n8.x4.shared.b16 {%0,%1,%2,%3}, [%4];" \
        : "=r"(r0), "=r"(r1), "=r"(r2), "=r"(r3) : "r"(addr))

#define MMA_BF16(c0,c1,c2,c3, a0,a1,a2,a3, b0,b1) \
    asm volatile("mma.sync.aligned.m16n8k16.row.col.f32.bf16.bf16.f32 " \
        "{%0,%1,%2,%3}, {%4,%5,%6,%7}, {%8,%9}, {%0,%1,%2,%3};" \
        : "+f"(c0), "+f"(c1), "+f"(c2), "+f"(c3) \
        : "r"(a0), "r"(a1), "r"(a2), "r"(a3), "r"(b0), "r"(b1))

#define MBARRIER_INIT(addr, cnt) \
    asm volatile("mbarrier.init.shared.b64 [%0], %1;" :: "r"((uint32_t)(addr)), "r"((uint32_t)(cnt)) : "memory")
#define MBARRIER_EXPECT_TX(addr, tx) \
    asm volatile("mbarrier.arrive.expect_tx.shared.b64 _, [%0], %1;" :: "r"((uint32_t)(addr)), "r"((uint32_t)(tx)) : "memory")
#define MBARRIER_WAIT_PARITY(addr, par) do { \
    uint32_t _m = (uint32_t)(addr); uint32_t _p = (uint32_t)(par); uint32_t _d; \
    asm volatile("{\n\t.reg .pred p;\n\tmbarrier.try_wait.parity.acquire.cta.shared::cta.b64 p, [%1], %2;\n\tselp.b32 %0, 1, 0, p;\n\t}" \
        : "=r"(_d) : "r"(_m), "r"(_p) : "memory"); \
    if (!_d) { \
        asm volatile("{\n\t.reg .pred P1;\n\tWL_%=:\n\tmbarrier.try_wait.parity.acquire.cta.shared::cta.b64 P1, [%0], %1, 0x989680;\n\t@P1 bra.uni WD_%=;\n\tbra.uni WL_%=;\n\tWD_%=:\n\t}" \
            :: "r"(_m), "r"(_p) : "memory"); \
    } } while (0)

#define TMA_LOAD_3D_CTA(smem_addr, tmap, c0, c1, c2, mbar) \
    asm volatile("cp.async.bulk.tensor.3d.shared::cta.global.tile.mbarrier::complete_tx::bytes " \
        "[%0], [%1, {%2, %3, %4}], [%5];" \
        :: "r"((uint32_t)(smem_addr)), "l"(tmap), "r"((int)(c0)), "r"((int)(c1)), "r"((int)(c2)), \
           "r"((uint32_t)(mbar)) : "memory")

__device__ __forceinline__ float tanh_fast(float x) {
    float r; asm("tanh.approx.f32 %0, %1;" : "=f"(r) : "f"(x)); return r;
}
__device__ __forceinline__ float sigmoid_fast(float x) {
    return 0.5f + 0.5f * tanh_fast(0.5f * x);
}

// ===================== device scratch =====================
__device__ __align__(16) float g_feats    [Bsz*EMB];
__device__ __align__(16) float g_ctx_base [Bsz*EMB];
__device__ __align__(16) float g_gate_base[Bsz*G4];
__device__ __align__(16) float g_gatesX   [(size_t)BT*G4];    // [t][b][j]
__device__ __align__(16) float g_bcomb    [G4];
__device__ __align__(16) float g_w0p      [G4*EMB];

__device__ __align__(1024) bf16 g_hhi[2][Bsz*HID];
__device__ __align__(1024) bf16 g_hlo[2][Bsz*HID];

__device__ __align__(16) bf16 g_cap_hi [(size_t)BT*HID];
__device__ __align__(16) bf16 g_cap_lo [(size_t)BT*HID];
__device__ __align__(16) bf16 g_ctx_hi [(size_t)BT*EMB];
__device__ __align__(16) bf16 g_ctx_lo [(size_t)BT*EMB];
__device__ __align__(16) bf16 g_hseq_hi[(size_t)BT*HID];
__device__ __align__(16) bf16 g_hseq_lo[(size_t)BT*HID];
__device__ __align__(16) bf16 g_watt_hi[EMB*HID],  g_watt_lo[EMB*HID];
__device__ __align__(16) bf16 g_wihp_hi[G4*EMB],   g_wihp_lo[G4*EMB];
__device__ __align__(16) bf16 g_whhp_hi[G4*HID],   g_whhp_lo[G4*HID];
__device__ __align__(16) bf16 g_wout_hi[VOCP*HID], g_wout_lo[VOCP*HID];

// group barrier state (4 independent batch-tile groups of 32 CTAs)
__device__ unsigned g_bar_arrive[4];
__device__ volatile unsigned g_bar_gen[4];

__global__ void init_state_kernel() {
    int i = blockIdx.x*blockDim.x + threadIdx.x;
    if (i < Bsz*HID) {
        g_hhi[0][i] = __float2bfloat16(0.f);
        g_hlo[0][i] = __float2bfloat16(0.f);
    }
}

// ===================== split fp32 -> (hi, lo) bf16 =====================
__global__ void split_mat(const float* __restrict__ src, int ldsrc, int Nreal, int K,
                          bf16* __restrict__ hi, bf16* __restrict__ lo, int Npad)
{
    size_t i = (size_t)blockIdx.x*blockDim.x + threadIdx.x;
    if (i >= (size_t)Npad*K) return;
    int n = (int)(i / K), k = (int)(i % K);
    float x = (n < Nreal) ? src[(size_t)n*ldsrc + k] : 0.f;
    bf16 h = __float2bfloat16(x);
    hi[i] = h;
    lo[i] = __float2bfloat16(x - __bfloat162float(h));
}

__global__ void perm_split_w(const float* __restrict__ src, int ldsrc, int koff, int K,
                             bf16* __restrict__ hi, bf16* __restrict__ lo)
{
    size_t i = (size_t)blockIdx.x*blockDim.x + threadIdx.x;
    if (i >= (size_t)G4*K) return;
    int j = (int)(i / K), k = (int)(i % K);
    int h = j >> 2, g = j & 3;
    float x = src[(size_t)(g*HID + h)*ldsrc + koff + k];
    bf16 hh = __float2bfloat16(x);
    hi[i] = hh;
    lo[i] = __float2bfloat16(x - __bfloat162float(hh));
}

__global__ void perm_w0_bias(const float* __restrict__ W_ih,
                             const float* __restrict__ b_ih,
                             const float* __restrict__ b_hh)
{
    int i = blockIdx.x*blockDim.x + threadIdx.x;
    if (i >= G4*EMB) return;
    int j = i >> 8, k = i & 255;
    int h = j >> 2, g = j & 3;
    g_w0p[i] = W_ih[(size_t)(g*HID + h)*(2*EMB) + k];
    if (k == 0) g_bcomb[j] = b_ih[g*HID + h] + b_hh[g*HID + h];
}

// ===================== HMMA bf16 NT GEMM, 3-pass split ================
#define SPAD 40

__global__ __launch_bounds__(256)
void hmma_nt(const bf16* __restrict__ Ahi, const bf16* __restrict__ Alo,
             const bf16* __restrict__ Bhi, const bf16* __restrict__ Blo,
             int K,
             float* __restrict__ C, bf16* __restrict__ Chi, bf16* __restrict__ Clo,
             int ldc, int Nreal,
             const float* __restrict__ bias,
             const float* __restrict__ rowAdd, int rowLd,
             int rowSwap)
{
    __shared__ bf16 sA[2][128*SPAD];
    __shared__ bf16 sB[2][128*SPAD];

    const int tid = threadIdx.x;
    const int wid = tid >> 5, lane = tid & 31;
    const int warpM = wid & 1, warpN = wid >> 1;
    const int n0 = blockIdx.x * 128, m0 = blockIdx.y * 128;

    const int kch = K >> 5;
    const int nch = 3 * kch;

    auto load_chunk = [&](int c, int st) {
        const int p = c / kch, kc = c % kch;
        const bf16* Ap = (p == 1) ? Alo : Ahi;
        const bf16* Bp = (p == 2) ? Blo : Bhi;
        #pragma unroll
        for (int j = 0; j < 4; j++) {
            const int u = tid + j * 256;
            const int tile = u >> 9;
            const int row = (u >> 2) & 127;
            const int seg = u & 3;
            const bf16* g = (tile ? Bp + (size_t)(n0 + row) * K
                                  : Ap + (size_t)(m0 + row) * K) + kc * 32 + seg * 8;
            bf16* dst = (tile ? sB[st] : sA[st]) + row * SPAD + seg * 8;
            cp16(smem_u32(dst), g);
        }
        CP_COMMIT();
    };

    float acc[4][4][4];
    #pragma unroll
    for (int a=0;a<4;a++)
        #pragma unroll
        for (int b=0;b<4;b++)
            #pragma unroll
            for (int d=0;d<4;d++) acc[a][b][d] = 0.f;

    load_chunk(0, 0);
    if (nch > 1) load_chunk(1, 1);

    const uint32_t aAddrBase0 = smem_u32(&sA[0][0]) +
        (uint32_t)((warpM*64 + (lane & 15)) * SPAD * 2) + ((lane >> 4) * 16);
    const uint32_t bAddrBase0 = smem_u32(&sB[0][0]) +
        (uint32_t)((warpN*32 + (lane & 15)) * SPAD * 2) + ((lane >> 4) * 16);
    const uint32_t stageOff = (uint32_t)(128 * SPAD * 2);

    for (int c = 0; c < nch; c++) {
        const int st = c & 1;
        if (c + 1 < nch) { CP_WAIT(1); } else { CP_WAIT(0); }
        __syncthreads();

        const uint32_t aB = aAddrBase0 + st * stageOff;
        const uint32_t bB = bAddrBase0 + st * stageOff;

        #pragma unroll
        for (int ks = 0; ks < 2; ks++) {
            uint32_t a[4][4];
            #pragma unroll
            for (int mf = 0; mf < 4; mf++)
                LDM_X4(a[mf][0], a[mf][1], a[mf][2], a[mf][3],
                       aB + (uint32_t)(mf * 16 * SPAD * 2) + ks * 32);
            uint32_t br[2][4];
            #pragma unroll
            for (int nq = 0; nq < 2; nq++)
                LDM_X4(br[nq][0], br[nq][1], br[nq][2], br[nq][3],
                       bB + (uint32_t)(nq * 16 * SPAD * 2) + ks * 32);
            #pragma unroll
            for (int mf = 0; mf < 4; mf++) {
                #pragma unroll
                for (int nf = 0; nf < 4; nf++) {
                    const int nq = nf >> 1, nh = nf & 1;
                    MMA_BF16(acc[mf][nf][0], acc[mf][nf][1], acc[mf][nf][2], acc[mf][nf][3],
                             a[mf][0], a[mf][1], a[mf][2], a[mf][3],
                             br[nq][nh], br[nq][nh + 2]);
                }
            }
        }
        __syncthreads();
        if (c + 2 < nch) load_chunk(c + 2, st);
    }

    const int rowbase = rowAdd ? (m0 >> 7) * rowLd : 0;
    const int mloc = warpM*64 + (lane >> 2);
    const int nloc = warpN*32 + 2*(lane & 3);

    #pragma unroll
    for (int mf = 0; mf < 4; mf++) {
        #pragma unroll
        for (int nf = 0; nf < 4; nf++) {
            const int gn = n0 + nloc + nf*8;
            float add0 = 0.f, add1 = 0.f;
            if (bias)   { add0 += bias[gn]; add1 += bias[gn+1]; }
            if (rowAdd) { add0 += rowAdd[rowbase + gn]; add1 += rowAdd[rowbase + gn + 1]; }
            #pragma unroll
            for (int half = 0; half < 2; half++) {
                const int gm = m0 + mloc + mf*16 + half*8;
                const int grow = rowSwap ? (gm % Tsz)*Bsz + gm/Tsz : gm;
                const float v0 = acc[mf][nf][half*2 + 0] + add0;
                const float v1 = acc[mf][nf][half*2 + 1] + add1;
                if (gn < Nreal) {
                    const size_t off = (size_t)grow * ldc + gn;
                    if (C) *(float2*)(C + off) = make_float2(v0, v1);
                    if (Chi) {
                        bf16 h0 = __float2bfloat16(v0);
                        bf16 h1 = __float2bfloat16(v1);
                        __nv_bfloat162 hv; hv.x = h0; hv.y = h1;
                        __nv_bfloat162 lv;
                        lv.x = __float2bfloat16(v0 - __bfloat162float(h0));
                        lv.y = __float2bfloat16(v1 - __bfloat162float(h1));
                        *(__nv_bfloat162*)(Chi + off) = hv;
                        *(__nv_bfloat162*)(Clo + off) = lv;
                    }
                }
            }
        }
    }
}

// ===================== small fp32 NT SGEMM =====================
__global__ __launch_bounds__(256)
void gemm64(const float* __restrict__ A, int lda,
            const float* __restrict__ W, int ldw,
            float* __restrict__ C, int ldc,
            int M, int N, int K,
            const float* __restrict__ bias)
{
    __shared__ float As[16][68];
    __shared__ float Ws[16][68];
    const int n0 = blockIdx.x*64, m0 = blockIdx.y*64;
    const int t  = threadIdx.x;
    const int lr = t>>2, lc = (t&3)*4;
    const int tx = t&15, ty = t>>4;
    const int cm = ty*4, cn = tx*4;
    float acc[4][4] = {};
    const float* Ap = A + (size_t)(m0+lr)*lda + lc;
    const bool wok = (n0+lr) < N;
    const float* Wp = W + (size_t)(wok ? (n0+lr) : 0)*ldw + lc;
    float4 av = *(const float4*)Ap;
    float4 wv = wok ? *(const float4*)Wp : make_float4(0,0,0,0);
    for (int k0 = 0; k0 < K; k0 += 16) {
        As[lc+0][lr]=av.x; As[lc+1][lr]=av.y; As[lc+2][lr]=av.z; As[lc+3][lr]=av.w;
        Ws[lc+0][lr]=wv.x; Ws[lc+1][lr]=wv.y; Ws[lc+2][lr]=wv.z; Ws[lc+3][lr]=wv.w;
        __syncthreads();
        if (k0 + 16 < K) {
            av = *(const float4*)(Ap + k0 + 16);
            wv = wok ? *(const float4*)(Wp + k0 + 16) : make_float4(0,0,0,0);
        }
        #pragma unroll
        for (int kk = 0; kk < 16; kk++) {
            float4 a = *(const float4*)&As[kk][cm];
            float4 w = *(const float4*)&Ws[kk][cn];
            acc[0][0]+=a.x*w.x; acc[0][1]+=a.x*w.y; acc[0][2]+=a.x*w.z; acc[0][3]+=a.x*w.w;
            acc[1][0]+=a.y*w.x; acc[1][1]+=a.y*w.y; acc[1][2]+=a.y*w.z; acc[1][3]+=a.y*w.w;
            acc[2][0]+=a.z*w.x; acc[2][1]+=a.z*w.y; acc[2][2]+=a.z*w.z; acc[2][3]+=a.z*w.w;
            acc[3][0]+=a.w*w.x; acc[3][1]+=a.w*w.y; acc[3][2]+=a.w*w.z; acc[3][3]+=a.w*w.w;
        }
        __syncthreads();
    }
    #pragma unroll
    for (int i = 0; i < 4; i++) {
        const int gm = m0 + cm + i;
        #pragma unroll
        for (int j = 0; j < 4; j++) {
            const int gn = n0 + cn + j;
            if (gn < N) C[(size_t)gm*ldc + gn] = acc[i][j] + (bias ? bias[gn] : 0.f);
        }
    }
}

// ===================== persistent HMMA LSTM (TMA A loads) =============
// grid (32 j-tiles, 4 b-tiles) = 128 CTAs, 1/SM.
// W_hh (hi+lo) resident smem (cp.async once); A slabs via TMA (SW128) into
// two 32KB stages; gatesX prefetched via cp.async into padded sG; c in regs.
// smem layout (bytes):
//   [0, 66560)        W hi (64 rows x 520 bf16, stride 1040)
//   [66560, 133120)   W lo
//   [133120, 165888)  A stage S0 (TMA, 4 kb-boxes x 64 rows x 128B, SW128)
//   [165888, 198656)  A stage S1
//   [198656, 198672)  mbarriers MB0, MB1
//   [198672, 216080)  sG: 64 x 68 floats (stride 272B)
#define WPAD   520
#define SM_W(p)   ((p) ? 66560u : 0u)
#define SM_S0     133120u
#define SM_S1     165888u
#define MB0       198656u
#define MB1       198664u
#define SM_G      198672u
#define LSTM_SMEM 216080

__device__ __forceinline__ void group_sync(int grp) {
    __syncthreads();
    if (threadIdx.x == 0) {
        __threadfence();
        unsigned gen = g_bar_gen[grp];
        if (atomicInc(&g_bar_arrive[grp], 31u) == 31u) {
            __threadfence();
            g_bar_gen[grp] = gen + 1;
        } else {
            while (g_bar_gen[grp] == gen) { }
            __threadfence();
        }
    }
    __syncthreads();
}

__global__ __launch_bounds__(256, 1)
void lstm_persist(const __grid_constant__ CUtensorMap mh0,
                  const __grid_constant__ CUtensorMap mh1,
                  const __grid_constant__ CUtensorMap ml0,
                  const __grid_constant__ CUtensorMap ml1)
{
    extern __shared__ __align__(1024) char smem[];
    const uint32_t sb = smem_u32(smem);

    const int tid = threadIdx.x;
    const int wid = tid >> 5, lane = tid & 31;
    const int warpM = wid & 1, warpN = wid >> 1;
    const int n0 = blockIdx.x * 64;
    const int m0 = blockIdx.y * 64;
    const int grp = blockIdx.y;

    // ---- resident W (hi+lo), cp.async once ----
    #pragma unroll
    for (int it = 0; it < 32; it++) {
        const int u = tid + it * 256;
        const int copy = u >> 12;
        const int v = u & 4095;
        const int row = v >> 6, seg = v & 63;
        const bf16* src = (copy ? g_whhp_lo : g_whhp_hi) + (size_t)(n0 + row) * HID + seg * 8;
        cp16(sb + SM_W(copy) + (uint32_t)(row * (WPAD*2) + seg * 16), src);
    }
    CP_COMMIT();
    if (tid == 0) { MBARRIER_INIT(sb + MB0, 1); MBARRIER_INIT(sb + MB1, 1); }
    CP_WAIT(0);
    __syncthreads();

    float c_reg[4] = {0.f, 0.f, 0.f, 0.f};
    const int bloc = tid & 63;
    const int hq = tid >> 6;
    const int gb = m0 + bloc;
    const int h0q = n0 >> 2;

    // A-side ldmatrix addressing (TMA SW128 layout)
    const int arow = warpM*32 + (lane & 15);
    const uint32_t swm = (uint32_t)((arow & 7) << 4);
    const uint32_t aRowB = (uint32_t)(arow * 128);
    const uint32_t cin = (uint32_t)((lane >> 4) * 16);
    // B-side (padded W)
    const uint32_t bOff = (uint32_t)((warpN*16 + (lane & 15)) * (WPAD*2)) + ((lane >> 4) * 16);

    float* sG = (float*)(smem + SM_G);
    uint32_t ph0 = 0, ph1 = 0;

    for (int t = 0; t < Tsz; t++) {
        const CUtensorMap* mhi = (t & 1) ? &mh1 : &mh0;
        const CUtensorMap* mlo = (t & 1) ? &ml1 : &ml0;
        bf16* __restrict__ Hhi = g_hhi[(t+1) & 1];
        bf16* __restrict__ Hlo = g_hlo[(t+1) & 1];

        // prefetch gatesX slab into sG (padded stride 272B)
        #pragma unroll
        for (int i = 0; i < 4; i++) {
            const int idx = tid + i * 256;
            const int row = idx >> 4, c16 = idx & 15;
            cp16(sb + SM_G + (uint32_t)(row * 272 + c16 * 16),
                 &g_gatesX[((size_t)t*Bsz + m0 + row)*G4 + n0 + c16*4]);
        }
        CP_COMMIT();

        // TMA: hi slab (both k halves)
        if (tid == 0) {
            MBARRIER_EXPECT_TX(sb + MB0, 32768);
            TMA_LOAD_3D_CTA(sb + SM_S0, mhi, 0, m0, 0, sb + MB0);
            MBARRIER_EXPECT_TX(sb + MB1, 32768);
            TMA_LOAD_3D_CTA(sb + SM_S1, mhi, 0, m0, 4, sb + MB1);
        }

        float acc[2][2][4];
        #pragma unroll
        for (int a=0;a<2;a++)
            #pragma unroll
            for (int b=0;b<2;b++)
                #pragma unroll
                for (int d=0;d<4;d++) acc[a][b][d] = 0.f;

        auto mma_chunk = [&](uint32_t stage, int wsel, int kc) {
            const uint32_t aBase = sb + stage;
            const uint32_t bB = sb + SM_W(wsel) + bOff + (uint32_t)(kc * 512);
            #pragma unroll
            for (int ks = 0; ks < 16; ks++) {
                uint32_t a[2][4];
                const uint32_t col = (((uint32_t)(ks & 3) * 32u) + cin) ^ swm;
                const uint32_t kbOff = ((uint32_t)(ks >> 2)) << 13;
                #pragma unroll
                for (int mf = 0; mf < 2; mf++)
                    LDM_X4(a[mf][0], a[mf][1], a[mf][2], a[mf][3],
                           aBase + kbOff + aRowB + (uint32_t)(mf * 2048) + col);
                uint32_t br[4];
                LDM_X4(br[0], br[1], br[2], br[3], bB + ks * 32);
                #pragma unroll
                for (int mf = 0; mf < 2; mf++) {
                    MMA_BF16(acc[mf][0][0], acc[mf][0][1], acc[mf][0][2], acc[mf][0][3],
                             a[mf][0], a[mf][1], a[mf][2], a[mf][3], br[0], br[2]);
                    MMA_BF16(acc[mf][1][0], acc[mf][1][1], acc[mf][1][2], acc[mf][1][3],
                             a[mf][0], a[mf][1], a[mf][2], a[mf][3], br[1], br[3]);
                }
            }
        };

        // c0: hi k0 x Whi
        MBARRIER_WAIT_PARITY(sb + MB0, ph0); ph0 ^= 1;
        mma_chunk(SM_S0, 0, 0);
        // c1: hi k1 x Whi
        MBARRIER_WAIT_PARITY(sb + MB1, ph1); ph1 ^= 1;
        mma_chunk(SM_S1, 0, 1);
        // c2: hi k0 x Wlo; then refill S0 with lo k0
        mma_chunk(SM_S0, 1, 0);
        __syncthreads();
        if (tid == 0) {
            MBARRIER_EXPECT_TX(sb + MB0, 32768);
            TMA_LOAD_3D_CTA(sb + SM_S0, mlo, 0, m0, 0, sb + MB0);
        }
        // c3: hi k1 x Wlo; then refill S1 with lo k1
        mma_chunk(SM_S1, 1, 1);
        __syncthreads();
        if (tid == 0) {
            MBARRIER_EXPECT_TX(sb + MB1, 32768);
            TMA_LOAD_3D_CTA(sb + SM_S1, mlo, 0, m0, 4, sb + MB1);
        }
        // c4: lo k0 x Whi
        MBARRIER_WAIT_PARITY(sb + MB0, ph0); ph0 ^= 1;
        mma_chunk(SM_S0, 0, 0);
        // c5: lo k1 x Whi
        MBARRIER_WAIT_PARITY(sb + MB1, ph1); ph1 ^= 1;
        mma_chunk(SM_S1, 0, 1);

        // gatesX arrived? then read-modify-write acc into sG
        CP_WAIT(0);
        __syncthreads();
        {
            const int mloc = warpM*32 + (lane >> 2);
            const int nloc = warpN*16 + 2*(lane & 3);
            #pragma unroll
            for (int mf = 0; mf < 2; mf++) {
                #pragma unroll
                for (int nf = 0; nf < 2; nf++) {
                    const int n = nloc + nf*8;
                    #pragma unroll
                    for (int half = 0; half < 2; half++) {
                        const int m = mloc + mf*16 + half*8;
                        float2* p = (float2*)&sG[m*68 + n];
                        float2 v = *p;
                        v.x += acc[mf][nf][half*2];
                        v.y += acc[mf][nf][half*2+1];
                        *p = v;
                    }
                }
            }
        }
        __syncthreads();

        // fused LSTM cell: 64 b x 16 h (4 consecutive h per thread)
        float hv[4];
        #pragma unroll
        for (int j = 0; j < 4; j++) {
            const int hsub = hq*4 + j;
            const float4 gv = *(const float4*)&sG[bloc*68 + hsub*4];
            const float si = sigmoid_fast(gv.x);
            const float sf = sigmoid_fast(gv.y);
            const float so = sigmoid_fast(gv.w);
            const float cnew = sf*c_reg[j] + si*tanh_fast(gv.z);
            hv[j] = so*tanh_fast(cnew);
            c_reg[j] = cnew;
        }
        union { bf16 v[4]; uint2 u; } ph, pl;
        #pragma unroll
        for (int j = 0; j < 4; j++) {
            ph.v[j] = __float2bfloat16(hv[j]);
            pl.v[j] = __float2bfloat16(hv[j] - __bfloat162float(ph.v[j]));
        }
        const int ci = gb*HID + h0q + hq*4;
        *(uint2*)&Hhi[ci] = ph.u;
        *(uint2*)&Hlo[ci] = pl.u;
        const size_t ho = ((size_t)gb*Tsz + t)*HID + h0q + hq*4;
        *(uint2*)&g_hseq_hi[ho] = ph.u;
        *(uint2*)&g_hseq_lo[ho] = pl.u;

        group_sync(grp);
    }
}

// ===================== launch =====================
typedef CUresult (*EncodeFn)(CUtensorMap*, CUtensorMapDataType, cuuint32_t, void*,
    const cuuint64_t*, const cuuint64_t*, const cuuint32_t*, const cuuint32_t*,
    CUtensorMapInterleave, CUtensorMapSwizzle, CUtensorMapL2promotion, CUtensorMapFloatOOBfill);

extern "C" void kernel_launch(void* const* d_in, const int* in_sizes, int n_in,
                              void* d_out, int out_size)
{
    const float* images   = (const float*)d_in[0];
    const float* captions = (const float*)d_in[1];
    const float* W_fc  = (const float*)d_in[2];
    const float* b_fc  = (const float*)d_in[3];
    const float* W_att = (const float*)d_in[4];
    const float* b_att = (const float*)d_in[5];
    const float* W_ih  = (const float*)d_in[6];
    const float* b_ih  = (const float*)d_in[7];
    const float* W_hh  = (const float*)d_in[8];
    const float* b_hh  = (const float*)d_in[9];
    const float* W_out = (const float*)d_in[10];
    const float* b_out = (const float*)d_in[11];
    float* out = (float*)d_out;

    float *p_feats, *p_ctxb, *p_gateb, *p_gatesX, *p_bcomb, *p_w0p;
    bf16 *p_hhi, *p_hlo;
    bf16 *p_cap_hi, *p_cap_lo, *p_ctx_hi, *p_ctx_lo, *p_hseq_hi, *p_hseq_lo;
    bf16 *p_watt_hi, *p_watt_lo, *p_wihp_hi, *p_wihp_lo, *p_whhp_hi, *p_whhp_lo, *p_wout_hi, *p_wout_lo;
    cudaGetSymbolAddress((void**)&p_feats,  g_feats);
    cudaGetSymbolAddress((void**)&p_ctxb,   g_ctx_base);
    cudaGetSymbolAddress((void**)&p_gateb,  g_gate_base);
    cudaGetSymbolAddress((void**)&p_gatesX, g_gatesX);
    cudaGetSymbolAddress((void**)&p_bcomb,  g_bcomb);
    cudaGetSymbolAddress((void**)&p_w0p,    g_w0p);
    cudaGetSymbolAddress((void**)&p_hhi,    g_hhi);
    cudaGetSymbolAddress((void**)&p_hlo,    g_hlo);
    cudaGetSymbolAddress((void**)&p_cap_hi, g_cap_hi);
    cudaGetSymbolAddress((void**)&p_cap_lo, g_cap_lo);
    cudaGetSymbolAddress((void**)&p_ctx_hi, g_ctx_hi);
    cudaGetSymbolAddress((void**)&p_ctx_lo, g_ctx_lo);
    cudaGetSymbolAddress((void**)&p_hseq_hi, g_hseq_hi);
    cudaGetSymbolAddress((void**)&p_hseq_lo, g_hseq_lo);
    cudaGetSymbolAddress((void**)&p_watt_hi, g_watt_hi);
    cudaGetSymbolAddress((void**)&p_watt_lo, g_watt_lo);
    cudaGetSymbolAddress((void**)&p_wihp_hi, g_wihp_hi);
    cudaGetSymbolAddress((void**)&p_wihp_lo, g_wihp_lo);
    cudaGetSymbolAddress((void**)&p_whhp_hi, g_whhp_hi);
    cudaGetSymbolAddress((void**)&p_whhp_lo, g_whhp_lo);
    cudaGetSymbolAddress((void**)&p_wout_hi, g_wout_hi);
    cudaGetSymbolAddress((void**)&p_wout_lo, g_wout_lo);

    // ---- one-time setup: smem attr + tensormaps ----
    static bool s_ready = false;
    static CUtensorMap s_mh0, s_mh1, s_ml0, s_ml1;
    if (!s_ready) {
        cudaFuncSetAttribute(lstm_persist, cudaFuncAttributeMaxDynamicSharedMemorySize, LSTM_SMEM);
        void* fn = nullptr;
        cudaDriverEntryPointQueryResult qr;
        cudaGetDriverEntryPoint("cuTensorMapEncodeTiled", &fn, cudaEnableDefault, &qr);
        EncodeFn enc = (EncodeFn)fn;
        auto mk = [&](CUtensorMap* m, void* base) {
            cuuint64_t dims[3]    = {64, Bsz, 8};          // ki, b, kb
            cuuint64_t strides[2] = {HID * 2, 128};        // b-stride, kb-stride (bytes)
            cuuint32_t box[3]     = {64, 64, 4};
            cuuint32_t es[3]      = {1, 1, 1};
            enc(m, CU_TENSOR_MAP_DATA_TYPE_BFLOAT16, 3, base, dims, strides, box, es,
                CU_TENSOR_MAP_INTERLEAVE_NONE, CU_TENSOR_MAP_SWIZZLE_128B,
                CU_TENSOR_MAP_L2_PROMOTION_L2_128B, CU_TENSOR_MAP_FLOAT_OOB_FILL_NONE);
        };
        mk(&s_mh0, (void*)p_hhi);
        mk(&s_mh1, (void*)(p_hhi + (size_t)Bsz*HID));
        mk(&s_ml0, (void*)p_hlo);
        mk(&s_ml1, (void*)(p_hlo + (size_t)Bsz*HID));
        s_ready = true;
    }

    init_state_kernel<<<(Bsz*HID + 255)/256, 256>>>();

    // ---- preprocessing: splits + permutes ----
    split_mat<<<((size_t)BT*HID + 255)/256, 256>>>(captions, HID, BT, HID, p_cap_hi, p_cap_lo, BT);
    split_mat<<<(EMB*HID + 255)/256, 256>>>(W_att + EMB, EMB+HID, EMB, HID, p_watt_hi, p_watt_lo, EMB);
    split_mat<<<(VOCP*HID + 255)/256, 256>>>(W_out, HID, VOC, HID, p_wout_hi, p_wout_lo, VOCP);
    perm_split_w<<<(G4*EMB + 255)/256, 256>>>(W_ih, 2*EMB, EMB, EMB, p_wihp_hi, p_wihp_lo);
    perm_split_w<<<(G4*HID + 255)/256, 256>>>(W_hh, HID, 0, HID, p_whhp_hi, p_whhp_lo);
    perm_w0_bias<<<(G4*EMB + 255)/256, 256>>>(W_ih, b_ih, b_hh);

    // ---- small fp32 GEMMs ----
    gemm64<<<dim3(EMB/64, Bsz/64), 256>>>(images, FCI, W_fc, FCI, p_feats, EMB, Bsz, EMB, FCI, b_fc);
    gemm64<<<dim3(EMB/64, Bsz/64), 256>>>(p_feats, EMB, W_att, EMB+HID, p_ctxb, EMB, Bsz, EMB, EMB, b_att);
    gemm64<<<dim3(G4/64, Bsz/64), 256>>>(p_feats, EMB, p_w0p, EMB, p_gateb, G4, Bsz, G4, EMB, p_bcomb);

    // ---- ctx = captions @ W_att'^T + ctx_base  ->  split bf16 ----
    hmma_nt<<<dim3(EMB/128, BT/128), 256>>>(
        p_cap_hi, p_cap_lo, p_watt_hi, p_watt_lo, HID,
        nullptr, p_ctx_hi, p_ctx_lo, EMB, EMB, nullptr, p_ctxb, EMB, 0);

    // ---- gatesX = ctx @ wihp^T + gate_base  ->  fp32, [t][b][j] ----
    hmma_nt<<<dim3(G4/128, BT/128), 256>>>(
        p_ctx_hi, p_ctx_lo, p_wihp_hi, p_wihp_lo, EMB,
        p_gatesX, nullptr, nullptr, G4, G4, nullptr, p_gateb, G4, 1);

    // ---- recurrence: ONE persistent kernel, TMA A loads ----
    lstm_persist<<<dim3(32, 4), 256, LSTM_SMEM>>>(s_mh0, s_mh1, s_ml0, s_ml1);

    // ---- out = hseq @ W_out^T + b_out ----
    hmma_nt<<<dim3(VOCP/128, BT/128), 256>>>(
        p_hseq_hi, p_hseq_lo, p_wout_hi, p_wout_lo, HID,
        out, nullptr, nullptr, VOC, VOC, b_out, nullptr, 0, 0);
}

// round 15
// speedup vs baseline: 3.0952x; 1.0368x over previous
#include <cuda_runtime.h>
#include <cuda_bf16.h>
#include <cuda.h>
#include <math.h>
#include <cstdint>

#define Bsz 256
#define Tsz 128
#define EMB 256
#define HID 512
#define VOC 1004
#define VOCP 1024
#define FCI 2048
#define BT  (Bsz*Tsz)
#define G4  (4*HID)

typedef __nv_bfloat16 bf16;

// ===================== PTX helpers =====================
__device__ __forceinline__ uint32_t smem_u32(const void* p) {
    uint32_t a;
    asm("{ .reg .u64 t; cvta.to.shared.u64 t, %1; cvt.u32.u64 %0, t; }" : "=r"(a) : "l"(p));
    return a;
}
__device__ __forceinline__ void cp16(uint32_t s, const void* g) {
    asm volatile("cp.async.cg.shared.global [%0], [%1], 16;" :: "r"(s), "l"(g) : "memory");
}
#define CP_COMMIT() asm volatile("cp.async.commit_group;" ::: "memory")
#define CP_WAIT(n)  asm volatile("cp.async.wait_group %0;" :: "n"(n) : "memory")

#define LDM_X4(r0,r1,r2,r3, addr) \
    asm volatile("ldmatrix.sync.aligned.m8n8.x4.shared.b16 {%0,%1,%2,%3}, [%4];" \
        : "=r"(r0), "=r"(r1), "=r"(r2), "=r"(r3) : "r"(addr))

#define MMA_BF16(c0,c1,c2,c3, a0,a1,a2,a3, b0,b1) \
    asm volatile("mma.sync.aligned.m16n8k16.row.col.f32.bf16.bf16.f32 " \
        "{%0,%1,%2,%3}, {%4,%5,%6,%7}, {%8,%9}, {%0,%1,%2,%3};" \
        : "+f"(c0), "+f"(c1), "+f"(c2), "+f"(c3) \
        : "r"(a0), "r"(a1), "r"(a2), "r"(a3), "r"(b0), "r"(b1))

#define MBARRIER_INIT(addr, cnt) \
    asm volatile("mbarrier.init.shared.b64 [%0], %1;" :: "r"((uint32_t)(addr)), "r"((uint32_t)(cnt)) : "memory")
#define MBARRIER_EXPECT_TX(addr, tx) \
    asm volatile("mbarrier.arrive.expect_tx.shared.b64 _, [%0], %1;" :: "r"((uint32_t)(addr)), "r"((uint32_t)(tx)) : "memory")
#define MBARRIER_WAIT_PARITY(addr, par) do { \
    uint32_t _m = (uint32_t)(addr); uint32_t _p = (uint32_t)(par); uint32_t _d; \
    asm volatile("{\n\t.reg .pred p;\n\tmbarrier.try_wait.parity.acquire.cta.shared::cta.b64 p, [%1], %2;\n\tselp.b32 %0, 1, 0, p;\n\t}" \
        : "=r"(_d) : "r"(_m), "r"(_p) : "memory"); \
    if (!_d) { \
        asm volatile("{\n\t.reg .pred P1;\n\tWL_%=:\n\tmbarrier.try_wait.parity.acquire.cta.shared::cta.b64 P1, [%0], %1, 0x989680;\n\t@P1 bra.uni WD_%=;\n\tbra.uni WL_%=;\n\tWD_%=:\n\t}" \
            :: "r"(_m), "r"(_p) : "memory"); \
    } } while (0)

#define TMA_LOAD_3D_CTA(smem_addr, tmap, c0, c1, c2, mbar) \
    asm volatile("cp.async.bulk.tensor.3d.shared::cta.global.tile.mbarrier::complete_tx::bytes " \
        "[%0], [%1, {%2, %3, %4}], [%5];" \
        :: "r"((uint32_t)(smem_addr)), "l"(tmap), "r"((int)(c0)), "r"((int)(c1)), "r"((int)(c2)), \
           "r"((uint32_t)(mbar)) : "memory")

__device__ __forceinline__ float tanh_fast(float x) {
    float r; asm("tanh.approx.f32 %0, %1;" : "=f"(r) : "f"(x)); return r;
}
__device__ __forceinline__ float sigmoid_fast(float x) {
    return 0.5f + 0.5f * tanh_fast(0.5f * x);
}

// ===================== device scratch =====================
__device__ __align__(16) float g_feats    [Bsz*EMB];
__device__ __align__(16) float g_ctx_base [Bsz*EMB];
__device__ __align__(16) float g_gate_base[Bsz*G4];
__device__ __align__(16) float g_gatesX   [(size_t)BT*G4];    // [t][b][j]
__device__ __align__(16) float g_bcomb    [G4];
__device__ __align__(16) float g_w0p      [G4*EMB];

__device__ __align__(1024) bf16 g_hhi[2][Bsz*HID];
__device__ __align__(1024) bf16 g_hlo[2][Bsz*HID];

__device__ __align__(16) bf16 g_cap_hi [(size_t)BT*HID];
__device__ __align__(16) bf16 g_cap_lo [(size_t)BT*HID];
__device__ __align__(16) bf16 g_ctx_hi [(size_t)BT*EMB];
__device__ __align__(16) bf16 g_ctx_lo [(size_t)BT*EMB];
__device__ __align__(16) bf16 g_hseq_hi[(size_t)BT*HID];
__device__ __align__(16) bf16 g_hseq_lo[(size_t)BT*HID];
__device__ __align__(16) bf16 g_watt_hi[EMB*HID],  g_watt_lo[EMB*HID];
__device__ __align__(16) bf16 g_wihp_hi[G4*EMB],   g_wihp_lo[G4*EMB];
__device__ __align__(16) bf16 g_whhp_hi[G4*HID],   g_whhp_lo[G4*HID];
__device__ __align__(16) bf16 g_wout_hi[VOCP*HID], g_wout_lo[VOCP*HID];

// producer/consumer counters: [group][k-half], monotonic, never reset
__device__ unsigned g_cnt[4][2];

__global__ void init_state_kernel() {
    int i = blockIdx.x*blockDim.x + threadIdx.x;
    if (i < Bsz*HID) {
        g_hhi[0][i] = __float2bfloat16(0.f);
        g_hlo[0][i] = __float2bfloat16(0.f);
    }
}

// ===================== split fp32 -> (hi, lo) bf16 =====================
__global__ void split_mat(const float* __restrict__ src, int ldsrc, int Nreal, int K,
                          bf16* __restrict__ hi, bf16* __restrict__ lo, int Npad)
{
    size_t i = (size_t)blockIdx.x*blockDim.x + threadIdx.x;
    if (i >= (size_t)Npad*K) return;
    int n = (int)(i / K), k = (int)(i % K);
    float x = (n < Nreal) ? src[(size_t)n*ldsrc + k] : 0.f;
    bf16 h = __float2bfloat16(x);
    hi[i] = h;
    lo[i] = __float2bfloat16(x - __bfloat162float(h));
}

__global__ void perm_split_w(const float* __restrict__ src, int ldsrc, int koff, int K,
                             bf16* __restrict__ hi, bf16* __restrict__ lo)
{
    size_t i = (size_t)blockIdx.x*blockDim.x + threadIdx.x;
    if (i >= (size_t)G4*K) return;
    int j = (int)(i / K), k = (int)(i % K);
    int h = j >> 2, g = j & 3;
    float x = src[(size_t)(g*HID + h)*ldsrc + koff + k];
    bf16 hh = __float2bfloat16(x);
    hi[i] = hh;
    lo[i] = __float2bfloat16(x - __bfloat162float(hh));
}

__global__ void perm_w0_bias(const float* __restrict__ W_ih,
                             const float* __restrict__ b_ih,
                             const float* __restrict__ b_hh)
{
    int i = blockIdx.x*blockDim.x + threadIdx.x;
    if (i >= G4*EMB) return;
    int j = i >> 8, k = i & 255;
    int h = j >> 2, g = j & 3;
    g_w0p[i] = W_ih[(size_t)(g*HID + h)*(2*EMB) + k];
    if (k == 0) g_bcomb[j] = b_ih[g*HID + h] + b_hh[g*HID + h];
}

// ===================== HMMA bf16 NT GEMM, 3-pass split ================
#define SPAD 40

__global__ __launch_bounds__(256)
void hmma_nt(const bf16* __restrict__ Ahi, const bf16* __restrict__ Alo,
             const bf16* __restrict__ Bhi, const bf16* __restrict__ Blo,
             int K,
             float* __restrict__ C, bf16* __restrict__ Chi, bf16* __restrict__ Clo,
             int ldc, int Nreal,
             const float* __restrict__ bias,
             const float* __restrict__ rowAdd, int rowLd,
             int rowSwap)
{
    __shared__ bf16 sA[2][128*SPAD];
    __shared__ bf16 sB[2][128*SPAD];

    const int tid = threadIdx.x;
    const int wid = tid >> 5, lane = tid & 31;
    const int warpM = wid & 1, warpN = wid >> 1;
    const int n0 = blockIdx.x * 128, m0 = blockIdx.y * 128;

    const int kch = K >> 5;
    const int nch = 3 * kch;

    auto load_chunk = [&](int c, int st) {
        const int p = c / kch, kc = c % kch;
        const bf16* Ap = (p == 1) ? Alo : Ahi;
        const bf16* Bp = (p == 2) ? Blo : Bhi;
        #pragma unroll
        for (int j = 0; j < 4; j++) {
            const int u = tid + j * 256;
            const int tile = u >> 9;
            const int row = (u >> 2) & 127;
            const int seg = u & 3;
            const bf16* g = (tile ? Bp + (size_t)(n0 + row) * K
                                  : Ap + (size_t)(m0 + row) * K) + kc * 32 + seg * 8;
            bf16* dst = (tile ? sB[st] : sA[st]) + row * SPAD + seg * 8;
            cp16(smem_u32(dst), g);
        }
        CP_COMMIT();
    };

    float acc[4][4][4];
    #pragma unroll
    for (int a=0;a<4;a++)
        #pragma unroll
        for (int b=0;b<4;b++)
            #pragma unroll
            for (int d=0;d<4;d++) acc[a][b][d] = 0.f;

    load_chunk(0, 0);
    if (nch > 1) load_chunk(1, 1);

    const uint32_t aAddrBase0 = smem_u32(&sA[0][0]) +
        (uint32_t)((warpM*64 + (lane & 15)) * SPAD * 2) + ((lane >> 4) * 16);
    const uint32_t bAddrBase0 = smem_u32(&sB[0][0]) +
        (uint32_t)((warpN*32 + (lane & 15)) * SPAD * 2) + ((lane >> 4) * 16);
    const uint32_t stageOff = (uint32_t)(128 * SPAD * 2);

    for (int c = 0; c < nch; c++) {
        const int st = c & 1;
        if (c + 1 < nch) { CP_WAIT(1); } else { CP_WAIT(0); }
        __syncthreads();

        const uint32_t aB = aAddrBase0 + st * stageOff;
        const uint32_t bB = bAddrBase0 + st * stageOff;

        #pragma unroll
        for (int ks = 0; ks < 2; ks++) {
            uint32_t a[4][4];
            #pragma unroll
            for (int mf = 0; mf < 4; mf++)
                LDM_X4(a[mf][0], a[mf][1], a[mf][2], a[mf][3],
                       aB + (uint32_t)(mf * 16 * SPAD * 2) + ks * 32);
            uint32_t br[2][4];
            #pragma unroll
            for (int nq = 0; nq < 2; nq++)
                LDM_X4(br[nq][0], br[nq][1], br[nq][2], br[nq][3],
                       bB + (uint32_t)(nq * 16 * SPAD * 2) + ks * 32);
            #pragma unroll
            for (int mf = 0; mf < 4; mf++) {
                #pragma unroll
                for (int nf = 0; nf < 4; nf++) {
                    const int nq = nf >> 1, nh = nf & 1;
                    MMA_BF16(acc[mf][nf][0], acc[mf][nf][1], acc[mf][nf][2], acc[mf][nf][3],
                             a[mf][0], a[mf][1], a[mf][2], a[mf][3],
                             br[nq][nh], br[nq][nh + 2]);
                }
            }
        }
        __syncthreads();
        if (c + 2 < nch) load_chunk(c + 2, st);
    }

    const int rowbase = rowAdd ? (m0 >> 7) * rowLd : 0;
    const int mloc = warpM*64 + (lane >> 2);
    const int nloc = warpN*32 + 2*(lane & 3);

    #pragma unroll
    for (int mf = 0; mf < 4; mf++) {
        #pragma unroll
        for (int nf = 0; nf < 4; nf++) {
            const int gn = n0 + nloc + nf*8;
            float add0 = 0.f, add1 = 0.f;
            if (bias)   { add0 += bias[gn]; add1 += bias[gn+1]; }
            if (rowAdd) { add0 += rowAdd[rowbase + gn]; add1 += rowAdd[rowbase + gn + 1]; }
            #pragma unroll
            for (int half = 0; half < 2; half++) {
                const int gm = m0 + mloc + mf*16 + half*8;
                const int grow = rowSwap ? (gm % Tsz)*Bsz + gm/Tsz : gm;
                const float v0 = acc[mf][nf][half*2 + 0] + add0;
                const float v1 = acc[mf][nf][half*2 + 1] + add1;
                if (gn < Nreal) {
                    const size_t off = (size_t)grow * ldc + gn;
                    if (C) *(float2*)(C + off) = make_float2(v0, v1);
                    if (Chi) {
                        bf16 h0 = __float2bfloat16(v0);
                        bf16 h1 = __float2bfloat16(v1);
                        __nv_bfloat162 hv; hv.x = h0; hv.y = h1;
                        __nv_bfloat162 lv;
                        lv.x = __float2bfloat16(v0 - __bfloat162float(h0));
                        lv.y = __float2bfloat16(v1 - __bfloat162float(h1));
                        *(__nv_bfloat162*)(Chi + off) = hv;
                        *(__nv_bfloat162*)(Clo + off) = lv;
                    }
                }
            }
        }
    }
}

// ===================== small fp32 NT SGEMM =====================
__global__ __launch_bounds__(256)
void gemm64(const float* __restrict__ A, int lda,
            const float* __restrict__ W, int ldw,
            float* __restrict__ C, int ldc,
            int M, int N, int K,
            const float* __restrict__ bias)
{
    __shared__ float As[16][68];
    __shared__ float Ws[16][68];
    const int n0 = blockIdx.x*64, m0 = blockIdx.y*64;
    const int t  = threadIdx.x;
    const int lr = t>>2, lc = (t&3)*4;
    const int tx = t&15, ty = t>>4;
    const int cm = ty*4, cn = tx*4;
    float acc[4][4] = {};
    const float* Ap = A + (size_t)(m0+lr)*lda + lc;
    const bool wok = (n0+lr) < N;
    const float* Wp = W + (size_t)(wok ? (n0+lr) : 0)*ldw + lc;
    float4 av = *(const float4*)Ap;
    float4 wv = wok ? *(const float4*)Wp : make_float4(0,0,0,0);
    for (int k0 = 0; k0 < K; k0 += 16) {
        As[lc+0][lr]=av.x; As[lc+1][lr]=av.y; As[lc+2][lr]=av.z; As[lc+3][lr]=av.w;
        Ws[lc+0][lr]=wv.x; Ws[lc+1][lr]=wv.y; Ws[lc+2][lr]=wv.z; Ws[lc+3][lr]=wv.w;
        __syncthreads();
        if (k0 + 16 < K) {
            av = *(const float4*)(Ap + k0 + 16);
            wv = wok ? *(const float4*)(Wp + k0 + 16) : make_float4(0,0,0,0);
        }
        #pragma unroll
        for (int kk = 0; kk < 16; kk++) {
            float4 a = *(const float4*)&As[kk][cm];
            float4 w = *(const float4*)&Ws[kk][cn];
            acc[0][0]+=a.x*w.x; acc[0][1]+=a.x*w.y; acc[0][2]+=a.x*w.z; acc[0][3]+=a.x*w.w;
            acc[1][0]+=a.y*w.x; acc[1][1]+=a.y*w.y; acc[1][2]+=a.y*w.z; acc[1][3]+=a.y*w.w;
            acc[2][0]+=a.z*w.x; acc[2][1]+=a.z*w.y; acc[2][2]+=a.z*w.z; acc[2][3]+=a.z*w.w;
            acc[3][0]+=a.w*w.x; acc[3][1]+=a.w*w.y; acc[3][2]+=a.w*w.z; acc[3][3]+=a.w*w.w;
        }
        __syncthreads();
    }
    #pragma unroll
    for (int i = 0; i < 4; i++) {
        const int gm = m0 + cm + i;
        #pragma unroll
        for (int j = 0; j < 4; j++) {
            const int gn = n0 + cn + j;
            if (gn < N) C[(size_t)gm*ldc + gn] = acc[i][j] + (bias ? bias[gn] : 0.f);
        }
    }
}

// ===================== persistent HMMA LSTM (TMA + counters) ==========
// grid (32 j-tiles, 4 b-tiles) = 128 CTAs, 1/SM.
// Per-(group, k-half) monotonic counters replace the full barrier; only
// tid0 polls (others block on TMA mbarrier). Chunk order S·Whi, S·Wlo
// frees each stage after 2 chunks for early refill.
#define WPAD   520
#define SM_W(p)   ((p) ? 66560u : 0u)
#define SM_S0     133120u
#define SM_S1     165888u
#define MB0       198656u
#define MB1       198664u
#define SM_G      198672u
#define LSTM_SMEM 216080

__global__ __launch_bounds__(256, 1)
void lstm_persist(const __grid_constant__ CUtensorMap mh0,
                  const __grid_constant__ CUtensorMap mh1,
                  const __grid_constant__ CUtensorMap ml0,
                  const __grid_constant__ CUtensorMap ml1)
{
    extern __shared__ __align__(1024) char smem[];
    const uint32_t sb = smem_u32(smem);

    const int tid = threadIdx.x;
    const int wid = tid >> 5, lane = tid & 31;
    const int warpM = wid & 1, warpN = wid >> 1;
    const int n0 = blockIdx.x * 64;
    const int m0 = blockIdx.y * 64;
    const int grp = blockIdx.y;
    const int myhalf = blockIdx.x >> 4;     // this CTA's h outputs fall in k-half

    // ---- counter base snapshot (graph-replay safe) ----
    unsigned base0 = 0, base1 = 0;
    if (tid == 0) {
        base0 = *(volatile unsigned*)&g_cnt[grp][0];
        base1 = *(volatile unsigned*)&g_cnt[grp][1];
    }

    // ---- resident W (hi+lo), cp.async once ----
    #pragma unroll
    for (int it = 0; it < 32; it++) {
        const int u = tid + it * 256;
        const int copy = u >> 12;
        const int v = u & 4095;
        const int row = v >> 6, seg = v & 63;
        const bf16* src = (copy ? g_whhp_lo : g_whhp_hi) + (size_t)(n0 + row) * HID + seg * 8;
        cp16(sb + SM_W(copy) + (uint32_t)(row * (WPAD*2) + seg * 16), src);
    }
    CP_COMMIT();
    if (tid == 0) { MBARRIER_INIT(sb + MB0, 1); MBARRIER_INIT(sb + MB1, 1); }
    CP_WAIT(0);
    __syncthreads();

    float c_reg[4] = {0.f, 0.f, 0.f, 0.f};
    const int bloc = tid & 63;
    const int hq = tid >> 6;
    const int gb = m0 + bloc;
    const int h0q = n0 >> 2;

    // A-side ldmatrix addressing (TMA SW128 layout)
    const int arow = warpM*32 + (lane & 15);
    const uint32_t swm = (uint32_t)((arow & 7) << 4);
    const uint32_t aRowB = (uint32_t)(arow * 128);
    const uint32_t cin = (uint32_t)((lane >> 4) * 16);
    const uint32_t bOff = (uint32_t)((warpN*16 + (lane & 15)) * (WPAD*2)) + ((lane >> 4) * 16);

    float* sG = (float*)(smem + SM_G);
    uint32_t ph0 = 0, ph1 = 0;

    for (int t = 0; t < Tsz; t++) {
        const CUtensorMap* mhi = (t & 1) ? &mh1 : &mh0;
        const CUtensorMap* mlo = (t & 1) ? &ml1 : &ml0;
        bf16* __restrict__ Hhi = g_hhi[(t+1) & 1];
        bf16* __restrict__ Hlo = g_hlo[(t+1) & 1];

        // prefetch gatesX slab into sG (all threads; overlaps everything)
        #pragma unroll
        for (int i = 0; i < 4; i++) {
            const int idx = tid + i * 256;
            const int row = idx >> 4, c16 = idx & 15;
            cp16(sb + SM_G + (uint32_t)(row * 272 + c16 * 16),
                 &g_gatesX[((size_t)t*Bsz + m0 + row)*G4 + n0 + c16*4]);
        }
        CP_COMMIT();

        // tid0: wait producers per k-half, issue hi TMA loads ASAP
        if (tid == 0) {
            const unsigned tgt0 = base0 + 16u * (unsigned)t;
            const unsigned tgt1 = base1 + 16u * (unsigned)t;
            volatile unsigned* c0p = &g_cnt[grp][0];
            volatile unsigned* c1p = &g_cnt[grp][1];
            while ((int)(*c0p - tgt0) < 0) { }
            __threadfence();
            MBARRIER_EXPECT_TX(sb + MB0, 32768);
            TMA_LOAD_3D_CTA(sb + SM_S0, mhi, 0, m0, 0, sb + MB0);
            while ((int)(*c1p - tgt1) < 0) { }
            __threadfence();
            MBARRIER_EXPECT_TX(sb + MB1, 32768);
            TMA_LOAD_3D_CTA(sb + SM_S1, mhi, 0, m0, 4, sb + MB1);
        }

        float acc[2][2][4];
        #pragma unroll
        for (int a=0;a<2;a++)
            #pragma unroll
            for (int b=0;b<2;b++)
                #pragma unroll
                for (int d=0;d<4;d++) acc[a][b][d] = 0.f;

        auto mma_chunk = [&](uint32_t stage, int wsel, int kc) {
            const uint32_t aBase = sb + stage;
            const uint32_t bB = sb + SM_W(wsel) + bOff + (uint32_t)(kc * 512);
            #pragma unroll
            for (int ks = 0; ks < 16; ks++) {
                uint32_t a[2][4];
                const uint32_t col = (((uint32_t)(ks & 3) * 32u) + cin) ^ swm;
                const uint32_t kbOff = ((uint32_t)(ks >> 2)) << 13;
                #pragma unroll
                for (int mf = 0; mf < 2; mf++)
                    LDM_X4(a[mf][0], a[mf][1], a[mf][2], a[mf][3],
                           aBase + kbOff + aRowB + (uint32_t)(mf * 2048) + col);
                uint32_t br[4];
                LDM_X4(br[0], br[1], br[2], br[3], bB + ks * 32);
                #pragma unroll
                for (int mf = 0; mf < 2; mf++) {
                    MMA_BF16(acc[mf][0][0], acc[mf][0][1], acc[mf][0][2], acc[mf][0][3],
                             a[mf][0], a[mf][1], a[mf][2], a[mf][3], br[0], br[2]);
                    MMA_BF16(acc[mf][1][0], acc[mf][1][1], acc[mf][1][2], acc[mf][1][3],
                             a[mf][0], a[mf][1], a[mf][2], a[mf][3], br[1], br[3]);
                }
            }
        };

        // S0 = hi k0: Whi then Wlo chunks, then refill S0 <- lo k0
        MBARRIER_WAIT_PARITY(sb + MB0, ph0); ph0 ^= 1;
        mma_chunk(SM_S0, 0, 0);
        mma_chunk(SM_S0, 1, 0);
        __syncthreads();
        if (tid == 0) {
            MBARRIER_EXPECT_TX(sb + MB0, 32768);
            TMA_LOAD_3D_CTA(sb + SM_S0, mlo, 0, m0, 0, sb + MB0);
        }
        // S1 = hi k1: Whi, Wlo, then refill S1 <- lo k1
        MBARRIER_WAIT_PARITY(sb + MB1, ph1); ph1 ^= 1;
        mma_chunk(SM_S1, 0, 1);
        mma_chunk(SM_S1, 1, 1);
        __syncthreads();
        if (tid == 0) {
            MBARRIER_EXPECT_TX(sb + MB1, 32768);
            TMA_LOAD_3D_CTA(sb + SM_S1, mlo, 0, m0, 4, sb + MB1);
        }
        // lo k0, lo k1 against Whi
        MBARRIER_WAIT_PARITY(sb + MB0, ph0); ph0 ^= 1;
        mma_chunk(SM_S0, 0, 0);
        MBARRIER_WAIT_PARITY(sb + MB1, ph1); ph1 ^= 1;
        mma_chunk(SM_S1, 0, 1);

        // gatesX arrived; read-modify-write acc into sG
        CP_WAIT(0);
        __syncthreads();
        {
            const int mloc = warpM*32 + (lane >> 2);
            const int nloc = warpN*16 + 2*(lane & 3);
            #pragma unroll
            for (int mf = 0; mf < 2; mf++) {
                #pragma unroll
                for (int nf = 0; nf < 2; nf++) {
                    const int n = nloc + nf*8;
                    #pragma unroll
                    for (int half = 0; half < 2; half++) {
                        const int m = mloc + mf*16 + half*8;
                        float2* p = (float2*)&sG[m*68 + n];
                        float2 v = *p;
                        v.x += acc[mf][nf][half*2];
                        v.y += acc[mf][nf][half*2+1];
                        *p = v;
                    }
                }
            }
        }
        __syncthreads();

        // fused LSTM cell: 64 b x 16 h
        float hv[4];
        #pragma unroll
        for (int j = 0; j < 4; j++) {
            const int hsub = hq*4 + j;
            const float4 gv = *(const float4*)&sG[bloc*68 + hsub*4];
            const float si = sigmoid_fast(gv.x);
            const float sf = sigmoid_fast(gv.y);
            const float so = sigmoid_fast(gv.w);
            const float cnew = sf*c_reg[j] + si*tanh_fast(gv.z);
            hv[j] = so*tanh_fast(cnew);
            c_reg[j] = cnew;
        }
        union { bf16 v[4]; uint2 u; } ph, pl;
        #pragma unroll
        for (int j = 0; j < 4; j++) {
            ph.v[j] = __float2bfloat16(hv[j]);
            pl.v[j] = __float2bfloat16(hv[j] - __bfloat162float(ph.v[j]));
        }
        const int ci = gb*HID + h0q + hq*4;
        *(uint2*)&Hhi[ci] = ph.u;
        *(uint2*)&Hlo[ci] = pl.u;
        const size_t ho = ((size_t)gb*Tsz + t)*HID + h0q + hq*4;
        *(uint2*)&g_hseq_hi[ho] = ph.u;
        *(uint2*)&g_hseq_lo[ho] = pl.u;

        // publish h(t+1): all stores done -> arrive on own half counter
        __syncthreads();
        if (tid == 0) {
            __threadfence();
            atomicAdd(&g_cnt[grp][myhalf], 1u);
        }
    }
}

// ===================== launch =====================
typedef CUresult (*EncodeFn)(CUtensorMap*, CUtensorMapDataType, cuuint32_t, void*,
    const cuuint64_t*, const cuuint64_t*, const cuuint32_t*, const cuuint32_t*,
    CUtensorMapInterleave, CUtensorMapSwizzle, CUtensorMapL2promotion, CUtensorMapFloatOOBfill);

extern "C" void kernel_launch(void* const* d_in, const int* in_sizes, int n_in,
                              void* d_out, int out_size)
{
    const float* images   = (const float*)d_in[0];
    const float* captions = (const float*)d_in[1];
    const float* W_fc  = (const float*)d_in[2];
    const float* b_fc  = (const float*)d_in[3];
    const float* W_att = (const float*)d_in[4];
    const float* b_att = (const float*)d_in[5];
    const float* W_ih  = (const float*)d_in[6];
    const float* b_ih  = (const float*)d_in[7];
    const float* W_hh  = (const float*)d_in[8];
    const float* b_hh  = (const float*)d_in[9];
    const float* W_out = (const float*)d_in[10];
    const float* b_out = (const float*)d_in[11];
    float* out = (float*)d_out;

    float *p_feats, *p_ctxb, *p_gateb, *p_gatesX, *p_bcomb, *p_w0p;
    bf16 *p_hhi, *p_hlo;
    bf16 *p_cap_hi, *p_cap_lo, *p_ctx_hi, *p_ctx_lo, *p_hseq_hi, *p_hseq_lo;
    bf16 *p_watt_hi, *p_watt_lo, *p_wihp_hi, *p_wihp_lo, *p_whhp_hi, *p_whhp_lo, *p_wout_hi, *p_wout_lo;
    cudaGetSymbolAddress((void**)&p_feats,  g_feats);
    cudaGetSymbolAddress((void**)&p_ctxb,   g_ctx_base);
    cudaGetSymbolAddress((void**)&p_gateb,  g_gate_base);
    cudaGetSymbolAddress((void**)&p_gatesX, g_gatesX);
    cudaGetSymbolAddress((void**)&p_bcomb,  g_bcomb);
    cudaGetSymbolAddress((void**)&p_w0p,    g_w0p);
    cudaGetSymbolAddress((void**)&p_hhi,    g_hhi);
    cudaGetSymbolAddress((void**)&p_hlo,    g_hlo);
    cudaGetSymbolAddress((void**)&p_cap_hi, g_cap_hi);
    cudaGetSymbolAddress((void**)&p_cap_lo, g_cap_lo);
    cudaGetSymbolAddress((void**)&p_ctx_hi, g_ctx_hi);
    cudaGetSymbolAddress((void**)&p_ctx_lo, g_ctx_lo);
    cudaGetSymbolAddress((void**)&p_hseq_hi, g_hseq_hi);
    cudaGetSymbolAddress((void**)&p_hseq_lo, g_hseq_lo);
    cudaGetSymbolAddress((void**)&p_watt_hi, g_watt_hi);
    cudaGetSymbolAddress((void**)&p_watt_lo, g_watt_lo);
    cudaGetSymbolAddress((void**)&p_wihp_hi, g_wihp_hi);
    cudaGetSymbolAddress((void**)&p_wihp_lo, g_wihp_lo);
    cudaGetSymbolAddress((void**)&p_whhp_hi, g_whhp_hi);
    cudaGetSymbolAddress((void**)&p_whhp_lo, g_whhp_lo);
    cudaGetSymbolAddress((void**)&p_wout_hi, g_wout_hi);
    cudaGetSymbolAddress((void**)&p_wout_lo, g_wout_lo);

    // ---- one-time setup: smem attr + tensormaps ----
    static bool s_ready = false;
    static CUtensorMap s_mh0, s_mh1, s_ml0, s_ml1;
    if (!s_ready) {
        cudaFuncSetAttribute(lstm_persist, cudaFuncAttributeMaxDynamicSharedMemorySize, LSTM_SMEM);
        void* fn = nullptr;
        cudaDriverEntryPointQueryResult qr;
        cudaGetDriverEntryPoint("cuTensorMapEncodeTiled", &fn, cudaEnableDefault, &qr);
        EncodeFn enc = (EncodeFn)fn;
        auto mk = [&](CUtensorMap* m, void* base) {
            cuuint64_t dims[3]    = {64, Bsz, 8};          // ki, b, kb
            cuuint64_t strides[2] = {HID * 2, 128};        // b-stride, kb-stride (bytes)
            cuuint32_t box[3]     = {64, 64, 4};
            cuuint32_t es[3]      = {1, 1, 1};
            enc(m, CU_TENSOR_MAP_DATA_TYPE_BFLOAT16, 3, base, dims, strides, box, es,
                CU_TENSOR_MAP_INTERLEAVE_NONE, CU_TENSOR_MAP_SWIZZLE_128B,
                CU_TENSOR_MAP_L2_PROMOTION_L2_128B, CU_TENSOR_MAP_FLOAT_OOB_FILL_NONE);
        };
        mk(&s_mh0, (void*)p_hhi);
        mk(&s_mh1, (void*)(p_hhi + (size_t)Bsz*HID));
        mk(&s_ml0, (void*)p_hlo);
        mk(&s_ml1, (void*)(p_hlo + (size_t)Bsz*HID));
        s_ready = true;
    }

    init_state_kernel<<<(Bsz*HID + 255)/256, 256>>>();

    // ---- preprocessing: splits + permutes ----
    split_mat<<<((size_t)BT*HID + 255)/256, 256>>>(captions, HID, BT, HID, p_cap_hi, p_cap_lo, BT);
    split_mat<<<(EMB*HID + 255)/256, 256>>>(W_att + EMB, EMB+HID, EMB, HID, p_watt_hi, p_watt_lo, EMB);
    split_mat<<<(VOCP*HID + 255)/256, 256>>>(W_out, HID, VOC, HID, p_wout_hi, p_wout_lo, VOCP);
    perm_split_w<<<(G4*EMB + 255)/256, 256>>>(W_ih, 2*EMB, EMB, EMB, p_wihp_hi, p_wihp_lo);
    perm_split_w<<<(G4*HID + 255)/256, 256>>>(W_hh, HID, 0, HID, p_whhp_hi, p_whhp_lo);
    perm_w0_bias<<<(G4*EMB + 255)/256, 256>>>(W_ih, b_ih, b_hh);

    // ---- small fp32 GEMMs ----
    gemm64<<<dim3(EMB/64, Bsz/64), 256>>>(images, FCI, W_fc, FCI, p_feats, EMB, Bsz, EMB, FCI, b_fc);
    gemm64<<<dim3(EMB/64, Bsz/64), 256>>>(p_feats, EMB, W_att, EMB+HID, p_ctxb, EMB, Bsz, EMB, EMB, b_att);
    gemm64<<<dim3(G4/64, Bsz/64), 256>>>(p_feats, EMB, p_w0p, EMB, p_gateb, G4, Bsz, G4, EMB, p_bcomb);

    // ---- ctx = captions @ W_att'^T + ctx_base  ->  split bf16 ----
    hmma_nt<<<dim3(EMB/128, BT/128), 256>>>(
        p_cap_hi, p_cap_lo, p_watt_hi, p_watt_lo, HID,
        nullptr, p_ctx_hi, p_ctx_lo, EMB, EMB, nullptr, p_ctxb, EMB, 0);

    // ---- gatesX = ctx @ wihp^T + gate_base  ->  fp32, [t][b][j] ----
    hmma_nt<<<dim3(G4/128, BT/128), 256>>>(
        p_ctx_hi, p_ctx_lo, p_wihp_hi, p_wihp_lo, EMB,
        p_gatesX, nullptr, nullptr, G4, G4, nullptr, p_gateb, G4, 1);

    // ---- recurrence: ONE persistent kernel, per-half producer counters ----
    lstm_persist<<<dim3(32, 4), 256, LSTM_SMEM>>>(s_mh0, s_mh1, s_ml0, s_ml1);

    // ---- out = hseq @ W_out^T + b_out ----
    hmma_nt<<<dim3(VOCP/128, BT/128), 256>>>(
        p_hseq_hi, p_hseq_lo, p_wout_hi, p_wout_lo, HID,
        out, nullptr, nullptr, VOC, VOC, b_out, nullptr, 0, 0);
}

// round 16
// speedup vs baseline: 3.1719x; 1.0248x over previous
#include <cuda_runtime.h>
#include <cuda_bf16.h>
#include <cuda.h>
#include <math.h>
#include <cstdint>

#define Bsz 256
#define Tsz 128
#define EMB 256
#define HID 512
#define VOC 1004
#define VOCP 1024
#define FCI 2048
#define BT  (Bsz*Tsz)
#define G4  (4*HID)

typedef __nv_bfloat16 bf16;

// ===================== PTX helpers =====================
__device__ __forceinline__ uint32_t smem_u32(const void* p) {
    uint32_t a;
    asm("{ .reg .u64 t; cvta.to.shared.u64 t, %1; cvt.u32.u64 %0, t; }" : "=r"(a) : "l"(p));
    return a;
}
__device__ __forceinline__ void cp16(uint32_t s, const void* g) {
    asm volatile("cp.async.cg.shared.global [%0], [%1], 16;" :: "r"(s), "l"(g) : "memory");
}
#define CP_COMMIT() asm volatile("cp.async.commit_group;" ::: "memory")
#define CP_WAIT(n)  asm volatile("cp.async.wait_group %0;" :: "n"(n) : "memory")

#define LDM_X4(r0,r1,r2,r3, addr) \
    asm volatile("ldmatrix.sync.aligned.m8n8.x4.shared.b16 {%0,%1,%2,%3}, [%4];" \
        : "=r"(r0), "=r"(r1), "=r"(r2), "=r"(r3) : "r"(addr))

#define MMA_BF16(c0,c1,c2,c3, a0,a1,a2,a3, b0,b1) \
    asm volatile("mma.sync.aligned.m16n8k16.row.col.f32.bf16.bf16.f32 " \
        "{%0,%1,%2,%3}, {%4,%5,%6,%7}, {%8,%9}, {%0,%1,%2,%3};" \
        : "+f"(c0), "+f"(c1), "+f"(c2), "+f"(c3) \
        : "r"(a0), "r"(a1), "r"(a2), "r"(a3), "r"(b0), "r"(b1))

#define MBARRIER_INIT(addr, cnt) \
    asm volatile("mbarrier.init.shared.b64 [%0], %1;" :: "r"((uint32_t)(addr)), "r"((uint32_t)(cnt)) : "memory")
#define MBARRIER_EXPECT_TX(addr, tx) \
    asm volatile("mbarrier.arrive.expect_tx.shared.b64 _, [%0], %1;" :: "r"((uint32_t)(addr)), "r"((uint32_t)(tx)) : "memory")
#define MBARRIER_WAIT_PARITY(addr, par) do { \
    uint32_t _m = (uint32_t)(addr); uint32_t _p = (uint32_t)(par); uint32_t _d; \
    asm volatile("{\n\t.reg .pred p;\n\tmbarrier.try_wait.parity.acquire.cta.shared::cta.b64 p, [%1], %2;\n\tselp.b32 %0, 1, 0, p;\n\t}" \
        : "=r"(_d) : "r"(_m), "r"(_p) : "memory"); \
    if (!_d) { \
        asm volatile("{\n\t.reg .pred P1;\n\tWL_%=:\n\tmbarrier.try_wait.parity.acquire.cta.shared::cta.b64 P1, [%0], %1, 0x989680;\n\t@P1 bra.uni WD_%=;\n\tbra.uni WL_%=;\n\tWD_%=:\n\t}" \
            :: "r"(_m), "r"(_p) : "memory"); \
    } } while (0)

#define TMA_LOAD_3D_CTA(smem_addr, tmap, c0, c1, c2, mbar) \
    asm volatile("cp.async.bulk.tensor.3d.shared::cta.global.tile.mbarrier::complete_tx::bytes " \
        "[%0], [%1, {%2, %3, %4}], [%5];" \
        :: "r"((uint32_t)(smem_addr)), "l"(tmap), "r"((int)(c0)), "r"((int)(c1)), "r"((int)(c2)), \
           "r"((uint32_t)(mbar)) : "memory")

__device__ __forceinline__ float tanh_fast(float x) {
    float r; asm("tanh.approx.f32 %0, %1;" : "=f"(r) : "f"(x)); return r;
}
__device__ __forceinline__ float sigmoid_fast(float x) {
    return 0.5f + 0.5f * tanh_fast(0.5f * x);
}
__device__ __forceinline__ unsigned ld_acq(unsigned* p) {
    unsigned v;
    asm volatile("ld.acquire.gpu.global.u32 %0, [%1];" : "=r"(v) : "l"(p) : "memory");
    return v;
}
__device__ __forceinline__ void red_rel_add(unsigned* p, unsigned v) {
    asm volatile("red.release.gpu.global.add.u32 [%0], %1;" :: "l"(p), "r"(v) : "memory");
}

// ===================== device scratch =====================
__device__ __align__(16) float g_feats    [Bsz*EMB];
__device__ __align__(16) float g_ctx_base [Bsz*EMB];
__device__ __align__(16) float g_gate_base[Bsz*G4];
__device__ __align__(16) float g_gatesX   [(size_t)BT*G4];    // [t][b][j]
__device__ __align__(16) float g_bcomb    [G4];
__device__ __align__(16) float g_w0p      [G4*EMB];

__device__ __align__(1024) bf16 g_hhi[2][Bsz*HID];
__device__ __align__(1024) bf16 g_hlo[2][Bsz*HID];

__device__ __align__(16) bf16 g_cap_hi [(size_t)BT*HID];
__device__ __align__(16) bf16 g_cap_lo [(size_t)BT*HID];
__device__ __align__(16) bf16 g_ctx_hi [(size_t)BT*EMB];
__device__ __align__(16) bf16 g_ctx_lo [(size_t)BT*EMB];
__device__ __align__(16) bf16 g_hseq_hi[(size_t)BT*HID];
__device__ __align__(16) bf16 g_hseq_lo[(size_t)BT*HID];
__device__ __align__(16) bf16 g_watt_hi[EMB*HID],  g_watt_lo[EMB*HID];
__device__ __align__(16) bf16 g_wihp_hi[G4*EMB],   g_wihp_lo[G4*EMB];
__device__ __align__(16) bf16 g_whhp_hi[G4*HID],   g_whhp_lo[G4*HID];
__device__ __align__(16) bf16 g_wout_hi[VOCP*HID], g_wout_lo[VOCP*HID];

// producer/consumer counters: [group][k-half], monotonic, never reset
__device__ unsigned g_cnt[4][2];

__global__ void init_state_kernel() {
    int i = blockIdx.x*blockDim.x + threadIdx.x;
    if (i < Bsz*HID) {
        g_hhi[0][i] = __float2bfloat16(0.f);
        g_hlo[0][i] = __float2bfloat16(0.f);
    }
}

// ===================== splits =====================
// vectorized flat split: 8 contiguous elems/thread
__global__ void split_flat8(const float* __restrict__ src,
                            bf16* __restrict__ hi, bf16* __restrict__ lo, size_t n8)
{
    size_t i = (size_t)blockIdx.x*blockDim.x + threadIdx.x;
    if (i >= n8) return;
    const float4* s4 = (const float4*)src;
    float4 a = s4[i*2], b = s4[i*2+1];
    float x[8] = {a.x,a.y,a.z,a.w,b.x,b.y,b.z,b.w};
    union { bf16 v[8]; uint4 u; } H, L;
    #pragma unroll
    for (int j = 0; j < 8; j++) {
        H.v[j] = __float2bfloat16(x[j]);
        L.v[j] = __float2bfloat16(x[j] - __bfloat162float(H.v[j]));
    }
    ((uint4*)hi)[i] = H.u;
    ((uint4*)lo)[i] = L.u;
}

__global__ void split_mat(const float* __restrict__ src, int ldsrc, int Nreal, int K,
                          bf16* __restrict__ hi, bf16* __restrict__ lo, int Npad)
{
    size_t i = (size_t)blockIdx.x*blockDim.x + threadIdx.x;
    if (i >= (size_t)Npad*K) return;
    int n = (int)(i / K), k = (int)(i % K);
    float x = (n < Nreal) ? src[(size_t)n*ldsrc + k] : 0.f;
    bf16 h = __float2bfloat16(x);
    hi[i] = h;
    lo[i] = __float2bfloat16(x - __bfloat162float(h));
}

__global__ void perm_split_w(const float* __restrict__ src, int ldsrc, int koff, int K,
                             bf16* __restrict__ hi, bf16* __restrict__ lo)
{
    size_t i = (size_t)blockIdx.x*blockDim.x + threadIdx.x;
    if (i >= (size_t)G4*K) return;
    int j = (int)(i / K), k = (int)(i % K);
    int h = j >> 2, g = j & 3;
    float x = src[(size_t)(g*HID + h)*ldsrc + koff + k];
    bf16 hh = __float2bfloat16(x);
    hi[i] = hh;
    lo[i] = __float2bfloat16(x - __bfloat162float(hh));
}

__global__ void perm_w0_bias(const float* __restrict__ W_ih,
                             const float* __restrict__ b_ih,
                             const float* __restrict__ b_hh)
{
    int i = blockIdx.x*blockDim.x + threadIdx.x;
    if (i >= G4*EMB) return;
    int j = i >> 8, k = i & 255;
    int h = j >> 2, g = j & 3;
    g_w0p[i] = W_ih[(size_t)(g*HID + h)*(2*EMB) + k];
    if (k == 0) g_bcomb[j] = b_ih[g*HID + h] + b_hh[g*HID + h];
}

// ===================== HMMA bf16 NT GEMM, 3-pass split ================
#define SPAD 40

__global__ __launch_bounds__(256)
void hmma_nt(const bf16* __restrict__ Ahi, const bf16* __restrict__ Alo,
             const bf16* __restrict__ Bhi, const bf16* __restrict__ Blo,
             int K,
             float* __restrict__ C, bf16* __restrict__ Chi, bf16* __restrict__ Clo,
             int ldc, int Nreal,
             const float* __restrict__ bias,
             const float* __restrict__ rowAdd, int rowLd,
             int rowSwap)
{
    // contiguous stage memory: [0],[1] = A stages; [2],[3] = B stages.
    // Reused as fp32 staging buffer (64x132) in the rowSwap epilogue.
    __shared__ __align__(16) bf16 sAB[4][128*SPAD];

    const int tid = threadIdx.x;
    const int wid = tid >> 5, lane = tid & 31;
    const int warpM = wid & 1, warpN = wid >> 1;
    const int n0 = blockIdx.x * 128, m0 = blockIdx.y * 128;

    const int kch = K >> 5;
    const int nch = 3 * kch;

    auto load_chunk = [&](int c, int st) {
        const int p = c / kch, kc = c % kch;
        const bf16* Ap = (p == 1) ? Alo : Ahi;
        const bf16* Bp = (p == 2) ? Blo : Bhi;
        #pragma unroll
        for (int j = 0; j < 4; j++) {
            const int u = tid + j * 256;
            const int tile = u >> 9;
            const int row = (u >> 2) & 127;
            const int seg = u & 3;
            const bf16* g = (tile ? Bp + (size_t)(n0 + row) * K
                                  : Ap + (size_t)(m0 + row) * K) + kc * 32 + seg * 8;
            bf16* dst = sAB[tile*2 + st] + row * SPAD + seg * 8;
            cp16(smem_u32(dst), g);
        }
        CP_COMMIT();
    };

    float acc[4][4][4];
    #pragma unroll
    for (int a=0;a<4;a++)
        #pragma unroll
        for (int b=0;b<4;b++)
            #pragma unroll
            for (int d=0;d<4;d++) acc[a][b][d] = 0.f;

    load_chunk(0, 0);
    if (nch > 1) load_chunk(1, 1);

    const uint32_t aAddrBase0 = smem_u32(&sAB[0][0]) +
        (uint32_t)((warpM*64 + (lane & 15)) * SPAD * 2) + ((lane >> 4) * 16);
    const uint32_t bAddrBase0 = smem_u32(&sAB[2][0]) +
        (uint32_t)((warpN*32 + (lane & 15)) * SPAD * 2) + ((lane >> 4) * 16);
    const uint32_t stageOff = (uint32_t)(128 * SPAD * 2);

    for (int c = 0; c < nch; c++) {
        const int st = c & 1;
        if (c + 1 < nch) { CP_WAIT(1); } else { CP_WAIT(0); }
        __syncthreads();

        const uint32_t aB = aAddrBase0 + st * stageOff;
        const uint32_t bB = bAddrBase0 + st * stageOff;

        #pragma unroll
        for (int ks = 0; ks < 2; ks++) {
            uint32_t a[4][4];
            #pragma unroll
            for (int mf = 0; mf < 4; mf++)
                LDM_X4(a[mf][0], a[mf][1], a[mf][2], a[mf][3],
                       aB + (uint32_t)(mf * 16 * SPAD * 2) + ks * 32);
            uint32_t br[2][4];
            #pragma unroll
            for (int nq = 0; nq < 2; nq++)
                LDM_X4(br[nq][0], br[nq][1], br[nq][2], br[nq][3],
                       bB + (uint32_t)(nq * 16 * SPAD * 2) + ks * 32);
            #pragma unroll
            for (int mf = 0; mf < 4; mf++) {
                #pragma unroll
                for (int nf = 0; nf < 4; nf++) {
                    const int nq = nf >> 1, nh = nf & 1;
                    MMA_BF16(acc[mf][nf][0], acc[mf][nf][1], acc[mf][nf][2], acc[mf][nf][3],
                             a[mf][0], a[mf][1], a[mf][2], a[mf][3],
                             br[nq][nh], br[nq][nh + 2]);
                }
            }
        }
        __syncthreads();
        if (c + 2 < nch) load_chunk(c + 2, st);
    }

    const int rowbase = rowAdd ? (m0 >> 7) * rowLd : 0;

    if (rowSwap) {
        // staged epilogue: coalesced writes for the [t][b][j] layout.
        float* sOut = (float*)&sAB[0][0];      // 64 x 132 floats = 33792 B (< 40960)
        #pragma unroll
        for (int hh = 0; hh < 2; hh++) {
            if (warpM == hh) {
                const int mrb = lane >> 2;
                const int nb = warpN*32 + 2*(lane & 3);
                #pragma unroll
                for (int mf = 0; mf < 4; mf++)
                    #pragma unroll
                    for (int nf = 0; nf < 4; nf++)
                        #pragma unroll
                        for (int half = 0; half < 2; half++) {
                            const int row = mf*16 + half*8 + mrb;
                            const int n = nb + nf*8;
                            sOut[row*132 + n]     = acc[mf][nf][half*2 + 0];
                            sOut[row*132 + n + 1] = acc[mf][nf][half*2 + 1];
                        }
            }
            __syncthreads();
            #pragma unroll
            for (int it = 0; it < 32; it++) {
                const int idx = tid + it * 256;
                const int row = idx >> 7, col = idx & 127;
                const int gm = m0 + hh*64 + row;
                const int grow = (gm & 127) * Bsz + (gm >> 7);
                float v = sOut[row*132 + col];
                if (rowAdd) v += rowAdd[rowbase + n0 + col];
                if (n0 + col < Nreal)
                    C[(size_t)grow * ldc + n0 + col] = v;
            }
            __syncthreads();
        }
        return;
    }

    const int mloc = warpM*64 + (lane >> 2);
    const int nloc = warpN*32 + 2*(lane & 3);

    #pragma unroll
    for (int mf = 0; mf < 4; mf++) {
        #pragma unroll
        for (int nf = 0; nf < 4; nf++) {
            const int gn = n0 + nloc + nf*8;
            float add0 = 0.f, add1 = 0.f;
            if (bias)   { add0 += bias[gn]; add1 += bias[gn+1]; }
            if (rowAdd) { add0 += rowAdd[rowbase + gn]; add1 += rowAdd[rowbase + gn + 1]; }
            #pragma unroll
            for (int half = 0; half < 2; half++) {
                const int gm = m0 + mloc + mf*16 + half*8;
                const float v0 = acc[mf][nf][half*2 + 0] + add0;
                const float v1 = acc[mf][nf][half*2 + 1] + add1;
                if (gn < Nreal) {
                    const size_t off = (size_t)gm * ldc + gn;
                    if (C) *(float2*)(C + off) = make_float2(v0, v1);
                    if (Chi) {
                        bf16 h0 = __float2bfloat16(v0);
                        bf16 h1 = __float2bfloat16(v1);
                        __nv_bfloat162 hv; hv.x = h0; hv.y = h1;
                        __nv_bfloat162 lv;
                        lv.x = __float2bfloat16(v0 - __bfloat162float(h0));
                        lv.y = __float2bfloat16(v1 - __bfloat162float(h1));
                        *(__nv_bfloat162*)(Chi + off) = hv;
                        *(__nv_bfloat162*)(Clo + off) = lv;
                    }
                }
            }
        }
    }
}

// ===================== small fp32 NT SGEMM =====================
__global__ __launch_bounds__(256)
void gemm64(const float* __restrict__ A, int lda,
            const float* __restrict__ W, int ldw,
            float* __restrict__ C, int ldc,
            int M, int N, int K,
            const float* __restrict__ bias)
{
    __shared__ float As[16][68];
    __shared__ float Ws[16][68];
    const int n0 = blockIdx.x*64, m0 = blockIdx.y*64;
    const int t  = threadIdx.x;
    const int lr = t>>2, lc = (t&3)*4;
    const int tx = t&15, ty = t>>4;
    const int cm = ty*4, cn = tx*4;
    float acc[4][4] = {};
    const float* Ap = A + (size_t)(m0+lr)*lda + lc;
    const bool wok = (n0+lr) < N;
    const float* Wp = W + (size_t)(wok ? (n0+lr) : 0)*ldw + lc;
    float4 av = *(const float4*)Ap;
    float4 wv = wok ? *(const float4*)Wp : make_float4(0,0,0,0);
    for (int k0 = 0; k0 < K; k0 += 16) {
        As[lc+0][lr]=av.x; As[lc+1][lr]=av.y; As[lc+2][lr]=av.z; As[lc+3][lr]=av.w;
        Ws[lc+0][lr]=wv.x; Ws[lc+1][lr]=wv.y; Ws[lc+2][lr]=wv.z; Ws[lc+3][lr]=wv.w;
        __syncthreads();
        if (k0 + 16 < K) {
            av = *(const float4*)(Ap + k0 + 16);
            wv = wok ? *(const float4*)(Wp + k0 + 16) : make_float4(0,0,0,0);
        }
        #pragma unroll
        for (int kk = 0; kk < 16; kk++) {
            float4 a = *(const float4*)&As[kk][cm];
            float4 w = *(const float4*)&Ws[kk][cn];
            acc[0][0]+=a.x*w.x; acc[0][1]+=a.x*w.y; acc[0][2]+=a.x*w.z; acc[0][3]+=a.x*w.w;
            acc[1][0]+=a.y*w.x; acc[1][1]+=a.y*w.y; acc[1][2]+=a.y*w.z; acc[1][3]+=a.y*w.w;
            acc[2][0]+=a.z*w.x; acc[2][1]+=a.z*w.y; acc[2][2]+=a.z*w.z; acc[2][3]+=a.z*w.w;
            acc[3][0]+=a.w*w.x; acc[3][1]+=a.w*w.y; acc[3][2]+=a.w*w.z; acc[3][3]+=a.w*w.w;
        }
        __syncthreads();
    }
    #pragma unroll
    for (int i = 0; i < 4; i++) {
        const int gm = m0 + cm + i;
        #pragma unroll
        for (int j = 0; j < 4; j++) {
            const int gn = n0 + cn + j;
            if (gn < N) C[(size_t)gm*ldc + gn] = acc[i][j] + (bias ? bias[gn] : 0.f);
        }
    }
}

// ===================== persistent HMMA LSTM (TMA + counters) ==========
#define WPAD   520
#define SM_W(p)   ((p) ? 66560u : 0u)
#define SM_S0     133120u
#define SM_S1     165888u
#define MB0       198656u
#define MB1       198664u
#define SM_G      198672u
#define LSTM_SMEM 216080

__global__ __launch_bounds__(256, 1)
void lstm_persist(const __grid_constant__ CUtensorMap mh0,
                  const __grid_constant__ CUtensorMap mh1,
                  const __grid_constant__ CUtensorMap ml0,
                  const __grid_constant__ CUtensorMap ml1)
{
    extern __shared__ __align__(1024) char smem[];
    const uint32_t sb = smem_u32(smem);

    const int tid = threadIdx.x;
    const int wid = tid >> 5, lane = tid & 31;
    const int warpM = wid & 1, warpN = wid >> 1;
    const int n0 = blockIdx.x * 64;
    const int m0 = blockIdx.y * 64;
    const int grp = blockIdx.y;
    const int myhalf = blockIdx.x >> 4;

    unsigned base0 = 0, base1 = 0;
    if (tid == 0) {
        base0 = *(volatile unsigned*)&g_cnt[grp][0];
        base1 = *(volatile unsigned*)&g_cnt[grp][1];
    }

    // ---- resident W (hi+lo), cp.async once ----
    #pragma unroll
    for (int it = 0; it < 32; it++) {
        const int u = tid + it * 256;
        const int copy = u >> 12;
        const int v = u & 4095;
        const int row = v >> 6, seg = v & 63;
        const bf16* src = (copy ? g_whhp_lo : g_whhp_hi) + (size_t)(n0 + row) * HID + seg * 8;
        cp16(sb + SM_W(copy) + (uint32_t)(row * (WPAD*2) + seg * 16), src);
    }
    CP_COMMIT();
    if (tid == 0) { MBARRIER_INIT(sb + MB0, 1); MBARRIER_INIT(sb + MB1, 1); }
    CP_WAIT(0);
    __syncthreads();

    float c_reg[4] = {0.f, 0.f, 0.f, 0.f};
    const int bloc = tid & 63;
    const int hq = tid >> 6;
    const int gb = m0 + bloc;
    const int h0q = n0 >> 2;

    const int arow = warpM*32 + (lane & 15);
    const uint32_t swm = (uint32_t)((arow & 7) << 4);
    const uint32_t aRowB = (uint32_t)(arow * 128);
    const uint32_t cin = (uint32_t)((lane >> 4) * 16);
    const uint32_t bOff = (uint32_t)((warpN*16 + (lane & 15)) * (WPAD*2)) + ((lane >> 4) * 16);

    float* sG = (float*)(smem + SM_G);
    uint32_t ph0 = 0, ph1 = 0;

    for (int t = 0; t < Tsz; t++) {
        const CUtensorMap* mhi = (t & 1) ? &mh1 : &mh0;
        const CUtensorMap* mlo = (t & 1) ? &ml1 : &ml0;
        bf16* __restrict__ Hhi = g_hhi[(t+1) & 1];
        bf16* __restrict__ Hlo = g_hlo[(t+1) & 1];

        // prefetch gatesX slab into sG
        #pragma unroll
        for (int i = 0; i < 4; i++) {
            const int idx = tid + i * 256;
            const int row = idx >> 4, c16 = idx & 15;
            cp16(sb + SM_G + (uint32_t)(row * 272 + c16 * 16),
                 &g_gatesX[((size_t)t*Bsz + m0 + row)*G4 + n0 + c16*4]);
        }
        CP_COMMIT();

        // tid0: wait producers per k-half (acquire loads), issue hi TMA loads
        if (tid == 0) {
            const unsigned tgt0 = base0 + 16u * (unsigned)t;
            const unsigned tgt1 = base1 + 16u * (unsigned)t;
            while ((int)(ld_acq(&g_cnt[grp][0]) - tgt0) < 0) { }
            MBARRIER_EXPECT_TX(sb + MB0, 32768);
            TMA_LOAD_3D_CTA(sb + SM_S0, mhi, 0, m0, 0, sb + MB0);
            while ((int)(ld_acq(&g_cnt[grp][1]) - tgt1) < 0) { }
            MBARRIER_EXPECT_TX(sb + MB1, 32768);
            TMA_LOAD_3D_CTA(sb + SM_S1, mhi, 0, m0, 4, sb + MB1);
        }

        float acc[2][2][4];
        #pragma unroll
        for (int a=0;a<2;a++)
            #pragma unroll
            for (int b=0;b<2;b++)
                #pragma unroll
                for (int d=0;d<4;d++) acc[a][b][d] = 0.f;

        auto mma_chunk = [&](uint32_t stage, int wsel, int kc) {
            const uint32_t aBase = sb + stage;
            const uint32_t bB = sb + SM_W(wsel) + bOff + (uint32_t)(kc * 512);
            #pragma unroll
            for (int ks = 0; ks < 16; ks++) {
                uint32_t a[2][4];
                const uint32_t col = (((uint32_t)(ks & 3) * 32u) + cin) ^ swm;
                const uint32_t kbOff = ((uint32_t)(ks >> 2)) << 13;
                #pragma unroll
                for (int mf = 0; mf < 2; mf++)
                    LDM_X4(a[mf][0], a[mf][1], a[mf][2], a[mf][3],
                           aBase + kbOff + aRowB + (uint32_t)(mf * 2048) + col);
                uint32_t br[4];
                LDM_X4(br[0], br[1], br[2], br[3], bB + ks * 32);
                #pragma unroll
                for (int mf = 0; mf < 2; mf++) {
                    MMA_BF16(acc[mf][0][0], acc[mf][0][1], acc[mf][0][2], acc[mf][0][3],
                             a[mf][0], a[mf][1], a[mf][2], a[mf][3], br[0], br[2]);
                    MMA_BF16(acc[mf][1][0], acc[mf][1][1], acc[mf][1][2], acc[mf][1][3],
                             a[mf][0], a[mf][1], a[mf][2], a[mf][3], br[1], br[3]);
                }
            }
        };

        // S0 = hi k0: Whi, Wlo, then refill S0 <- lo k0
        MBARRIER_WAIT_PARITY(sb + MB0, ph0); ph0 ^= 1;
        mma_chunk(SM_S0, 0, 0);
        mma_chunk(SM_S0, 1, 0);
        __syncthreads();
        if (tid == 0) {
            MBARRIER_EXPECT_TX(sb + MB0, 32768);
            TMA_LOAD_3D_CTA(sb + SM_S0, mlo, 0, m0, 0, sb + MB0);
        }
        // S1 = hi k1: Whi, Wlo, then refill S1 <- lo k1
        MBARRIER_WAIT_PARITY(sb + MB1, ph1); ph1 ^= 1;
        mma_chunk(SM_S1, 0, 1);
        mma_chunk(SM_S1, 1, 1);
        __syncthreads();
        if (tid == 0) {
            MBARRIER_EXPECT_TX(sb + MB1, 32768);
            TMA_LOAD_3D_CTA(sb + SM_S1, mlo, 0, m0, 4, sb + MB1);
        }
        // lo k0, lo k1 against Whi
        MBARRIER_WAIT_PARITY(sb + MB0, ph0); ph0 ^= 1;
        mma_chunk(SM_S0, 0, 0);
        MBARRIER_WAIT_PARITY(sb + MB1, ph1); ph1 ^= 1;
        mma_chunk(SM_S1, 0, 1);

        // gatesX arrived; read-modify-write acc into sG
        CP_WAIT(0);
        __syncthreads();
        {
            const int mloc = warpM*32 + (lane >> 2);
            const int nloc = warpN*16 + 2*(lane & 3);
            #pragma unroll
            for (int mf = 0; mf < 2; mf++) {
                #pragma unroll
                for (int nf = 0; nf < 2; nf++) {
                    const int n = nloc + nf*8;
                    #pragma unroll
                    for (int half = 0; half < 2; half++) {
                        const int m = mloc + mf*16 + half*8;
                        float2* p = (float2*)&sG[m*68 + n];
                        float2 v = *p;
                        v.x += acc[mf][nf][half*2];
                        v.y += acc[mf][nf][half*2+1];
                        *p = v;
                    }
                }
            }
        }
        __syncthreads();

        // fused LSTM cell: 64 b x 16 h
        float hv[4];
        #pragma unroll
        for (int j = 0; j < 4; j++) {
            const int hsub = hq*4 + j;
            const float4 gv = *(const float4*)&sG[bloc*68 + hsub*4];
            const float si = sigmoid_fast(gv.x);
            const float sf = sigmoid_fast(gv.y);
            const float so = sigmoid_fast(gv.w);
            const float cnew = sf*c_reg[j] + si*tanh_fast(gv.z);
            hv[j] = so*tanh_fast(cnew);
            c_reg[j] = cnew;
        }
        union { bf16 v[4]; uint2 u; } ph, pl;
        #pragma unroll
        for (int j = 0; j < 4; j++) {
            ph.v[j] = __float2bfloat16(hv[j]);
            pl.v[j] = __float2bfloat16(hv[j] - __bfloat162float(ph.v[j]));
        }
        const int ci = gb*HID + h0q + hq*4;
        *(uint2*)&Hhi[ci] = ph.u;
        *(uint2*)&Hlo[ci] = pl.u;
        const size_t ho = ((size_t)gb*Tsz + t)*HID + h0q + hq*4;
        *(uint2*)&g_hseq_hi[ho] = ph.u;
        *(uint2*)&g_hseq_lo[ho] = pl.u;

        // publish h(t+1): release-add on own half counter
        __syncthreads();
        if (tid == 0)
            red_rel_add(&g_cnt[grp][myhalf], 1u);
    }
}

// ===================== launch =====================
typedef CUresult (*EncodeFn)(CUtensorMap*, CUtensorMapDataType, cuuint32_t, void*,
    const cuuint64_t*, const cuuint64_t*, const cuuint32_t*, const cuuint32_t*,
    CUtensorMapInterleave, CUtensorMapSwizzle, CUtensorMapL2promotion, CUtensorMapFloatOOBfill);

extern "C" void kernel_launch(void* const* d_in, const int* in_sizes, int n_in,
                              void* d_out, int out_size)
{
    const float* images   = (const float*)d_in[0];
    const float* captions = (const float*)d_in[1];
    const float* W_fc  = (const float*)d_in[2];
    const float* b_fc  = (const float*)d_in[3];
    const float* W_att = (const float*)d_in[4];
    const float* b_att = (const float*)d_in[5];
    const float* W_ih  = (const float*)d_in[6];
    const float* b_ih  = (const float*)d_in[7];
    const float* W_hh  = (const float*)d_in[8];
    const float* b_hh  = (const float*)d_in[9];
    const float* W_out = (const float*)d_in[10];
    const float* b_out = (const float*)d_in[11];
    float* out = (float*)d_out;

    float *p_feats, *p_ctxb, *p_gateb, *p_gatesX, *p_bcomb, *p_w0p;
    bf16 *p_hhi, *p_hlo;
    bf16 *p_cap_hi, *p_cap_lo, *p_ctx_hi, *p_ctx_lo, *p_hseq_hi, *p_hseq_lo;
    bf16 *p_watt_hi, *p_watt_lo, *p_wihp_hi, *p_wihp_lo, *p_whhp_hi, *p_whhp_lo, *p_wout_hi, *p_wout_lo;
    cudaGetSymbolAddress((void**)&p_feats,  g_feats);
    cudaGetSymbolAddress((void**)&p_ctxb,   g_ctx_base);
    cudaGetSymbolAddress((void**)&p_gateb,  g_gate_base);
    cudaGetSymbolAddress((void**)&p_gatesX, g_gatesX);
    cudaGetSymbolAddress((void**)&p_bcomb,  g_bcomb);
    cudaGetSymbolAddress((void**)&p_w0p,    g_w0p);
    cudaGetSymbolAddress((void**)&p_hhi,    g_hhi);
    cudaGetSymbolAddress((void**)&p_hlo,    g_hlo);
    cudaGetSymbolAddress((void**)&p_cap_hi, g_cap_hi);
    cudaGetSymbolAddress((void**)&p_cap_lo, g_cap_lo);
    cudaGetSymbolAddress((void**)&p_ctx_hi, g_ctx_hi);
    cudaGetSymbolAddress((void**)&p_ctx_lo, g_ctx_lo);
    cudaGetSymbolAddress((void**)&p_hseq_hi, g_hseq_hi);
    cudaGetSymbolAddress((void**)&p_hseq_lo, g_hseq_lo);
    cudaGetSymbolAddress((void**)&p_watt_hi, g_watt_hi);
    cudaGetSymbolAddress((void**)&p_watt_lo, g_watt_lo);
    cudaGetSymbolAddress((void**)&p_wihp_hi, g_wihp_hi);
    cudaGetSymbolAddress((void**)&p_wihp_lo, g_wihp_lo);
    cudaGetSymbolAddress((void**)&p_whhp_hi, g_whhp_hi);
    cudaGetSymbolAddress((void**)&p_whhp_lo, g_whhp_lo);
    cudaGetSymbolAddress((void**)&p_wout_hi, g_wout_hi);
    cudaGetSymbolAddress((void**)&p_wout_lo, g_wout_lo);

    static bool s_ready = false;
    static CUtensorMap s_mh0, s_mh1, s_ml0, s_ml1;
    if (!s_ready) {
        cudaFuncSetAttribute(lstm_persist, cudaFuncAttributeMaxDynamicSharedMemorySize, LSTM_SMEM);
        void* fn = nullptr;
        cudaDriverEntryPointQueryResult qr;
        cudaGetDriverEntryPoint("cuTensorMapEncodeTiled", &fn, cudaEnableDefault, &qr);
        EncodeFn enc = (EncodeFn)fn;
        auto mk = [&](CUtensorMap* m, void* base) {
            cuuint64_t dims[3]    = {64, Bsz, 8};
            cuuint64_t strides[2] = {HID * 2, 128};
            cuuint32_t box[3]     = {64, 64, 4};
            cuuint32_t es[3]      = {1, 1, 1};
            enc(m, CU_TENSOR_MAP_DATA_TYPE_BFLOAT16, 3, base, dims, strides, box, es,
                CU_TENSOR_MAP_INTERLEAVE_NONE, CU_TENSOR_MAP_SWIZZLE_128B,
                CU_TENSOR_MAP_L2_PROMOTION_L2_128B, CU_TENSOR_MAP_FLOAT_OOB_FILL_NONE);
        };
        mk(&s_mh0, (void*)p_hhi);
        mk(&s_mh1, (void*)(p_hhi + (size_t)Bsz*HID));
        mk(&s_ml0, (void*)p_hlo);
        mk(&s_ml1, (void*)(p_hlo + (size_t)Bsz*HID));
        s_ready = true;
    }

    init_state_kernel<<<(Bsz*HID + 255)/256, 256>>>();

    // ---- preprocessing: splits + permutes ----
    {
        const size_t n8 = (size_t)BT*HID/8;
        split_flat8<<<(unsigned)((n8 + 255)/256), 256>>>(captions, p_cap_hi, p_cap_lo, n8);
    }
    split_mat<<<(EMB*HID + 255)/256, 256>>>(W_att + EMB, EMB+HID, EMB, HID, p_watt_hi, p_watt_lo, EMB);
    split_mat<<<(VOCP*HID + 255)/256, 256>>>(W_out, HID, VOC, HID, p_wout_hi, p_wout_lo, VOCP);
    perm_split_w<<<(G4*EMB + 255)/256, 256>>>(W_ih, 2*EMB, EMB, EMB, p_wihp_hi, p_wihp_lo);
    perm_split_w<<<(G4*HID + 255)/256, 256>>>(W_hh, HID, 0, HID, p_whhp_hi, p_whhp_lo);
    perm_w0_bias<<<(G4*EMB + 255)/256, 256>>>(W_ih, b_ih, b_hh);

    // ---- small fp32 GEMMs ----
    gemm64<<<dim3(EMB/64, Bsz/64), 256>>>(images, FCI, W_fc, FCI, p_feats, EMB, Bsz, EMB, FCI, b_fc);
    gemm64<<<dim3(EMB/64, Bsz/64), 256>>>(p_feats, EMB, W_att, EMB+HID, p_ctxb, EMB, Bsz, EMB, EMB, b_att);
    gemm64<<<dim3(G4/64, Bsz/64), 256>>>(p_feats, EMB, p_w0p, EMB, p_gateb, G4, Bsz, G4, EMB, p_bcomb);

    // ---- ctx = captions @ W_att'^T + ctx_base  ->  split bf16 ----
    hmma_nt<<<dim3(EMB/128, BT/128), 256>>>(
        p_cap_hi, p_cap_lo, p_watt_hi, p_watt_lo, HID,
        nullptr, p_ctx_hi, p_ctx_lo, EMB, EMB, nullptr, p_ctxb, EMB, 0);

    // ---- gatesX = ctx @ wihp^T + gate_base  ->  fp32, [t][b][j] ----
    hmma_nt<<<dim3(G4/128, BT/128), 256>>>(
        p_ctx_hi, p_ctx_lo, p_wihp_hi, p_wihp_lo, EMB,
        p_gatesX, nullptr, nullptr, G4, G4, nullptr, p_gateb, G4, 1);

    // ---- recurrence: ONE persistent kernel, per-half producer counters ----
    lstm_persist<<<dim3(32, 4), 256, LSTM_SMEM>>>(s_mh0, s_mh1, s_ml0, s_ml1);

    // ---- out = hseq @ W_out^T + b_out ----
    hmma_nt<<<dim3(VOCP/128, BT/128), 256>>>(
        p_hseq_hi, p_hseq_lo, p_wout_hi, p_wout_lo, HID,
        out, nullptr, nullptr, VOC, VOC, b_out, nullptr, 0, 0);
}